// round 10
// baseline (speedup 1.0000x reference)
#include <cuda_runtime.h>
#include <cuda_bf16.h>
#include <math.h>
#include <stdint.h>

// ---------------------------------------------------------------------------
// Problem constants
// ---------------------------------------------------------------------------
#define BB 256
#define TT 64
#define LL 1024
#define SS 512
#define NCLS 239
#define MBT (BB * TT)          // 16384

typedef __nv_bfloat16 bf16;

// ---------------------------------------------------------------------------
// Scratch (device globals; no runtime allocation allowed)
// ---------------------------------------------------------------------------
__device__ bf16 g_x_hi  [MBT * 2048];
__device__ bf16 g_x_lo  [MBT * 2048];
__device__ bf16 g_xs_hi [MBT * 1280];
__device__ bf16 g_xs_lo [MBT * 1280];
__device__ bf16 g_f_hi  [MBT * 2048];
__device__ bf16 g_f_lo  [MBT * 2048];
__device__ bf16 g_sf_hi [MBT * 512];
__device__ bf16 g_sf_lo [MBT * 512];
__device__ bf16 g_Wp_hi [2048 * 2048];
__device__ bf16 g_Wp_lo [2048 * 2048];
__device__ bf16 g_Ws_hi [512 * 1280];
__device__ bf16 g_Ws_lo [512 * 1280];
__device__ bf16 g_Wl_hi [4096 * 2560];   // Wih_l full (K-concat GEMM)
__device__ bf16 g_Wl_lo [4096 * 2560];
__device__ bf16 g_Whl_hi[4096 * 1024];   // Whh_l
__device__ bf16 g_Whl_lo[4096 * 1024];
__device__ bf16 g_Wis_hi[2048 * 512];    // Wih_s
__device__ bf16 g_Wis_lo[2048 * 512];
__device__ bf16 g_Whs_hi[2048 * 512];    // Whh_s
__device__ bf16 g_Whs_lo[2048 * 512];
__device__ bf16 g_Wc_hi [NCLS * 1024];
__device__ bf16 g_Wc_lo [NCLS * 1024];
__device__ float g_sfeats[MBT * 512];
__device__ float g_sgpre [MBT * 2048];
__device__ float g_lgpre [MBT * 4096];
__device__ float g_Gs2[2][BB * 2048];    // Gs split-K partials
__device__ float g_Gl4[4][BB * 4096];    // Gl split-K partials
__device__ float g_hl[2][BB * LL];
__device__ float g_cl[2][BB * LL];
__device__ float g_hs[2][BB * SS];
__device__ float g_cs[2][BB * SS];
__device__ bf16 g_hl_hi[2][BB * LL];
__device__ bf16 g_hl_lo[2][BB * LL];
__device__ bf16 g_hs_hi[2][BB * SS];
__device__ bf16 g_hs_lo[2][BB * SS];

// ---------------------------------------------------------------------------
// PTX helpers (legacy tensor path only — harness targets compute_100)
// ---------------------------------------------------------------------------
__device__ __forceinline__ uint32_t smem_u32(const void* p) {
    return (uint32_t)__cvta_generic_to_shared(p);
}
__device__ __forceinline__ void cp16(uint32_t dst, const void* src, int srcsize) {
    asm volatile("cp.async.cg.shared.global [%0], [%1], 16, %2;\n"
                 :: "r"(dst), "l"(src), "r"(srcsize));
}
__device__ __forceinline__ void cp_commit() {
    asm volatile("cp.async.commit_group;\n");
}
template<int N>
__device__ __forceinline__ void cp_wait() {
    asm volatile("cp.async.wait_group %0;\n" :: "n"(N));
}
__device__ __forceinline__ void ldsm4(uint32_t* r, uint32_t addr) {
    asm volatile("ldmatrix.sync.aligned.m8n8.x4.shared.b16 {%0,%1,%2,%3}, [%4];\n"
                 : "=r"(r[0]), "=r"(r[1]), "=r"(r[2]), "=r"(r[3]) : "r"(addr));
}
__device__ __forceinline__ void mma_bf16(float* d, const uint32_t* a, uint32_t b0, uint32_t b1) {
    asm volatile("mma.sync.aligned.m16n8k16.row.col.f32.bf16.bf16.f32 "
                 "{%0,%1,%2,%3},{%4,%5,%6,%7},{%8,%9},{%0,%1,%2,%3};\n"
                 : "+f"(d[0]), "+f"(d[1]), "+f"(d[2]), "+f"(d[3])
                 : "r"(a[0]), "r"(a[1]), "r"(a[2]), "r"(a[3]), "r"(b0), "r"(b1));
}

// ---------------------------------------------------------------------------
// Split-bf16 triple-product GEMM core, register-reuse schedule, K64 chunks.
//   C[M,N] = epi( A@W^T ), A = A_hi+A_lo, W = W_hi+W_lo, computed as
//   Ahi*Whi + Ahi*Wlo + Alo*Whi accumulated in fp32.
//   One pipeline stage = one K64 chunk = 8 K32 tiles {Ah,Al,Bh,Bl} x {k0,k1};
//   NSTG=2 ring (163840 B). ONE barrier + ONE cp.wait per K64 chunk.
//   BM=BN=128, 512 threads (16 warps, 32x32 tiles), 1 CTA/SM.
//   A may be a K-concat: cols [0,K1) from A, [K1,K) from A2 (K1 % 64 == 0).
//   Requires K % 64 == 0.
// ---------------------------------------------------------------------------
#define LDSH 40                         // halves per smem row (padded)
#define TILEB (128 * LDSH * 2)          // one K32 tile = 10240 bytes
#define GSMEM (16 * TILEB)              // 2 stages * 8 tiles = 163840 bytes

__device__ __forceinline__ void gemm_core(
    char* smem, int bx, int by,
    const bf16* __restrict__ Ahi, const bf16* __restrict__ Alo, int lda,
    const bf16* __restrict__ A2hi, const bf16* __restrict__ A2lo, int lda2, int K1,
    const bf16* __restrict__ Bhi, const bf16* __restrict__ Blo, int ldb,
    int N, int K,
    const float* __restrict__ b1, const float* __restrict__ b2,
    const float* __restrict__ addsrc, int ldadd,
    const float* __restrict__ gamma, const float* __restrict__ beta,
    float* __restrict__ Cf, int ldc,
    bf16* __restrict__ Chi, bf16* __restrict__ Clo, int ldsp)
{
    constexpr int BM = 128;
    const int tid  = threadIdx.x;
    const int lane = tid & 31;
    const int wid  = tid >> 5;          // 0..15
    const int wm   = wid >> 2;          // 4 warp rows (32 each)
    const int wn   = wid & 3;           // 4 warp cols (32 each)
    const int bm   = by * BM;
    const int bn   = bx * BM;

    const int NC = K / 64;              // K64 chunks

    float acc[2][4][4];
#pragma unroll
    for (int i = 0; i < 2; i++)
#pragma unroll
        for (int j = 0; j < 4; j++)
#pragma unroll
            for (int r = 0; r < 4; r++) acc[i][j][r] = 0.f;

    // one cp16 per thread per K32 tile (512 threads cover a 128x32 tile)
    const int srow = tid >> 2;
    const int skc  = (tid & 3) * 8;
    auto stage = [&](int c) {
        int k0 = c * 64;
        const bf16 *Ah, *Al; int ald, ak;
        if (k0 < K1) { Ah = Ahi;  Al = Alo;  ald = lda;  ak = k0; }
        else         { Ah = A2hi; Al = A2lo; ald = lda2; ak = k0 - K1; }
        uint32_t base = smem_u32(smem) + (c & 1) * (8 * TILEB);
        uint32_t soff = (srow * LDSH + skc) * 2;
        int n = bn + srow;
        bool ok = (n < N);
#pragma unroll
        for (int h = 0; h < 2; h++) {
            size_t aoff = (size_t)(bm + srow) * ald + ak + h * 32 + skc;
            cp16(base + (0 + h) * TILEB + soff, Ah + aoff, 16);
            cp16(base + (2 + h) * TILEB + soff, Al + aoff, 16);
            size_t boff = (size_t)(ok ? n : 0) * ldb + k0 + h * 32 + skc;
            cp16(base + (4 + h) * TILEB + soff, Bhi + boff, ok ? 16 : 0);
            cp16(base + (6 + h) * TILEB + soff, Blo + boff, ok ? 16 : 0);
        }
    };

    stage(0); cp_commit();

    // fragment addresses (fixed per thread, K-offset varies)
    const int arow = wm * 32 + (lane & 15);
    const int akk0 = (lane >> 4) * 8;
    const int brow = wn * 32 + (lane & 7) + ((lane >> 4) << 3);
    const int bkk0 = ((lane >> 3) & 1) << 3;

    for (int c = 0; c < NC; c++) {
        cp_wait<0>();
        __syncthreads();   // chunk c landed; all warps done reading chunk c-1
        if (c + 1 < NC) { stage(c + 1); cp_commit(); }

        uint32_t base = smem_u32(smem) + (c & 1) * (8 * TILEB);
#pragma unroll
        for (int h = 0; h < 2; h++) {
            uint32_t bAh = base + (0 + h) * TILEB;
            uint32_t bAl = base + (2 + h) * TILEB;
            uint32_t bBh = base + (4 + h) * TILEB;
            uint32_t bBl = base + (6 + h) * TILEB;
#pragma unroll
            for (int ks = 0; ks < 32; ks += 16) {
                uint32_t ah[2][4], al[2][4], bh[4][2], bl[4][2];
                const int akk = ks + akk0;
                const int bkk = ks + bkk0;
#pragma unroll
                for (int mi = 0; mi < 2; mi++) {
                    uint32_t ro = ((arow + mi * 16) * LDSH + akk) * 2;
                    ldsm4(ah[mi], bAh + ro);
                    ldsm4(al[mi], bAl + ro);
                }
#pragma unroll
                for (int ng = 0; ng < 2; ng++) {
                    uint32_t ro = ((brow + ng * 16) * LDSH + bkk) * 2;
                    uint32_t t[4];
                    ldsm4(t, bBh + ro);
                    bh[2 * ng][0] = t[0]; bh[2 * ng][1] = t[1];
                    bh[2 * ng + 1][0] = t[2]; bh[2 * ng + 1][1] = t[3];
                    ldsm4(t, bBl + ro);
                    bl[2 * ng][0] = t[0]; bl[2 * ng][1] = t[1];
                    bl[2 * ng + 1][0] = t[2]; bl[2 * ng + 1][1] = t[3];
                }
                // 3 products, full register reuse
#pragma unroll
                for (int mi = 0; mi < 2; mi++)
#pragma unroll
                    for (int nj = 0; nj < 4; nj++)
                        mma_bf16(acc[mi][nj], ah[mi], bh[nj][0], bh[nj][1]);
#pragma unroll
                for (int mi = 0; mi < 2; mi++)
#pragma unroll
                    for (int nj = 0; nj < 4; nj++)
                        mma_bf16(acc[mi][nj], ah[mi], bl[nj][0], bl[nj][1]);
#pragma unroll
                for (int mi = 0; mi < 2; mi++)
#pragma unroll
                    for (int nj = 0; nj < 4; nj++)
                        mma_bf16(acc[mi][nj], al[mi], bh[nj][0], bh[nj][1]);
            }
        }
    }

    // ---- epilogue (register-resident)
    const float inv_std = rsqrtf(1.0f + 1e-5f);
    const int g  = lane >> 2;
    const int tg = lane & 3;
#pragma unroll
    for (int mi = 0; mi < 2; mi++)
#pragma unroll
        for (int nj = 0; nj < 4; nj++)
#pragma unroll
            for (int r = 0; r < 4; r++) {
                int m = bm + wm * 32 + mi * 16 + g + ((r >> 1) << 3);
                int n = bn + wn * 32 + nj * 8 + tg * 2 + (r & 1);
                if (n >= N) continue;
                float v = acc[mi][nj][r];
                if (b1)     v += b1[n];
                if (b2)     v += b2[n];
                if (addsrc) v += addsrc[(size_t)m * ldadd + n];
                if (gamma)  v = fmaxf(0.f, v * (gamma[n] * inv_std) + beta[n]);
                if (Cf)     Cf[(size_t)m * ldc + n] = v;
                if (Chi) {
                    bf16 h = __float2bfloat16(v);
                    Chi[(size_t)m * ldsp + n] = h;
                    Clo[(size_t)m * ldsp + n] = __float2bfloat16(v - __bfloat162float(h));
                }
            }
}

// standalone GEMM launcher (512 threads, 1 CTA/SM)
__global__ void __launch_bounds__(512, 1)
gemm3_kernel(const bf16* Ahi, const bf16* Alo, int lda,
             const bf16* A2hi, const bf16* A2lo, int lda2, int K1,
             const bf16* Bhi, const bf16* Blo, int ldb,
             int N, int K,
             const float* b1, const float* b2,
             const float* addsrc, int ldadd,
             const float* gamma, const float* beta,
             float* Cf, int ldc,
             bf16* Chi, bf16* Clo, int ldsp)
{
    extern __shared__ char smem[];
    gemm_core(smem, blockIdx.x, blockIdx.y,
              Ahi, Alo, lda, A2hi, A2lo, lda2, K1, Bhi, Blo, ldb, N, K,
              b1, b2, addsrc, ldadd, gamma, beta, Cf, ldc, Chi, Clo, ldsp);
}

// fused per-step GEMM, fine split-K for load balance (320 CTAs x 4 K64-chunks):
//   bid 0..255:   Gl part p = bid>>6 (K = [p*256, p*256+256)), tile t = bid&63
//                 (bx = t>>1 over N=4096, by = t&1); addsrc = lgpre_t on p==0.
//   bid 256..319: Gs part p (K-half of 512), tile over N=2048; addsrc on p==0.
__global__ void __launch_bounds__(512, 1)
step_gemm_kernel(const bf16* hsh, const bf16* hsl, const bf16* Whsh, const bf16* Whsl,
                 const float* sgpre_t,
                 const bf16* hlh, const bf16* hll, const bf16* Whlh, const bf16* Whll,
                 const float* lgpre_t,
                 float* Gs2, float* Gl4)
{
    extern __shared__ char smem[];
    int bid = blockIdx.x;
    if (bid < 256) {
        int p  = bid >> 6;
        int t  = bid & 63;
        int bx = t >> 1, by = t & 1;
        gemm_core(smem, bx, by,
                  hlh + p * 256, hll + p * 256, 1024, nullptr, nullptr, 0, 256,
                  Whlh + p * 256, Whll + p * 256, 1024, 4096, 256,
                  nullptr, nullptr, (p == 0) ? lgpre_t : nullptr, TT * 4096,
                  nullptr, nullptr,
                  Gl4 + (size_t)p * BB * 4096, 4096, nullptr, nullptr, 0);
    } else {
        int t  = bid - 256;
        int p  = t >> 5;
        int tt = t & 31;
        int bx = tt >> 1, by = tt & 1;
        gemm_core(smem, bx, by,
                  hsh + p * 256, hsl + p * 256, 512, nullptr, nullptr, 0, 256,
                  Whsh + p * 256, Whsl + p * 256, 512, 2048, 256,
                  nullptr, nullptr, (p == 0) ? sgpre_t : nullptr, TT * 2048,
                  nullptr, nullptr,
                  Gs2 + (size_t)p * BB * 2048, 2048, nullptr, nullptr, 0);
    }
}

// ---------------------------------------------------------------------------
// Elementwise kernels
// ---------------------------------------------------------------------------
__device__ __forceinline__ float sigf(float x) { return 1.f / (1.f + expf(-x)); }
__device__ __forceinline__ void split1(float v, bf16* hi, bf16* lo, size_t i) {
    bf16 h = __float2bfloat16(v);
    hi[i] = h;
    lo[i] = __float2bfloat16(v - __bfloat162float(h));
}

// one fused split kernel over all 9 tensors (float4-vectorized, grid-stride)
struct SJob { const float4* src; __nv_bfloat162* hi; __nv_bfloat162* lo; };
struct SJobs { SJob j[9]; unsigned cum[10]; };

__global__ void __launch_bounds__(256)
split_all_kernel(SJobs jb, unsigned total4)
{
    const unsigned stride = gridDim.x * blockDim.x;
    for (unsigned i = blockIdx.x * blockDim.x + threadIdx.x; i < total4; i += stride) {
        int k = 0;
#pragma unroll
        for (int q = 0; q < 8; q++) if (i >= jb.cum[q + 1]) k = q + 1;
        unsigned off = i - jb.cum[k];
        float4 v = jb.j[k].src[off];
        bf16 h0 = __float2bfloat16(v.x), h1 = __float2bfloat16(v.y);
        bf16 h2 = __float2bfloat16(v.z), h3 = __float2bfloat16(v.w);
        bf16 l0 = __float2bfloat16(v.x - __bfloat162float(h0));
        bf16 l1 = __float2bfloat16(v.y - __bfloat162float(h1));
        bf16 l2 = __float2bfloat16(v.z - __bfloat162float(h2));
        bf16 l3 = __float2bfloat16(v.w - __bfloat162float(h3));
        jb.j[k].hi[2 * off]     = __nv_bfloat162(h0, h1);
        jb.j[k].hi[2 * off + 1] = __nv_bfloat162(h2, h3);
        jb.j[k].lo[2 * off]     = __nv_bfloat162(l0, l1);
        jb.j[k].lo[2 * off + 1] = __nv_bfloat162(l2, l3);
    }
}

__global__ void zero_states_kernel(float* hl, float* cl, float* hs, float* cs,
                                   bf16* hlh, bf16* hll, bf16* hsh, bf16* hsl)
{
    int i = blockIdx.x * blockDim.x + threadIdx.x;
    if (i < BB * LL) { hl[i] = 0.f; cl[i] = 0.f; hlh[i] = __float2bfloat16(0.f); hll[i] = __float2bfloat16(0.f); }
    if (i < BB * SS) { hs[i] = 0.f; cs[i] = 0.f; hsh[i] = __float2bfloat16(0.f); hsl[i] = __float2bfloat16(0.f); }
}

// fused per-step post-GEMM kernel: small LSTM act + hard gate + large act/merge.
// One block per batch row. Gl = sum of 4 split-K partials; Gs = sum of 2.
__global__ void __launch_bounds__(256)
step_post_kernel(const float* __restrict__ Gs2, const float* __restrict__ Gl4,
                 const float* __restrict__ sfeats, int t,
                 const float* __restrict__ h_old, const float* __restrict__ c_old,
                 const float* __restrict__ cs_old,
                 float* __restrict__ hs_new, float* __restrict__ cs_new,
                 bf16* __restrict__ hsh, bf16* __restrict__ hsl,
                 const float* __restrict__ W_g, const float* __restrict__ b_g,
                 float* __restrict__ r_out,
                 float* __restrict__ h_new, float* __restrict__ c_new,
                 bf16* __restrict__ hh, bf16* __restrict__ hl)
{
    const int b   = blockIdx.x;
    const int tid = threadIdx.x;
    __shared__ float sh_h[SS], sh_c[SS];
    __shared__ float s0[256], s1[256];
    __shared__ float r0sh;

    // ---- small LSTM activation (Gs = part0 + part1)
    const float* gs0 = Gs2 + (size_t)b * (4 * SS);
    const float* gs1 = Gs2 + (size_t)BB * 2048 + (size_t)b * (4 * SS);
    for (int n = tid; n < SS; n += 256) {
        float i_ = sigf(gs0[n] + gs1[n]);
        float f_ = sigf(gs0[SS + n] + gs1[SS + n]);
        float gg = tanhf(gs0[2 * SS + n] + gs1[2 * SS + n]);
        float o_ = sigf(gs0[3 * SS + n] + gs1[3 * SS + n]);
        float c2 = f_ * cs_old[(size_t)b * SS + n] + i_ * gg;
        float h2 = o_ * tanhf(c2);
        sh_h[n] = h2; sh_c[n] = c2;
        cs_new[(size_t)b * SS + n] = c2;
        hs_new[(size_t)b * SS + n] = h2;
        split1(h2, hsh, hsl, (size_t)b * SS + n);
    }

    // ---- hard gate on OLD large state: r = one_hot(argmax(p))
    const float* s = sfeats + ((size_t)b * TT + t) * SS;
    const float* h = h_old + (size_t)b * LL;
    const float* c = c_old + (size_t)b * LL;
    const float* w0 = W_g;
    const float* w1 = W_g + 2560;
    float p0 = 0.f, p1 = 0.f;
    for (int j = tid; j < SS; j += 256) { float v = s[j]; p0 += v * w0[j]; p1 += v * w1[j]; }
    for (int j = tid; j < LL; j += 256) { float v = h[j]; p0 += v * w0[SS + j]; p1 += v * w1[SS + j]; }
    for (int j = tid; j < LL; j += 256) { float v = c[j]; p0 += v * w0[SS + LL + j]; p1 += v * w1[SS + LL + j]; }
    s0[tid] = p0; s1[tid] = p1;
    __syncthreads();                       // also publishes sh_h/sh_c
    for (int st = 128; st > 0; st >>= 1) {
        if (tid < st) { s0[tid] += s0[tid + st]; s1[tid] += s1[tid + st]; }
        __syncthreads();
    }
    if (tid == 0) {
        float r0 = (s0[0] + b_g[0] >= s1[0] + b_g[1]) ? 1.f : 0.f;
        r0sh = r0;
        r_out[b * 2 + 0] = r0;
        r_out[b * 2 + 1] = 1.f - r0;
    }
    __syncthreads();
    const float r0 = r0sh, r1 = 1.f - r0sh;

    // ---- large LSTM activation + straight-through merge (Gl = 4 partials)
    const float* gA = Gl4 + (size_t)b * (4 * LL);
    const float* gB = Gl4 + (size_t)BB * 4096 + (size_t)b * (4 * LL);
    const float* gC = Gl4 + (size_t)2 * BB * 4096 + (size_t)b * (4 * LL);
    const float* gD = Gl4 + (size_t)3 * BB * 4096 + (size_t)b * (4 * LL);
    for (int n = tid; n < LL; n += 256) {
        size_t idx = (size_t)b * LL + n;
        float i_ = sigf(gA[n] + gB[n] + gC[n] + gD[n]);
        float f_ = sigf(gA[LL + n] + gB[LL + n] + gC[LL + n] + gD[LL + n]);
        float gg = tanhf(gA[2 * LL + n] + gB[2 * LL + n] + gC[2 * LL + n] + gD[2 * LL + n]);
        float o_ = sigf(gA[3 * LL + n] + gB[3 * LL + n] + gC[3 * LL + n] + gD[3 * LL + n]);
        float c_ln = f_ * c_old[idx] + i_ * gg;
        float h_ln = o_ * tanhf(c_ln);
        float ph = (n < SS) ? sh_h[n] : h_old[idx];
        float pc = (n < SS) ? sh_c[n] : c_old[idx];
        float h2 = r0 * h_ln + r1 * ph;
        c_new[idx] = r0 * c_ln + r1 * pc;
        h_new[idx] = h2;
        split1(h2, hh, hl, idx);
    }
}

// ---------------------------------------------------------------------------
// Launch
// ---------------------------------------------------------------------------
static inline float* fsym(const void* s) { void* p = nullptr; cudaGetSymbolAddress(&p, s); return (float*)p; }
static inline bf16*  bsym(const void* s) { void* p = nullptr; cudaGetSymbolAddress(&p, s); return (bf16*)p; }

extern "C" void kernel_launch(void* const* d_in, const int* in_sizes, int n_in,
                              void* d_out, int out_size)
{
    const float* x     = (const float*)d_in[0];
    const float* xs    = (const float*)d_in[1];
    const float* W_p   = (const float*)d_in[2];
    const float* b_p   = (const float*)d_in[3];
    const float* g_p   = (const float*)d_in[4];
    const float* be_p  = (const float*)d_in[5];
    const float* W_s   = (const float*)d_in[6];
    const float* b_s   = (const float*)d_in[7];
    const float* g_s   = (const float*)d_in[8];
    const float* be_s  = (const float*)d_in[9];
    const float* Wih_l = (const float*)d_in[10];
    const float* Whh_l = (const float*)d_in[11];
    const float* bih_l = (const float*)d_in[12];
    const float* bhh_l = (const float*)d_in[13];
    const float* Wih_s = (const float*)d_in[14];
    const float* Whh_s = (const float*)d_in[15];
    const float* bih_s = (const float*)d_in[16];
    const float* bhh_s = (const float*)d_in[17];
    const float* W_g   = (const float*)d_in[18];
    const float* b_g   = (const float*)d_in[19];
    const float* W_c   = (const float*)d_in[20];
    const float* b_c   = (const float*)d_in[21];

    float* out = (float*)d_out;
    float* out_logits = out;
    float* out_r      = out + BB * NCLS;

    bf16 *xh = bsym(g_x_hi), *xl = bsym(g_x_lo);
    bf16 *xsh = bsym(g_xs_hi), *xsl = bsym(g_xs_lo);
    bf16 *fh = bsym(g_f_hi), *fl = bsym(g_f_lo);
    bf16 *sfh = bsym(g_sf_hi), *sfl = bsym(g_sf_lo);
    bf16 *Wph = bsym(g_Wp_hi), *Wpl = bsym(g_Wp_lo);
    bf16 *Wsh = bsym(g_Ws_hi), *Wsl = bsym(g_Ws_lo);
    bf16 *Wlh = bsym(g_Wl_hi), *Wll = bsym(g_Wl_lo);
    bf16 *Whlh = bsym(g_Whl_hi), *Whll = bsym(g_Whl_lo);
    bf16 *Wish = bsym(g_Wis_hi), *Wisl = bsym(g_Wis_lo);
    bf16 *Whsh = bsym(g_Whs_hi), *Whsl = bsym(g_Whs_lo);
    bf16 *Wch = bsym(g_Wc_hi), *Wcl = bsym(g_Wc_lo);

    float* sfeats = fsym(g_sfeats);
    float* sgpre  = fsym(g_sgpre);
    float* lgpre  = fsym(g_lgpre);
    float* Gs2 = fsym(g_Gs2);
    float* Gl4 = fsym(g_Gl4);
    float* hl = fsym(g_hl);
    float* cl = fsym(g_cl);
    float* hs = fsym(g_hs);
    float* cs = fsym(g_cs);
    bf16* hlh = bsym(g_hl_hi); bf16* hll = bsym(g_hl_lo);
    bf16* hsh = bsym(g_hs_hi); bf16* hsl = bsym(g_hs_lo);

    cudaFuncSetAttribute(gemm3_kernel, cudaFuncAttributeMaxDynamicSharedMemorySize, GSMEM);
    cudaFuncSetAttribute(step_gemm_kernel, cudaFuncAttributeMaxDynamicSharedMemorySize, GSMEM);

    const int TPB = 256;

    // ---- fused split of all inputs & weights into bf16 pairs
    {
        SJobs jb;
        const float* srcs[9] = { x, xs, W_p, W_s, Wih_l, Whh_l, Wih_s, Whh_s, W_c };
        bf16* his[9] = { xh, xsh, Wph, Wsh, Wlh, Whlh, Wish, Whsh, Wch };
        bf16* los[9] = { xl, xsl, Wpl, Wsl, Wll, Whll, Wisl, Whsl, Wcl };
        long  ns [9] = { (long)MBT * 2048, (long)MBT * 1280, 2048L * 2048, 512L * 1280,
                         4096L * 2560, 4096L * 1024, 2048L * 512, 2048L * 512,
                         (long)NCLS * 1024 };
        unsigned cum = 0;
        for (int k = 0; k < 9; k++) {
            jb.j[k].src = (const float4*)srcs[k];
            jb.j[k].hi  = (__nv_bfloat162*)his[k];
            jb.j[k].lo  = (__nv_bfloat162*)los[k];
            jb.cum[k] = cum;
            cum += (unsigned)(ns[k] / 4);
        }
        jb.cum[9] = cum;
        int grid = (int)((cum / 2 + TPB - 1) / TPB);     // 2 float4 per thread
        split_all_kernel<<<grid, TPB>>>(jb, cum);
    }
    zero_states_kernel<<<(BB * LL + 255) / 256, TPB>>>(hl, cl, hs, cs, hlh, hll, hsh, hsl);

    // ---- Phase 1: time-parallel GEMMs
    // feats(split) = relu(BN(x @ W_p^T + b_p))
    gemm3_kernel<<<dim3(2048 / 128, MBT / 128), 512, GSMEM>>>(
        xh, xl, 2048, nullptr, nullptr, 0, 2048,
        Wph, Wpl, 2048, 2048, 2048,
        b_p, nullptr, nullptr, 0, g_p, be_p,
        nullptr, 0, fh, fl, 2048);
    // sfeats(fp32+split) = relu(BN(xs @ W_s^T + b_s))
    gemm3_kernel<<<dim3(512 / 128, MBT / 128), 512, GSMEM>>>(
        xsh, xsl, 1280, nullptr, nullptr, 0, 1280,
        Wsh, Wsl, 1280, 512, 1280,
        b_s, nullptr, nullptr, 0, g_s, be_s,
        sfeats, 512, sfh, sfl, 512);
    // sgpre = sfeats @ Wih_s^T + bih_s + bhh_s
    gemm3_kernel<<<dim3(2048 / 128, MBT / 128), 512, GSMEM>>>(
        sfh, sfl, 512, nullptr, nullptr, 0, 512,
        Wish, Wisl, 512, 2048, 512,
        bih_s, bhh_s, nullptr, 0, nullptr, nullptr,
        sgpre, 2048, nullptr, nullptr, 0);
    // lgpre = [feats, sfeats] @ Wih_l^T + bih_l + bhh_l   (K-concat 2048+512)
    gemm3_kernel<<<dim3(4096 / 128, MBT / 128), 512, GSMEM>>>(
        fh, fl, 2048, sfh, sfl, 512, 2048,
        Wlh, Wll, 2560, 4096, 2560,
        bih_l, bhh_l, nullptr, 0, nullptr, nullptr,
        lgpre, 4096, nullptr, nullptr, 0);

    // ---- Phase 2: recurrence (2 launches per step)
    for (int t = 0; t < TT; t++) {
        int cur = t & 1, nxt = 1 - cur;
        float* hl_c = hl + (size_t)cur * BB * LL;
        float* cl_c = cl + (size_t)cur * BB * LL;
        float* hl_n = hl + (size_t)nxt * BB * LL;
        float* cl_n = cl + (size_t)nxt * BB * LL;
        float* cs_c = cs + (size_t)cur * BB * SS;
        float* hs_n = hs + (size_t)nxt * BB * SS;
        float* cs_n = cs + (size_t)nxt * BB * SS;
        bf16* hlh_c = hlh + (size_t)cur * BB * LL;
        bf16* hll_c = hll + (size_t)cur * BB * LL;
        bf16* hlh_n = hlh + (size_t)nxt * BB * LL;
        bf16* hll_n = hll + (size_t)nxt * BB * LL;
        bf16* hsh_c = hsh + (size_t)cur * BB * SS;
        bf16* hsl_c = hsl + (size_t)cur * BB * SS;
        bf16* hsh_n = hsh + (size_t)nxt * BB * SS;
        bf16* hsl_n = hsl + (size_t)nxt * BB * SS;
        float* r_t = out_r + (size_t)t * BB * 2;

        step_gemm_kernel<<<320, 512, GSMEM>>>(
            hsh_c, hsl_c, Whsh, Whsl, sgpre + (size_t)t * 2048,
            hlh_c, hll_c, Whlh, Whll, lgpre + (size_t)t * 4096,
            Gs2, Gl4);
        step_post_kernel<<<BB, 256>>>(
            Gs2, Gl4, sfeats, t, hl_c, cl_c, cs_c,
            hs_n, cs_n, hsh_n, hsl_n,
            W_g, b_g, r_t, hl_n, cl_n, hlh_n, hll_n);
    }

    // ---- classifier on final h_l (buffer 0 after 64 steps)
    gemm3_kernel<<<dim3((NCLS + 127) / 128, BB / 128), 512, GSMEM>>>(
        hlh, hll, 1024, nullptr, nullptr, 0, 1024,
        Wch, Wcl, 1024, NCLS, 1024,
        b_c, nullptr, nullptr, 0, nullptr, nullptr,
        out_logits, NCLS, nullptr, nullptr, 0);
}

// round 11
// speedup vs baseline: 1.0377x; 1.0377x over previous
#include <cuda_runtime.h>
#include <cuda_bf16.h>
#include <math.h>
#include <stdint.h>

// ---------------------------------------------------------------------------
// Problem constants
// ---------------------------------------------------------------------------
#define BB 256
#define TT 64
#define LL 1024
#define SS 512
#define NCLS 239
#define MBT (BB * TT)          // 16384

typedef __nv_bfloat16 bf16;

// ---------------------------------------------------------------------------
// Scratch (device globals; no runtime allocation allowed)
// ---------------------------------------------------------------------------
__device__ bf16 g_x_hi  [MBT * 2048];
__device__ bf16 g_x_lo  [MBT * 2048];
__device__ bf16 g_xs_hi [MBT * 1280];
__device__ bf16 g_xs_lo [MBT * 1280];
__device__ bf16 g_f_hi  [MBT * 2048];
__device__ bf16 g_f_lo  [MBT * 2048];
__device__ bf16 g_sf_hi [MBT * 512];
__device__ bf16 g_sf_lo [MBT * 512];
__device__ bf16 g_Wp_hi [2048 * 2048];
__device__ bf16 g_Wp_lo [2048 * 2048];
__device__ bf16 g_Ws_hi [512 * 1280];
__device__ bf16 g_Ws_lo [512 * 1280];
__device__ bf16 g_Wl_hi [4096 * 2560];   // Wih_l full (K-concat GEMM)
__device__ bf16 g_Wl_lo [4096 * 2560];
__device__ bf16 g_Whl_hi[4096 * 1024];   // Whh_l
__device__ bf16 g_Whl_lo[4096 * 1024];
__device__ bf16 g_Wis_hi[2048 * 512];    // Wih_s
__device__ bf16 g_Wis_lo[2048 * 512];
__device__ bf16 g_Whs_hi[2048 * 512];    // Whh_s
__device__ bf16 g_Whs_lo[2048 * 512];
__device__ bf16 g_Wc_hi [NCLS * 1024];
__device__ bf16 g_Wc_lo [NCLS * 1024];
__device__ float g_sfeats[MBT * 512];
__device__ float g_sgpre [MBT * 2048];
__device__ float g_lgpre [MBT * 4096];
__device__ float g_Gs2[2][BB * 2048];    // Gs split-K partials
__device__ float g_Gl4[4][BB * 4096];    // Gl split-K partials
__device__ float g_hl[2][BB * LL];
__device__ float g_cl[2][BB * LL];
__device__ float g_hs[2][BB * SS];
__device__ float g_cs[2][BB * SS];
__device__ bf16 g_hl_hi[2][BB * LL];
__device__ bf16 g_hl_lo[2][BB * LL];
__device__ bf16 g_hs_hi[2][BB * SS];
__device__ bf16 g_hs_lo[2][BB * SS];

// ---------------------------------------------------------------------------
// PTX helpers (legacy tensor path only — harness targets compute_100)
// ---------------------------------------------------------------------------
__device__ __forceinline__ uint32_t smem_u32(const void* p) {
    return (uint32_t)__cvta_generic_to_shared(p);
}
__device__ __forceinline__ void cp16(uint32_t dst, const void* src, int srcsize) {
    asm volatile("cp.async.cg.shared.global [%0], [%1], 16, %2;\n"
                 :: "r"(dst), "l"(src), "r"(srcsize));
}
__device__ __forceinline__ void cp_commit() {
    asm volatile("cp.async.commit_group;\n");
}
template<int N>
__device__ __forceinline__ void cp_wait() {
    asm volatile("cp.async.wait_group %0;\n" :: "n"(N));
}
__device__ __forceinline__ void ldsm4(uint32_t* r, uint32_t addr) {
    asm volatile("ldmatrix.sync.aligned.m8n8.x4.shared.b16 {%0,%1,%2,%3}, [%4];\n"
                 : "=r"(r[0]), "=r"(r[1]), "=r"(r[2]), "=r"(r[3]) : "r"(addr));
}
__device__ __forceinline__ void mma_bf16(float* d, const uint32_t* a, uint32_t b0, uint32_t b1) {
    asm volatile("mma.sync.aligned.m16n8k16.row.col.f32.bf16.bf16.f32 "
                 "{%0,%1,%2,%3},{%4,%5,%6,%7},{%8,%9},{%0,%1,%2,%3};\n"
                 : "+f"(d[0]), "+f"(d[1]), "+f"(d[2]), "+f"(d[3])
                 : "r"(a[0]), "r"(a[1]), "r"(a[2]), "r"(a[3]), "r"(b0), "r"(b1));
}

// ---------------------------------------------------------------------------
// Split-bf16 triple-product GEMM core, register-reuse schedule, K64 chunks.
//   C[M,N] = epi( A@W^T ), A = A_hi+A_lo, W = W_hi+W_lo, computed as
//   Ahi*Whi + Ahi*Wlo + Alo*Whi accumulated in fp32.
//   One pipeline stage = one K64 chunk = 8 K32 tiles {Ah,Al,Bh,Bl} x {k0,k1};
//   NSTG=2 ring (163840 B). ONE barrier + ONE cp.wait per K64 chunk.
//   BM=BN=128, 512 threads (16 warps, 32x32 tiles), 1 CTA/SM.
//   A may be a K-concat: cols [0,K1) from A, [K1,K) from A2 (K1 % 64 == 0).
//   Requires K % 64 == 0.
// ---------------------------------------------------------------------------
#define LDSH 40                         // halves per smem row (padded)
#define TILEB (128 * LDSH * 2)          // one K32 tile = 10240 bytes
#define GSMEM (16 * TILEB)              // 2 stages * 8 tiles = 163840 bytes

__device__ __forceinline__ void gemm_core(
    char* smem, int bx, int by,
    const bf16* __restrict__ Ahi, const bf16* __restrict__ Alo, int lda,
    const bf16* __restrict__ A2hi, const bf16* __restrict__ A2lo, int lda2, int K1,
    const bf16* __restrict__ Bhi, const bf16* __restrict__ Blo, int ldb,
    int N, int K,
    const float* __restrict__ b1, const float* __restrict__ b2,
    const float* __restrict__ addsrc, int ldadd,
    const float* __restrict__ gamma, const float* __restrict__ beta,
    float* __restrict__ Cf, int ldc,
    bf16* __restrict__ Chi, bf16* __restrict__ Clo, int ldsp)
{
    constexpr int BM = 128;
    const int tid  = threadIdx.x;
    const int lane = tid & 31;
    const int wid  = tid >> 5;          // 0..15
    const int wm   = wid >> 2;          // 4 warp rows (32 each)
    const int wn   = wid & 3;           // 4 warp cols (32 each)
    const int bm   = by * BM;
    const int bn   = bx * BM;

    const int NC = K / 64;              // K64 chunks

    float acc[2][4][4];
#pragma unroll
    for (int i = 0; i < 2; i++)
#pragma unroll
        for (int j = 0; j < 4; j++)
#pragma unroll
            for (int r = 0; r < 4; r++) acc[i][j][r] = 0.f;

    // one cp16 per thread per K32 tile (512 threads cover a 128x32 tile)
    const int srow = tid >> 2;
    const int skc  = (tid & 3) * 8;
    auto stage = [&](int c) {
        int k0 = c * 64;
        const bf16 *Ah, *Al; int ald, ak;
        if (k0 < K1) { Ah = Ahi;  Al = Alo;  ald = lda;  ak = k0; }
        else         { Ah = A2hi; Al = A2lo; ald = lda2; ak = k0 - K1; }
        uint32_t base = smem_u32(smem) + (c & 1) * (8 * TILEB);
        uint32_t soff = (srow * LDSH + skc) * 2;
        int n = bn + srow;
        bool ok = (n < N);
#pragma unroll
        for (int h = 0; h < 2; h++) {
            size_t aoff = (size_t)(bm + srow) * ald + ak + h * 32 + skc;
            cp16(base + (0 + h) * TILEB + soff, Ah + aoff, 16);
            cp16(base + (2 + h) * TILEB + soff, Al + aoff, 16);
            size_t boff = (size_t)(ok ? n : 0) * ldb + k0 + h * 32 + skc;
            cp16(base + (4 + h) * TILEB + soff, Bhi + boff, ok ? 16 : 0);
            cp16(base + (6 + h) * TILEB + soff, Blo + boff, ok ? 16 : 0);
        }
    };

    stage(0); cp_commit();

    // fragment addresses (fixed per thread, K-offset varies)
    const int arow = wm * 32 + (lane & 15);
    const int akk0 = (lane >> 4) * 8;
    const int brow = wn * 32 + (lane & 7) + ((lane >> 4) << 3);
    const int bkk0 = ((lane >> 3) & 1) << 3;

    for (int c = 0; c < NC; c++) {
        cp_wait<0>();
        __syncthreads();   // chunk c landed; all warps done reading chunk c-1
        if (c + 1 < NC) { stage(c + 1); cp_commit(); }

        uint32_t base = smem_u32(smem) + (c & 1) * (8 * TILEB);
#pragma unroll
        for (int h = 0; h < 2; h++) {
            uint32_t bAh = base + (0 + h) * TILEB;
            uint32_t bAl = base + (2 + h) * TILEB;
            uint32_t bBh = base + (4 + h) * TILEB;
            uint32_t bBl = base + (6 + h) * TILEB;
#pragma unroll
            for (int ks = 0; ks < 32; ks += 16) {
                uint32_t ah[2][4], al[2][4], bh[4][2], bl[4][2];
                const int akk = ks + akk0;
                const int bkk = ks + bkk0;
#pragma unroll
                for (int mi = 0; mi < 2; mi++) {
                    uint32_t ro = ((arow + mi * 16) * LDSH + akk) * 2;
                    ldsm4(ah[mi], bAh + ro);
                    ldsm4(al[mi], bAl + ro);
                }
#pragma unroll
                for (int ng = 0; ng < 2; ng++) {
                    uint32_t ro = ((brow + ng * 16) * LDSH + bkk) * 2;
                    uint32_t t[4];
                    ldsm4(t, bBh + ro);
                    bh[2 * ng][0] = t[0]; bh[2 * ng][1] = t[1];
                    bh[2 * ng + 1][0] = t[2]; bh[2 * ng + 1][1] = t[3];
                    ldsm4(t, bBl + ro);
                    bl[2 * ng][0] = t[0]; bl[2 * ng][1] = t[1];
                    bl[2 * ng + 1][0] = t[2]; bl[2 * ng + 1][1] = t[3];
                }
                // 3 products, full register reuse
#pragma unroll
                for (int mi = 0; mi < 2; mi++)
#pragma unroll
                    for (int nj = 0; nj < 4; nj++)
                        mma_bf16(acc[mi][nj], ah[mi], bh[nj][0], bh[nj][1]);
#pragma unroll
                for (int mi = 0; mi < 2; mi++)
#pragma unroll
                    for (int nj = 0; nj < 4; nj++)
                        mma_bf16(acc[mi][nj], ah[mi], bl[nj][0], bl[nj][1]);
#pragma unroll
                for (int mi = 0; mi < 2; mi++)
#pragma unroll
                    for (int nj = 0; nj < 4; nj++)
                        mma_bf16(acc[mi][nj], al[mi], bh[nj][0], bh[nj][1]);
            }
        }
    }

    // ---- epilogue (register-resident)
    const float inv_std = rsqrtf(1.0f + 1e-5f);
    const int g  = lane >> 2;
    const int tg = lane & 3;
#pragma unroll
    for (int mi = 0; mi < 2; mi++)
#pragma unroll
        for (int nj = 0; nj < 4; nj++)
#pragma unroll
            for (int r = 0; r < 4; r++) {
                int m = bm + wm * 32 + mi * 16 + g + ((r >> 1) << 3);
                int n = bn + wn * 32 + nj * 8 + tg * 2 + (r & 1);
                if (n >= N) continue;
                float v = acc[mi][nj][r];
                if (b1)     v += b1[n];
                if (b2)     v += b2[n];
                if (addsrc) v += addsrc[(size_t)m * ldadd + n];
                if (gamma)  v = fmaxf(0.f, v * (gamma[n] * inv_std) + beta[n]);
                if (Cf)     Cf[(size_t)m * ldc + n] = v;
                if (Chi) {
                    bf16 h = __float2bfloat16(v);
                    Chi[(size_t)m * ldsp + n] = h;
                    Clo[(size_t)m * ldsp + n] = __float2bfloat16(v - __bfloat162float(h));
                }
            }
}

// standalone GEMM launcher (512 threads, 1 CTA/SM) — used for the classifier
__global__ void __launch_bounds__(512, 1)
gemm3_kernel(const bf16* Ahi, const bf16* Alo, int lda,
             const bf16* A2hi, const bf16* A2lo, int lda2, int K1,
             const bf16* Bhi, const bf16* Blo, int ldb,
             int N, int K,
             const float* b1, const float* b2,
             const float* addsrc, int ldadd,
             const float* gamma, const float* beta,
             float* Cf, int ldc,
             bf16* Chi, bf16* Clo, int ldsp)
{
    extern __shared__ char smem[];
    gemm_core(smem, blockIdx.x, blockIdx.y,
              Ahi, Alo, lda, A2hi, A2lo, lda2, K1, Bhi, Blo, ldb, N, K,
              b1, b2, addsrc, ldadd, gamma, beta, Cf, ldc, Chi, Clo, ldsp);
}

// merged phase-1 launch A: feats (2048 CTAs, K=2048, long — first) then
// sfeats (512 CTAs, K=1280). Short jobs backfill the long jobs' tail wave.
__global__ void __launch_bounds__(512, 1)
phase1a_kernel(const bf16* xh, const bf16* xl, const bf16* Wph, const bf16* Wpl,
               const float* b_p, const float* g_p, const float* be_p,
               bf16* fh, bf16* fl,
               const bf16* xsh, const bf16* xsl, const bf16* Wsh, const bf16* Wsl,
               const float* b_s, const float* g_s, const float* be_s,
               float* sfeats, bf16* sfh, bf16* sfl)
{
    extern __shared__ char smem[];
    int bid = blockIdx.x;
    if (bid < 2048) {
        gemm_core(smem, bid & 15, bid >> 4,
                  xh, xl, 2048, nullptr, nullptr, 0, 2048,
                  Wph, Wpl, 2048, 2048, 2048,
                  b_p, nullptr, nullptr, 0, g_p, be_p,
                  nullptr, 0, fh, fl, 2048);
    } else {
        int t = bid - 2048;
        gemm_core(smem, t & 3, t >> 2,
                  xsh, xsl, 1280, nullptr, nullptr, 0, 1280,
                  Wsh, Wsl, 1280, 512, 1280,
                  b_s, nullptr, nullptr, 0, g_s, be_s,
                  sfeats, 512, sfh, sfl, 512);
    }
}

// merged phase-1 launch B: lgpre (4096 CTAs, K=2560, long — first) then
// sgpre (2048 CTAs, K=512).
__global__ void __launch_bounds__(512, 1)
phase1b_kernel(const bf16* fh, const bf16* fl, const bf16* sfh, const bf16* sfl,
               const bf16* Wlh, const bf16* Wll,
               const float* bih_l, const float* bhh_l, float* lgpre,
               const bf16* Wish, const bf16* Wisl,
               const float* bih_s, const float* bhh_s, float* sgpre)
{
    extern __shared__ char smem[];
    int bid = blockIdx.x;
    if (bid < 4096) {
        gemm_core(smem, bid & 31, bid >> 5,
                  fh, fl, 2048, sfh, sfl, 512, 2048,
                  Wlh, Wll, 2560, 4096, 2560,
                  bih_l, bhh_l, nullptr, 0, nullptr, nullptr,
                  lgpre, 4096, nullptr, nullptr, 0);
    } else {
        int t = bid - 4096;
        gemm_core(smem, t & 15, t >> 4,
                  sfh, sfl, 512, nullptr, nullptr, 0, 512,
                  Wish, Wisl, 512, 2048, 512,
                  bih_s, bhh_s, nullptr, 0, nullptr, nullptr,
                  sgpre, 2048, nullptr, nullptr, 0);
    }
}

// fused per-step GEMM, fine split-K for load balance (320 CTAs x 4 K64-chunks):
//   bid 0..255:   Gl part p = bid>>6 (K = [p*256, p*256+256)), tile t = bid&63
//                 (bx = t>>1 over N=4096, by = t&1); addsrc = lgpre_t on p==0.
//   bid 256..319: Gs part p (K-half of 512), tile over N=2048; addsrc on p==0.
__global__ void __launch_bounds__(512, 1)
step_gemm_kernel(const bf16* hsh, const bf16* hsl, const bf16* Whsh, const bf16* Whsl,
                 const float* sgpre_t,
                 const bf16* hlh, const bf16* hll, const bf16* Whlh, const bf16* Whll,
                 const float* lgpre_t,
                 float* Gs2, float* Gl4)
{
    extern __shared__ char smem[];
    int bid = blockIdx.x;
    if (bid < 256) {
        int p  = bid >> 6;
        int t  = bid & 63;
        int bx = t >> 1, by = t & 1;
        gemm_core(smem, bx, by,
                  hlh + p * 256, hll + p * 256, 1024, nullptr, nullptr, 0, 256,
                  Whlh + p * 256, Whll + p * 256, 1024, 4096, 256,
                  nullptr, nullptr, (p == 0) ? lgpre_t : nullptr, TT * 4096,
                  nullptr, nullptr,
                  Gl4 + (size_t)p * BB * 4096, 4096, nullptr, nullptr, 0);
    } else {
        int t  = bid - 256;
        int p  = t >> 5;
        int tt = t & 31;
        int bx = tt >> 1, by = tt & 1;
        gemm_core(smem, bx, by,
                  hsh + p * 256, hsl + p * 256, 512, nullptr, nullptr, 0, 256,
                  Whsh + p * 256, Whsl + p * 256, 512, 2048, 256,
                  nullptr, nullptr, (p == 0) ? sgpre_t : nullptr, TT * 2048,
                  nullptr, nullptr,
                  Gs2 + (size_t)p * BB * 2048, 2048, nullptr, nullptr, 0);
    }
}

// ---------------------------------------------------------------------------
// Elementwise kernels
// ---------------------------------------------------------------------------
__device__ __forceinline__ float sigf(float x) { return 1.f / (1.f + expf(-x)); }
__device__ __forceinline__ void split1(float v, bf16* hi, bf16* lo, size_t i) {
    bf16 h = __float2bfloat16(v);
    hi[i] = h;
    lo[i] = __float2bfloat16(v - __bfloat162float(h));
}

// one fused split kernel over all 9 tensors (float4-vectorized, grid-stride)
struct SJob { const float4* src; __nv_bfloat162* hi; __nv_bfloat162* lo; };
struct SJobs { SJob j[9]; unsigned cum[10]; };

__global__ void __launch_bounds__(256)
split_all_kernel(SJobs jb, unsigned total4)
{
    const unsigned stride = gridDim.x * blockDim.x;
    for (unsigned i = blockIdx.x * blockDim.x + threadIdx.x; i < total4; i += stride) {
        int k = 0;
#pragma unroll
        for (int q = 0; q < 8; q++) if (i >= jb.cum[q + 1]) k = q + 1;
        unsigned off = i - jb.cum[k];
        float4 v = jb.j[k].src[off];
        bf16 h0 = __float2bfloat16(v.x), h1 = __float2bfloat16(v.y);
        bf16 h2 = __float2bfloat16(v.z), h3 = __float2bfloat16(v.w);
        bf16 l0 = __float2bfloat16(v.x - __bfloat162float(h0));
        bf16 l1 = __float2bfloat16(v.y - __bfloat162float(h1));
        bf16 l2 = __float2bfloat16(v.z - __bfloat162float(h2));
        bf16 l3 = __float2bfloat16(v.w - __bfloat162float(h3));
        jb.j[k].hi[2 * i - 2 * jb.cum[k]]     = __nv_bfloat162(h0, h1);
        jb.j[k].hi[2 * i - 2 * jb.cum[k] + 1] = __nv_bfloat162(h2, h3);
        jb.j[k].lo[2 * off]     = __nv_bfloat162(l0, l1);
        jb.j[k].lo[2 * off + 1] = __nv_bfloat162(l2, l3);
    }
}

__global__ void zero_states_kernel(float* hl, float* cl, float* hs, float* cs,
                                   bf16* hlh, bf16* hll, bf16* hsh, bf16* hsl)
{
    int i = blockIdx.x * blockDim.x + threadIdx.x;
    if (i < BB * LL) { hl[i] = 0.f; cl[i] = 0.f; hlh[i] = __float2bfloat16(0.f); hll[i] = __float2bfloat16(0.f); }
    if (i < BB * SS) { hs[i] = 0.f; cs[i] = 0.f; hsh[i] = __float2bfloat16(0.f); hsl[i] = __float2bfloat16(0.f); }
}

// fused per-step post-GEMM kernel: small LSTM act + hard gate + large act/merge.
// One block per batch row. Gl = sum of 4 split-K partials; Gs = sum of 2.
__global__ void __launch_bounds__(256)
step_post_kernel(const float* __restrict__ Gs2, const float* __restrict__ Gl4,
                 const float* __restrict__ sfeats, int t,
                 const float* __restrict__ h_old, const float* __restrict__ c_old,
                 const float* __restrict__ cs_old,
                 float* __restrict__ hs_new, float* __restrict__ cs_new,
                 bf16* __restrict__ hsh, bf16* __restrict__ hsl,
                 const float* __restrict__ W_g, const float* __restrict__ b_g,
                 float* __restrict__ r_out,
                 float* __restrict__ h_new, float* __restrict__ c_new,
                 bf16* __restrict__ hh, bf16* __restrict__ hl)
{
    const int b   = blockIdx.x;
    const int tid = threadIdx.x;
    __shared__ float sh_h[SS], sh_c[SS];
    __shared__ float s0[256], s1[256];
    __shared__ float r0sh;

    // ---- small LSTM activation (Gs = part0 + part1)
    const float* gs0 = Gs2 + (size_t)b * (4 * SS);
    const float* gs1 = Gs2 + (size_t)BB * 2048 + (size_t)b * (4 * SS);
    for (int n = tid; n < SS; n += 256) {
        float i_ = sigf(gs0[n] + gs1[n]);
        float f_ = sigf(gs0[SS + n] + gs1[SS + n]);
        float gg = tanhf(gs0[2 * SS + n] + gs1[2 * SS + n]);
        float o_ = sigf(gs0[3 * SS + n] + gs1[3 * SS + n]);
        float c2 = f_ * cs_old[(size_t)b * SS + n] + i_ * gg;
        float h2 = o_ * tanhf(c2);
        sh_h[n] = h2; sh_c[n] = c2;
        cs_new[(size_t)b * SS + n] = c2;
        hs_new[(size_t)b * SS + n] = h2;
        split1(h2, hsh, hsl, (size_t)b * SS + n);
    }

    // ---- hard gate on OLD large state: r = one_hot(argmax(p))
    const float* s = sfeats + ((size_t)b * TT + t) * SS;
    const float* h = h_old + (size_t)b * LL;
    const float* c = c_old + (size_t)b * LL;
    const float* w0 = W_g;
    const float* w1 = W_g + 2560;
    float p0 = 0.f, p1 = 0.f;
    for (int j = tid; j < SS; j += 256) { float v = s[j]; p0 += v * w0[j]; p1 += v * w1[j]; }
    for (int j = tid; j < LL; j += 256) { float v = h[j]; p0 += v * w0[SS + j]; p1 += v * w1[SS + j]; }
    for (int j = tid; j < LL; j += 256) { float v = c[j]; p0 += v * w0[SS + LL + j]; p1 += v * w1[SS + LL + j]; }
    s0[tid] = p0; s1[tid] = p1;
    __syncthreads();                       // also publishes sh_h/sh_c
    for (int st = 128; st > 0; st >>= 1) {
        if (tid < st) { s0[tid] += s0[tid + st]; s1[tid] += s1[tid + st]; }
        __syncthreads();
    }
    if (tid == 0) {
        float r0 = (s0[0] + b_g[0] >= s1[0] + b_g[1]) ? 1.f : 0.f;
        r0sh = r0;
        r_out[b * 2 + 0] = r0;
        r_out[b * 2 + 1] = 1.f - r0;
    }
    __syncthreads();
    const float r0 = r0sh, r1 = 1.f - r0sh;

    // ---- large LSTM activation + straight-through merge (Gl = 4 partials)
    const float* gA = Gl4 + (size_t)b * (4 * LL);
    const float* gB = Gl4 + (size_t)BB * 4096 + (size_t)b * (4 * LL);
    const float* gC = Gl4 + (size_t)2 * BB * 4096 + (size_t)b * (4 * LL);
    const float* gD = Gl4 + (size_t)3 * BB * 4096 + (size_t)b * (4 * LL);
    for (int n = tid; n < LL; n += 256) {
        size_t idx = (size_t)b * LL + n;
        float i_ = sigf(gA[n] + gB[n] + gC[n] + gD[n]);
        float f_ = sigf(gA[LL + n] + gB[LL + n] + gC[LL + n] + gD[LL + n]);
        float gg = tanhf(gA[2 * LL + n] + gB[2 * LL + n] + gC[2 * LL + n] + gD[2 * LL + n]);
        float o_ = sigf(gA[3 * LL + n] + gB[3 * LL + n] + gC[3 * LL + n] + gD[3 * LL + n]);
        float c_ln = f_ * c_old[idx] + i_ * gg;
        float h_ln = o_ * tanhf(c_ln);
        float ph = (n < SS) ? sh_h[n] : h_old[idx];
        float pc = (n < SS) ? sh_c[n] : c_old[idx];
        float h2 = r0 * h_ln + r1 * ph;
        c_new[idx] = r0 * c_ln + r1 * pc;
        h_new[idx] = h2;
        split1(h2, hh, hl, idx);
    }
}

// ---------------------------------------------------------------------------
// Launch
// ---------------------------------------------------------------------------
static inline float* fsym(const void* s) { void* p = nullptr; cudaGetSymbolAddress(&p, s); return (float*)p; }
static inline bf16*  bsym(const void* s) { void* p = nullptr; cudaGetSymbolAddress(&p, s); return (bf16*)p; }

extern "C" void kernel_launch(void* const* d_in, const int* in_sizes, int n_in,
                              void* d_out, int out_size)
{
    const float* x     = (const float*)d_in[0];
    const float* xs    = (const float*)d_in[1];
    const float* W_p   = (const float*)d_in[2];
    const float* b_p   = (const float*)d_in[3];
    const float* g_p   = (const float*)d_in[4];
    const float* be_p  = (const float*)d_in[5];
    const float* W_s   = (const float*)d_in[6];
    const float* b_s   = (const float*)d_in[7];
    const float* g_s   = (const float*)d_in[8];
    const float* be_s  = (const float*)d_in[9];
    const float* Wih_l = (const float*)d_in[10];
    const float* Whh_l = (const float*)d_in[11];
    const float* bih_l = (const float*)d_in[12];
    const float* bhh_l = (const float*)d_in[13];
    const float* Wih_s = (const float*)d_in[14];
    const float* Whh_s = (const float*)d_in[15];
    const float* bih_s = (const float*)d_in[16];
    const float* bhh_s = (const float*)d_in[17];
    const float* W_g   = (const float*)d_in[18];
    const float* b_g   = (const float*)d_in[19];
    const float* W_c   = (const float*)d_in[20];
    const float* b_c   = (const float*)d_in[21];

    float* out = (float*)d_out;
    float* out_logits = out;
    float* out_r      = out + BB * NCLS;

    bf16 *xh = bsym(g_x_hi), *xl = bsym(g_x_lo);
    bf16 *xsh = bsym(g_xs_hi), *xsl = bsym(g_xs_lo);
    bf16 *fh = bsym(g_f_hi), *fl = bsym(g_f_lo);
    bf16 *sfh = bsym(g_sf_hi), *sfl = bsym(g_sf_lo);
    bf16 *Wph = bsym(g_Wp_hi), *Wpl = bsym(g_Wp_lo);
    bf16 *Wsh = bsym(g_Ws_hi), *Wsl = bsym(g_Ws_lo);
    bf16 *Wlh = bsym(g_Wl_hi), *Wll = bsym(g_Wl_lo);
    bf16 *Whlh = bsym(g_Whl_hi), *Whll = bsym(g_Whl_lo);
    bf16 *Wish = bsym(g_Wis_hi), *Wisl = bsym(g_Wis_lo);
    bf16 *Whsh = bsym(g_Whs_hi), *Whsl = bsym(g_Whs_lo);
    bf16 *Wch = bsym(g_Wc_hi), *Wcl = bsym(g_Wc_lo);

    float* sfeats = fsym(g_sfeats);
    float* sgpre  = fsym(g_sgpre);
    float* lgpre  = fsym(g_lgpre);
    float* Gs2 = fsym(g_Gs2);
    float* Gl4 = fsym(g_Gl4);
    float* hl = fsym(g_hl);
    float* cl = fsym(g_cl);
    float* hs = fsym(g_hs);
    float* cs = fsym(g_cs);
    bf16* hlh = bsym(g_hl_hi); bf16* hll = bsym(g_hl_lo);
    bf16* hsh = bsym(g_hs_hi); bf16* hsl = bsym(g_hs_lo);

    cudaFuncSetAttribute(gemm3_kernel, cudaFuncAttributeMaxDynamicSharedMemorySize, GSMEM);
    cudaFuncSetAttribute(phase1a_kernel, cudaFuncAttributeMaxDynamicSharedMemorySize, GSMEM);
    cudaFuncSetAttribute(phase1b_kernel, cudaFuncAttributeMaxDynamicSharedMemorySize, GSMEM);
    cudaFuncSetAttribute(step_gemm_kernel, cudaFuncAttributeMaxDynamicSharedMemorySize, GSMEM);

    const int TPB = 256;

    // ---- fused split of all inputs & weights into bf16 pairs
    {
        SJobs jb;
        const float* srcs[9] = { x, xs, W_p, W_s, Wih_l, Whh_l, Wih_s, Whh_s, W_c };
        bf16* his[9] = { xh, xsh, Wph, Wsh, Wlh, Whlh, Wish, Whsh, Wch };
        bf16* los[9] = { xl, xsl, Wpl, Wsl, Wll, Whll, Wisl, Whsl, Wcl };
        long  ns [9] = { (long)MBT * 2048, (long)MBT * 1280, 2048L * 2048, 512L * 1280,
                         4096L * 2560, 4096L * 1024, 2048L * 512, 2048L * 512,
                         (long)NCLS * 1024 };
        unsigned cum = 0;
        for (int k = 0; k < 9; k++) {
            jb.j[k].src = (const float4*)srcs[k];
            jb.j[k].hi  = (__nv_bfloat162*)his[k];
            jb.j[k].lo  = (__nv_bfloat162*)los[k];
            jb.cum[k] = cum;
            cum += (unsigned)(ns[k] / 4);
        }
        jb.cum[9] = cum;
        int grid = (int)((cum / 2 + TPB - 1) / TPB);     // 2 float4 per thread
        split_all_kernel<<<grid, TPB>>>(jb, cum);
    }
    zero_states_kernel<<<(BB * LL + 255) / 256, TPB>>>(hl, cl, hs, cs, hlh, hll, hsh, hsl);

    // ---- Phase 1: time-parallel GEMMs (two merged launches)
    // A: feats = relu(BN(x @ W_p^T + b_p)) [long, first]
    //    sfeats = relu(BN(xs @ W_s^T + b_s)) [backfills tail]
    phase1a_kernel<<<2048 + 512, 512, GSMEM>>>(
        xh, xl, Wph, Wpl, b_p, g_p, be_p, fh, fl,
        xsh, xsl, Wsh, Wsl, b_s, g_s, be_s, sfeats, sfh, sfl);
    // B: lgpre = [feats, sfeats] @ Wih_l^T + bih_l + bhh_l [long, first]
    //    sgpre = sfeats @ Wih_s^T + bih_s + bhh_s [backfills tail]
    phase1b_kernel<<<4096 + 2048, 512, GSMEM>>>(
        fh, fl, sfh, sfl, Wlh, Wll, bih_l, bhh_l, lgpre,
        Wish, Wisl, bih_s, bhh_s, sgpre);

    // ---- Phase 2: recurrence (2 launches per step)
    for (int t = 0; t < TT; t++) {
        int cur = t & 1, nxt = 1 - cur;
        float* hl_c = hl + (size_t)cur * BB * LL;
        float* cl_c = cl + (size_t)cur * BB * LL;
        float* hl_n = hl + (size_t)nxt * BB * LL;
        float* cl_n = cl + (size_t)nxt * BB * LL;
        float* cs_c = cs + (size_t)cur * BB * SS;
        float* hs_n = hs + (size_t)nxt * BB * SS;
        float* cs_n = cs + (size_t)nxt * BB * SS;
        bf16* hlh_c = hlh + (size_t)cur * BB * LL;
        bf16* hll_c = hll + (size_t)cur * BB * LL;
        bf16* hlh_n = hlh + (size_t)nxt * BB * LL;
        bf16* hll_n = hll + (size_t)nxt * BB * LL;
        bf16* hsh_c = hsh + (size_t)cur * BB * SS;
        bf16* hsl_c = hsl + (size_t)cur * BB * SS;
        bf16* hsh_n = hsh + (size_t)nxt * BB * SS;
        bf16* hsl_n = hsl + (size_t)nxt * BB * SS;
        float* r_t = out_r + (size_t)t * BB * 2;

        step_gemm_kernel<<<320, 512, GSMEM>>>(
            hsh_c, hsl_c, Whsh, Whsl, sgpre + (size_t)t * 2048,
            hlh_c, hll_c, Whlh, Whll, lgpre + (size_t)t * 4096,
            Gs2, Gl4);
        step_post_kernel<<<BB, 256>>>(
            Gs2, Gl4, sfeats, t, hl_c, cl_c, cs_c,
            hs_n, cs_n, hsh_n, hsl_n,
            W_g, b_g, r_t, hl_n, cl_n, hlh_n, hll_n);
    }

    // ---- classifier on final h_l (buffer 0 after 64 steps)
    gemm3_kernel<<<dim3((NCLS + 127) / 128, BB / 128), 512, GSMEM>>>(
        hlh, hll, 1024, nullptr, nullptr, 0, 1024,
        Wch, Wcl, 1024, NCLS, 1024,
        b_c, nullptr, nullptr, 0, nullptr, nullptr,
        out_logits, NCLS, nullptr, nullptr, 0);
}

// round 12
// speedup vs baseline: 1.0552x; 1.0169x over previous
#include <cuda_runtime.h>
#include <cuda_bf16.h>
#include <math.h>
#include <stdint.h>

// ---------------------------------------------------------------------------
// Problem constants
// ---------------------------------------------------------------------------
#define BB 256
#define TT 64
#define LL 1024
#define SS 512
#define NCLS 239
#define MBT (BB * TT)          // 16384

typedef __nv_bfloat16 bf16;

// ---------------------------------------------------------------------------
// Scratch (device globals; no runtime allocation allowed)
// ---------------------------------------------------------------------------
__device__ bf16 g_x_hi  [MBT * 2048];
__device__ bf16 g_x_lo  [MBT * 2048];
__device__ bf16 g_xs_hi [MBT * 1280];
__device__ bf16 g_xs_lo [MBT * 1280];
__device__ bf16 g_f_hi  [MBT * 2048];
__device__ bf16 g_f_lo  [MBT * 2048];
__device__ bf16 g_sf_hi [MBT * 512];
__device__ bf16 g_sf_lo [MBT * 512];
__device__ bf16 g_Wp_hi [2048 * 2048];
__device__ bf16 g_Wp_lo [2048 * 2048];
__device__ bf16 g_Ws_hi [512 * 1280];
__device__ bf16 g_Ws_lo [512 * 1280];
__device__ bf16 g_Wl_hi [4096 * 2560];   // Wih_l full (K-concat GEMM)
__device__ bf16 g_Wl_lo [4096 * 2560];
__device__ bf16 g_Whl_hi[4096 * 1024];   // Whh_l
__device__ bf16 g_Whl_lo[4096 * 1024];
__device__ bf16 g_Wis_hi[2048 * 512];    // Wih_s
__device__ bf16 g_Wis_lo[2048 * 512];
__device__ bf16 g_Whs_hi[2048 * 512];    // Whh_s
__device__ bf16 g_Whs_lo[2048 * 512];
__device__ bf16 g_Wc_hi [NCLS * 1024];
__device__ bf16 g_Wc_lo [NCLS * 1024];
__device__ float g_sfeats[MBT * 512];
__device__ float g_sgpre [MBT * 2048];
__device__ float g_lgpre [MBT * 4096];
__device__ float g_Gs2[2][BB * 2048];    // Gs split-K partials
__device__ float g_Gl4[4][BB * 4096];    // Gl split-K partials
__device__ float g_hl[2][BB * LL];
__device__ float g_cl[2][BB * LL];
__device__ float g_hs[2][BB * SS];
__device__ float g_cs[2][BB * SS];
__device__ bf16 g_hl_hi[2][BB * LL];
__device__ bf16 g_hl_lo[2][BB * LL];
__device__ bf16 g_hs_hi[2][BB * SS];
__device__ bf16 g_hs_lo[2][BB * SS];

// ---------------------------------------------------------------------------
// PTX helpers (legacy tensor path only — harness targets compute_100)
// ---------------------------------------------------------------------------
__device__ __forceinline__ uint32_t smem_u32(const void* p) {
    return (uint32_t)__cvta_generic_to_shared(p);
}
__device__ __forceinline__ void cp16(uint32_t dst, const void* src, int srcsize) {
    asm volatile("cp.async.cg.shared.global [%0], [%1], 16, %2;\n"
                 :: "r"(dst), "l"(src), "r"(srcsize));
}
__device__ __forceinline__ void cp_commit() {
    asm volatile("cp.async.commit_group;\n");
}
template<int N>
__device__ __forceinline__ void cp_wait() {
    asm volatile("cp.async.wait_group %0;\n" :: "n"(N));
}
__device__ __forceinline__ void ldsm4(uint32_t* r, uint32_t addr) {
    asm volatile("ldmatrix.sync.aligned.m8n8.x4.shared.b16 {%0,%1,%2,%3}, [%4];\n"
                 : "=r"(r[0]), "=r"(r[1]), "=r"(r[2]), "=r"(r[3]) : "r"(addr));
}
__device__ __forceinline__ void mma_bf16(float* d, const uint32_t* a, uint32_t b0, uint32_t b1) {
    asm volatile("mma.sync.aligned.m16n8k16.row.col.f32.bf16.bf16.f32 "
                 "{%0,%1,%2,%3},{%4,%5,%6,%7},{%8,%9},{%0,%1,%2,%3};\n"
                 : "+f"(d[0]), "+f"(d[1]), "+f"(d[2]), "+f"(d[3])
                 : "r"(a[0]), "r"(a[1]), "r"(a[2]), "r"(a[3]), "r"(b0), "r"(b1));
}

// ---------------------------------------------------------------------------
// Split-bf16 triple-product GEMM core, register-reuse schedule, K64 chunks.
//   C[M,N] = epi( A@W^T ), A = A_hi+A_lo, W = W_hi+W_lo, computed as
//   Ahi*Whi + Ahi*Wlo + Alo*Whi accumulated in fp32.
//   One pipeline stage = one K64 chunk = 8 K32 tiles {Ah,Al,Bh,Bl} x {k0,k1};
//   NSTG=2 ring (163840 B). ONE barrier + ONE cp.wait per K64 chunk.
//   Fragment loads ordered (ah,bh) -> product1 MMAs -> (al,bl) -> products 2,3
//   to shorten the ldsm->MMA dependency head.
//   BM=BN=128, 512 threads (16 warps, 32x32 tiles), 1 CTA/SM.
//   A may be a K-concat: cols [0,K1) from A, [K1,K) from A2 (K1 % 64 == 0).
//   Requires K % 64 == 0.
// ---------------------------------------------------------------------------
#define LDSH 40                         // halves per smem row (padded)
#define TILEB (128 * LDSH * 2)          // one K32 tile = 10240 bytes
#define GSMEM (16 * TILEB)              // 2 stages * 8 tiles = 163840 bytes

__device__ __forceinline__ void gemm_core(
    char* smem, int bx, int by,
    const bf16* __restrict__ Ahi, const bf16* __restrict__ Alo, int lda,
    const bf16* __restrict__ A2hi, const bf16* __restrict__ A2lo, int lda2, int K1,
    const bf16* __restrict__ Bhi, const bf16* __restrict__ Blo, int ldb,
    int N, int K,
    const float* __restrict__ b1, const float* __restrict__ b2,
    const float* __restrict__ addsrc, int ldadd,
    const float* __restrict__ gamma, const float* __restrict__ beta,
    float* __restrict__ Cf, int ldc,
    bf16* __restrict__ Chi, bf16* __restrict__ Clo, int ldsp)
{
    constexpr int BM = 128;
    const int tid  = threadIdx.x;
    const int lane = tid & 31;
    const int wid  = tid >> 5;          // 0..15
    const int wm   = wid >> 2;          // 4 warp rows (32 each)
    const int wn   = wid & 3;           // 4 warp cols (32 each)
    const int bm   = by * BM;
    const int bn   = bx * BM;

    const int NC = K / 64;              // K64 chunks

    float acc[2][4][4];
#pragma unroll
    for (int i = 0; i < 2; i++)
#pragma unroll
        for (int j = 0; j < 4; j++)
#pragma unroll
            for (int r = 0; r < 4; r++) acc[i][j][r] = 0.f;

    // one cp16 per thread per K32 tile (512 threads cover a 128x32 tile)
    const int srow = tid >> 2;
    const int skc  = (tid & 3) * 8;
    auto stage = [&](int c) {
        int k0 = c * 64;
        const bf16 *Ah, *Al; int ald, ak;
        if (k0 < K1) { Ah = Ahi;  Al = Alo;  ald = lda;  ak = k0; }
        else         { Ah = A2hi; Al = A2lo; ald = lda2; ak = k0 - K1; }
        uint32_t base = smem_u32(smem) + (c & 1) * (8 * TILEB);
        uint32_t soff = (srow * LDSH + skc) * 2;
        int n = bn + srow;
        bool ok = (n < N);
#pragma unroll
        for (int h = 0; h < 2; h++) {
            size_t aoff = (size_t)(bm + srow) * ald + ak + h * 32 + skc;
            cp16(base + (0 + h) * TILEB + soff, Ah + aoff, 16);
            cp16(base + (2 + h) * TILEB + soff, Al + aoff, 16);
            size_t boff = (size_t)(ok ? n : 0) * ldb + k0 + h * 32 + skc;
            cp16(base + (4 + h) * TILEB + soff, Bhi + boff, ok ? 16 : 0);
            cp16(base + (6 + h) * TILEB + soff, Blo + boff, ok ? 16 : 0);
        }
    };

    stage(0); cp_commit();

    // fragment addresses (fixed per thread, K-offset varies)
    const int arow = wm * 32 + (lane & 15);
    const int akk0 = (lane >> 4) * 8;
    const int brow = wn * 32 + (lane & 7) + ((lane >> 4) << 3);
    const int bkk0 = ((lane >> 3) & 1) << 3;

    for (int c = 0; c < NC; c++) {
        cp_wait<0>();
        __syncthreads();   // chunk c landed; all warps done reading chunk c-1
        if (c + 1 < NC) { stage(c + 1); cp_commit(); }

        uint32_t base = smem_u32(smem) + (c & 1) * (8 * TILEB);
#pragma unroll
        for (int h = 0; h < 2; h++) {
            uint32_t bAh = base + (0 + h) * TILEB;
            uint32_t bAl = base + (2 + h) * TILEB;
            uint32_t bBh = base + (4 + h) * TILEB;
            uint32_t bBl = base + (6 + h) * TILEB;
#pragma unroll
            for (int ks = 0; ks < 32; ks += 16) {
                uint32_t ah[2][4], al[2][4], bh[4][2], bl[4][2];
                const int akk = ks + akk0;
                const int bkk = ks + bkk0;
                // --- hi fragments first: unlock product 1 ASAP
#pragma unroll
                for (int mi = 0; mi < 2; mi++)
                    ldsm4(ah[mi], bAh + ((arow + mi * 16) * LDSH + akk) * 2);
#pragma unroll
                for (int ng = 0; ng < 2; ng++) {
                    uint32_t t[4];
                    ldsm4(t, bBh + ((brow + ng * 16) * LDSH + bkk) * 2);
                    bh[2 * ng][0] = t[0]; bh[2 * ng][1] = t[1];
                    bh[2 * ng + 1][0] = t[2]; bh[2 * ng + 1][1] = t[3];
                }
#pragma unroll
                for (int mi = 0; mi < 2; mi++)
#pragma unroll
                    for (int nj = 0; nj < 4; nj++)
                        mma_bf16(acc[mi][nj], ah[mi], bh[nj][0], bh[nj][1]);
                // --- lo fragments overlap under product-1 MMAs
#pragma unroll
                for (int mi = 0; mi < 2; mi++)
                    ldsm4(al[mi], bAl + ((arow + mi * 16) * LDSH + akk) * 2);
#pragma unroll
                for (int ng = 0; ng < 2; ng++) {
                    uint32_t t[4];
                    ldsm4(t, bBl + ((brow + ng * 16) * LDSH + bkk) * 2);
                    bl[2 * ng][0] = t[0]; bl[2 * ng][1] = t[1];
                    bl[2 * ng + 1][0] = t[2]; bl[2 * ng + 1][1] = t[3];
                }
#pragma unroll
                for (int mi = 0; mi < 2; mi++)
#pragma unroll
                    for (int nj = 0; nj < 4; nj++)
                        mma_bf16(acc[mi][nj], ah[mi], bl[nj][0], bl[nj][1]);
#pragma unroll
                for (int mi = 0; mi < 2; mi++)
#pragma unroll
                    for (int nj = 0; nj < 4; nj++)
                        mma_bf16(acc[mi][nj], al[mi], bh[nj][0], bh[nj][1]);
            }
        }
    }

    // ---- epilogue (register-resident)
    const float inv_std = rsqrtf(1.0f + 1e-5f);
    const int g  = lane >> 2;
    const int tg = lane & 3;
#pragma unroll
    for (int mi = 0; mi < 2; mi++)
#pragma unroll
        for (int nj = 0; nj < 4; nj++)
#pragma unroll
            for (int r = 0; r < 4; r++) {
                int m = bm + wm * 32 + mi * 16 + g + ((r >> 1) << 3);
                int n = bn + wn * 32 + nj * 8 + tg * 2 + (r & 1);
                if (n >= N) continue;
                float v = acc[mi][nj][r];
                if (b1)     v += b1[n];
                if (b2)     v += b2[n];
                if (addsrc) v += addsrc[(size_t)m * ldadd + n];
                if (gamma)  v = fmaxf(0.f, v * (gamma[n] * inv_std) + beta[n]);
                if (Cf)     Cf[(size_t)m * ldc + n] = v;
                if (Chi) {
                    bf16 h = __float2bfloat16(v);
                    Chi[(size_t)m * ldsp + n] = h;
                    Clo[(size_t)m * ldsp + n] = __float2bfloat16(v - __bfloat162float(h));
                }
            }
}

// standalone GEMM launcher (512 threads, 1 CTA/SM) — used for the classifier
__global__ void __launch_bounds__(512, 1)
gemm3_kernel(const bf16* Ahi, const bf16* Alo, int lda,
             const bf16* A2hi, const bf16* A2lo, int lda2, int K1,
             const bf16* Bhi, const bf16* Blo, int ldb,
             int N, int K,
             const float* b1, const float* b2,
             const float* addsrc, int ldadd,
             const float* gamma, const float* beta,
             float* Cf, int ldc,
             bf16* Chi, bf16* Clo, int ldsp)
{
    extern __shared__ char smem[];
    gemm_core(smem, blockIdx.x, blockIdx.y,
              Ahi, Alo, lda, A2hi, A2lo, lda2, K1, Bhi, Blo, ldb, N, K,
              b1, b2, addsrc, ldadd, gamma, beta, Cf, ldc, Chi, Clo, ldsp);
}

// merged phase-1 launch A: feats (2048 CTAs, K=2048, long — first) then
// sfeats (512 CTAs, K=1280). Short jobs backfill the long jobs' tail wave.
__global__ void __launch_bounds__(512, 1)
phase1a_kernel(const bf16* xh, const bf16* xl, const bf16* Wph, const bf16* Wpl,
               const float* b_p, const float* g_p, const float* be_p,
               bf16* fh, bf16* fl,
               const bf16* xsh, const bf16* xsl, const bf16* Wsh, const bf16* Wsl,
               const float* b_s, const float* g_s, const float* be_s,
               float* sfeats, bf16* sfh, bf16* sfl)
{
    extern __shared__ char smem[];
    int bid = blockIdx.x;
    if (bid < 2048) {
        gemm_core(smem, bid & 15, bid >> 4,
                  xh, xl, 2048, nullptr, nullptr, 0, 2048,
                  Wph, Wpl, 2048, 2048, 2048,
                  b_p, nullptr, nullptr, 0, g_p, be_p,
                  nullptr, 0, fh, fl, 2048);
    } else {
        int t = bid - 2048;
        gemm_core(smem, t & 3, t >> 2,
                  xsh, xsl, 1280, nullptr, nullptr, 0, 1280,
                  Wsh, Wsl, 1280, 512, 1280,
                  b_s, nullptr, nullptr, 0, g_s, be_s,
                  sfeats, 512, sfh, sfl, 512);
    }
}

// merged phase-1 launch B: lgpre (4096 CTAs, K=2560, long — first) then
// sgpre (2048 CTAs, K=512).
__global__ void __launch_bounds__(512, 1)
phase1b_kernel(const bf16* fh, const bf16* fl, const bf16* sfh, const bf16* sfl,
               const bf16* Wlh, const bf16* Wll,
               const float* bih_l, const float* bhh_l, float* lgpre,
               const bf16* Wish, const bf16* Wisl,
               const float* bih_s, const float* bhh_s, float* sgpre)
{
    extern __shared__ char smem[];
    int bid = blockIdx.x;
    if (bid < 4096) {
        gemm_core(smem, bid & 31, bid >> 5,
                  fh, fl, 2048, sfh, sfl, 512, 2048,
                  Wlh, Wll, 2560, 4096, 2560,
                  bih_l, bhh_l, nullptr, 0, nullptr, nullptr,
                  lgpre, 4096, nullptr, nullptr, 0);
    } else {
        int t = bid - 4096;
        gemm_core(smem, t & 15, t >> 4,
                  sfh, sfl, 512, nullptr, nullptr, 0, 512,
                  Wish, Wisl, 512, 2048, 512,
                  bih_s, bhh_s, nullptr, 0, nullptr, nullptr,
                  sgpre, 2048, nullptr, nullptr, 0);
    }
}

// fused per-step GEMM + gate, fine split-K (328 CTAs):
//   bid 0..255:   Gl part p = bid>>6, tile t = bid&63; addsrc = lgpre_t on p==0.
//   bid 256..319: Gs part p, tile over N=2048; addsrc on p==0.
//   bid 320..327: hard gate on OLD state (depends only on pre-step state):
//                 32 batch rows/CTA, 16 threads/row, writes r_out directly.
__global__ void __launch_bounds__(512, 1)
step_gemm_kernel(const bf16* hsh, const bf16* hsl, const bf16* Whsh, const bf16* Whsl,
                 const float* sgpre_t,
                 const bf16* hlh, const bf16* hll, const bf16* Whlh, const bf16* Whll,
                 const float* lgpre_t,
                 float* Gs2, float* Gl4,
                 const float* sfeats, int t,
                 const float* hl_f32, const float* cl_f32,
                 const float* W_g, const float* b_g, float* r_out)
{
    extern __shared__ char smem[];
    int bid = blockIdx.x;
    if (bid < 256) {
        int p  = bid >> 6;
        int tt = bid & 63;
        int bx = tt >> 1, by = tt & 1;
        gemm_core(smem, bx, by,
                  hlh + p * 256, hll + p * 256, 1024, nullptr, nullptr, 0, 256,
                  Whlh + p * 256, Whll + p * 256, 1024, 4096, 256,
                  nullptr, nullptr, (p == 0) ? lgpre_t : nullptr, TT * 4096,
                  nullptr, nullptr,
                  Gl4 + (size_t)p * BB * 4096, 4096, nullptr, nullptr, 0);
    } else if (bid < 320) {
        int q  = bid - 256;
        int p  = q >> 5;
        int tt = q & 31;
        int bx = tt >> 1, by = tt & 1;
        gemm_core(smem, bx, by,
                  hsh + p * 256, hsl + p * 256, 512, nullptr, nullptr, 0, 256,
                  Whsh + p * 256, Whsl + p * 256, 512, 2048, 256,
                  nullptr, nullptr, (p == 0) ? sgpre_t : nullptr, TT * 2048,
                  nullptr, nullptr,
                  Gs2 + (size_t)p * BB * 2048, 2048, nullptr, nullptr, 0);
    } else {
        // gate: r = one_hot(argmax([s_t, h_l, c_l] @ W_g^T + b_g))
        int b   = (bid - 320) * 32 + (threadIdx.x >> 4);
        int sub = threadIdx.x & 15;
        const float* s = sfeats + ((size_t)b * TT + t) * SS;
        const float* h = hl_f32 + (size_t)b * LL;
        const float* c = cl_f32 + (size_t)b * LL;
        const float* w0 = W_g;
        const float* w1 = W_g + 2560;
        float p0 = 0.f, p1 = 0.f;
        for (int j = sub; j < SS; j += 16) { float v = s[j]; p0 += v * w0[j]; p1 += v * w1[j]; }
        for (int j = sub; j < LL; j += 16) { float v = h[j]; p0 += v * w0[SS + j]; p1 += v * w1[SS + j]; }
        for (int j = sub; j < LL; j += 16) { float v = c[j]; p0 += v * w0[SS + LL + j]; p1 += v * w1[SS + LL + j]; }
#pragma unroll
        for (int o = 8; o > 0; o >>= 1) {
            p0 += __shfl_down_sync(0xFFFFFFFFu, p0, o, 16);
            p1 += __shfl_down_sync(0xFFFFFFFFu, p1, o, 16);
        }
        if (sub == 0) {
            float r0 = (p0 + b_g[0] >= p1 + b_g[1]) ? 1.f : 0.f;
            r_out[b * 2 + 0] = r0;
            r_out[b * 2 + 1] = 1.f - r0;
        }
    }
}

// ---------------------------------------------------------------------------
// Elementwise kernels
// ---------------------------------------------------------------------------
__device__ __forceinline__ float sigf(float x) { return 1.f / (1.f + expf(-x)); }
__device__ __forceinline__ void split1(float v, bf16* hi, bf16* lo, size_t i) {
    bf16 h = __float2bfloat16(v);
    hi[i] = h;
    lo[i] = __float2bfloat16(v - __bfloat162float(h));
}

// one fused split kernel over all 9 tensors (float4-vectorized, grid-stride)
struct SJob { const float4* src; __nv_bfloat162* hi; __nv_bfloat162* lo; };
struct SJobs { SJob j[9]; unsigned cum[10]; };

__global__ void __launch_bounds__(256)
split_all_kernel(SJobs jb, unsigned total4)
{
    const unsigned stride = gridDim.x * blockDim.x;
    for (unsigned i = blockIdx.x * blockDim.x + threadIdx.x; i < total4; i += stride) {
        int k = 0;
#pragma unroll
        for (int q = 0; q < 8; q++) if (i >= jb.cum[q + 1]) k = q + 1;
        unsigned off = i - jb.cum[k];
        float4 v = jb.j[k].src[off];
        bf16 h0 = __float2bfloat16(v.x), h1 = __float2bfloat16(v.y);
        bf16 h2 = __float2bfloat16(v.z), h3 = __float2bfloat16(v.w);
        bf16 l0 = __float2bfloat16(v.x - __bfloat162float(h0));
        bf16 l1 = __float2bfloat16(v.y - __bfloat162float(h1));
        bf16 l2 = __float2bfloat16(v.z - __bfloat162float(h2));
        bf16 l3 = __float2bfloat16(v.w - __bfloat162float(h3));
        jb.j[k].hi[2 * off]     = __nv_bfloat162(h0, h1);
        jb.j[k].hi[2 * off + 1] = __nv_bfloat162(h2, h3);
        jb.j[k].lo[2 * off]     = __nv_bfloat162(l0, l1);
        jb.j[k].lo[2 * off + 1] = __nv_bfloat162(l2, l3);
    }
}

__global__ void zero_states_kernel(float* hl, float* cl, float* hs, float* cs,
                                   bf16* hlh, bf16* hll, bf16* hsh, bf16* hsl)
{
    int i = blockIdx.x * blockDim.x + threadIdx.x;
    if (i < BB * LL) { hl[i] = 0.f; cl[i] = 0.f; hlh[i] = __float2bfloat16(0.f); hll[i] = __float2bfloat16(0.f); }
    if (i < BB * SS) { hs[i] = 0.f; cs[i] = 0.f; hsh[i] = __float2bfloat16(0.f); hsl[i] = __float2bfloat16(0.f); }
}

// fused per-step post-GEMM kernel: small LSTM act + large act/merge.
// Gate already computed by step_gemm (read from r_in). One block per batch row.
__global__ void __launch_bounds__(256)
step_post_kernel(const float* __restrict__ Gs2, const float* __restrict__ Gl4,
                 const float* __restrict__ r_in,
                 const float* __restrict__ h_old, const float* __restrict__ c_old,
                 const float* __restrict__ cs_old,
                 float* __restrict__ hs_new, float* __restrict__ cs_new,
                 bf16* __restrict__ hsh, bf16* __restrict__ hsl,
                 float* __restrict__ h_new, float* __restrict__ c_new,
                 bf16* __restrict__ hh, bf16* __restrict__ hl)
{
    const int b   = blockIdx.x;
    const int tid = threadIdx.x;
    __shared__ float sh_h[SS], sh_c[SS];

    // ---- small LSTM activation (Gs = part0 + part1)
    const float* gs0 = Gs2 + (size_t)b * (4 * SS);
    const float* gs1 = Gs2 + (size_t)BB * 2048 + (size_t)b * (4 * SS);
    for (int n = tid; n < SS; n += 256) {
        float i_ = sigf(gs0[n] + gs1[n]);
        float f_ = sigf(gs0[SS + n] + gs1[SS + n]);
        float gg = tanhf(gs0[2 * SS + n] + gs1[2 * SS + n]);
        float o_ = sigf(gs0[3 * SS + n] + gs1[3 * SS + n]);
        float c2 = f_ * cs_old[(size_t)b * SS + n] + i_ * gg;
        float h2 = o_ * tanhf(c2);
        sh_h[n] = h2; sh_c[n] = c2;
        cs_new[(size_t)b * SS + n] = c2;
        hs_new[(size_t)b * SS + n] = h2;
        split1(h2, hsh, hsl, (size_t)b * SS + n);
    }
    __syncthreads();                       // publish sh_h/sh_c

    const float r0 = r_in[b * 2], r1 = 1.f - r0;

    // ---- large LSTM activation + straight-through merge (Gl = 4 partials)
    const float* gA = Gl4 + (size_t)b * (4 * LL);
    const float* gB = Gl4 + (size_t)BB * 4096 + (size_t)b * (4 * LL);
    const float* gC = Gl4 + (size_t)2 * BB * 4096 + (size_t)b * (4 * LL);
    const float* gD = Gl4 + (size_t)3 * BB * 4096 + (size_t)b * (4 * LL);
    for (int n = tid; n < LL; n += 256) {
        size_t idx = (size_t)b * LL + n;
        float i_ = sigf(gA[n] + gB[n] + gC[n] + gD[n]);
        float f_ = sigf(gA[LL + n] + gB[LL + n] + gC[LL + n] + gD[LL + n]);
        float gg = tanhf(gA[2 * LL + n] + gB[2 * LL + n] + gC[2 * LL + n] + gD[2 * LL + n]);
        float o_ = sigf(gA[3 * LL + n] + gB[3 * LL + n] + gC[3 * LL + n] + gD[3 * LL + n]);
        float c_ln = f_ * c_old[idx] + i_ * gg;
        float h_ln = o_ * tanhf(c_ln);
        float ph = (n < SS) ? sh_h[n] : h_old[idx];
        float pc = (n < SS) ? sh_c[n] : c_old[idx];
        float h2 = r0 * h_ln + r1 * ph;
        c_new[idx] = r0 * c_ln + r1 * pc;
        h_new[idx] = h2;
        split1(h2, hh, hl, idx);
    }
}

// ---------------------------------------------------------------------------
// Launch
// ---------------------------------------------------------------------------
static inline float* fsym(const void* s) { void* p = nullptr; cudaGetSymbolAddress(&p, s); return (float*)p; }
static inline bf16*  bsym(const void* s) { void* p = nullptr; cudaGetSymbolAddress(&p, s); return (bf16*)p; }

extern "C" void kernel_launch(void* const* d_in, const int* in_sizes, int n_in,
                              void* d_out, int out_size)
{
    const float* x     = (const float*)d_in[0];
    const float* xs    = (const float*)d_in[1];
    const float* W_p   = (const float*)d_in[2];
    const float* b_p   = (const float*)d_in[3];
    const float* g_p   = (const float*)d_in[4];
    const float* be_p  = (const float*)d_in[5];
    const float* W_s   = (const float*)d_in[6];
    const float* b_s   = (const float*)d_in[7];
    const float* g_s   = (const float*)d_in[8];
    const float* be_s  = (const float*)d_in[9];
    const float* Wih_l = (const float*)d_in[10];
    const float* Whh_l = (const float*)d_in[11];
    const float* bih_l = (const float*)d_in[12];
    const float* bhh_l = (const float*)d_in[13];
    const float* Wih_s = (const float*)d_in[14];
    const float* Whh_s = (const float*)d_in[15];
    const float* bih_s = (const float*)d_in[16];
    const float* bhh_s = (const float*)d_in[17];
    const float* W_g   = (const float*)d_in[18];
    const float* b_g   = (const float*)d_in[19];
    const float* W_c   = (const float*)d_in[20];
    const float* b_c   = (const float*)d_in[21];

    float* out = (float*)d_out;
    float* out_logits = out;
    float* out_r      = out + BB * NCLS;

    bf16 *xh = bsym(g_x_hi), *xl = bsym(g_x_lo);
    bf16 *xsh = bsym(g_xs_hi), *xsl = bsym(g_xs_lo);
    bf16 *fh = bsym(g_f_hi), *fl = bsym(g_f_lo);
    bf16 *sfh = bsym(g_sf_hi), *sfl = bsym(g_sf_lo);
    bf16 *Wph = bsym(g_Wp_hi), *Wpl = bsym(g_Wp_lo);
    bf16 *Wsh = bsym(g_Ws_hi), *Wsl = bsym(g_Ws_lo);
    bf16 *Wlh = bsym(g_Wl_hi), *Wll = bsym(g_Wl_lo);
    bf16 *Whlh = bsym(g_Whl_hi), *Whll = bsym(g_Whl_lo);
    bf16 *Wish = bsym(g_Wis_hi), *Wisl = bsym(g_Wis_lo);
    bf16 *Whsh = bsym(g_Whs_hi), *Whsl = bsym(g_Whs_lo);
    bf16 *Wch = bsym(g_Wc_hi), *Wcl = bsym(g_Wc_lo);

    float* sfeats = fsym(g_sfeats);
    float* sgpre  = fsym(g_sgpre);
    float* lgpre  = fsym(g_lgpre);
    float* Gs2 = fsym(g_Gs2);
    float* Gl4 = fsym(g_Gl4);
    float* hl = fsym(g_hl);
    float* cl = fsym(g_cl);
    float* hs = fsym(g_hs);
    float* cs = fsym(g_cs);
    bf16* hlh = bsym(g_hl_hi); bf16* hll = bsym(g_hl_lo);
    bf16* hsh = bsym(g_hs_hi); bf16* hsl = bsym(g_hs_lo);

    cudaFuncSetAttribute(gemm3_kernel, cudaFuncAttributeMaxDynamicSharedMemorySize, GSMEM);
    cudaFuncSetAttribute(phase1a_kernel, cudaFuncAttributeMaxDynamicSharedMemorySize, GSMEM);
    cudaFuncSetAttribute(phase1b_kernel, cudaFuncAttributeMaxDynamicSharedMemorySize, GSMEM);
    cudaFuncSetAttribute(step_gemm_kernel, cudaFuncAttributeMaxDynamicSharedMemorySize, GSMEM);

    const int TPB = 256;

    // ---- fused split of all inputs & weights into bf16 pairs
    {
        SJobs jb;
        const float* srcs[9] = { x, xs, W_p, W_s, Wih_l, Whh_l, Wih_s, Whh_s, W_c };
        bf16* his[9] = { xh, xsh, Wph, Wsh, Wlh, Whlh, Wish, Whsh, Wch };
        bf16* los[9] = { xl, xsl, Wpl, Wsl, Wll, Whll, Wisl, Whsl, Wcl };
        long  ns [9] = { (long)MBT * 2048, (long)MBT * 1280, 2048L * 2048, 512L * 1280,
                         4096L * 2560, 4096L * 1024, 2048L * 512, 2048L * 512,
                         (long)NCLS * 1024 };
        unsigned cum = 0;
        for (int k = 0; k < 9; k++) {
            jb.j[k].src = (const float4*)srcs[k];
            jb.j[k].hi  = (__nv_bfloat162*)his[k];
            jb.j[k].lo  = (__nv_bfloat162*)los[k];
            jb.cum[k] = cum;
            cum += (unsigned)(ns[k] / 4);
        }
        jb.cum[9] = cum;
        int grid = (int)((cum / 2 + TPB - 1) / TPB);     // 2 float4 per thread
        split_all_kernel<<<grid, TPB>>>(jb, cum);
    }
    zero_states_kernel<<<(BB * LL + 255) / 256, TPB>>>(hl, cl, hs, cs, hlh, hll, hsh, hsl);

    // ---- Phase 1: time-parallel GEMMs (two merged launches)
    phase1a_kernel<<<2048 + 512, 512, GSMEM>>>(
        xh, xl, Wph, Wpl, b_p, g_p, be_p, fh, fl,
        xsh, xsl, Wsh, Wsl, b_s, g_s, be_s, sfeats, sfh, sfl);
    phase1b_kernel<<<4096 + 2048, 512, GSMEM>>>(
        fh, fl, sfh, sfl, Wlh, Wll, bih_l, bhh_l, lgpre,
        Wish, Wisl, bih_s, bhh_s, sgpre);

    // ---- Phase 2: recurrence (2 launches per step; gate fused into GEMM wave)
    for (int t = 0; t < TT; t++) {
        int cur = t & 1, nxt = 1 - cur;
        float* hl_c = hl + (size_t)cur * BB * LL;
        float* cl_c = cl + (size_t)cur * BB * LL;
        float* hl_n = hl + (size_t)nxt * BB * LL;
        float* cl_n = cl + (size_t)nxt * BB * LL;
        float* cs_c = cs + (size_t)cur * BB * SS;
        float* hs_n = hs + (size_t)nxt * BB * SS;
        float* cs_n = cs + (size_t)nxt * BB * SS;
        bf16* hlh_c = hlh + (size_t)cur * BB * LL;
        bf16* hll_c = hll + (size_t)cur * BB * LL;
        bf16* hlh_n = hlh + (size_t)nxt * BB * LL;
        bf16* hll_n = hll + (size_t)nxt * BB * LL;
        bf16* hsh_c = hsh + (size_t)cur * BB * SS;
        bf16* hsl_c = hsl + (size_t)cur * BB * SS;
        bf16* hsh_n = hsh + (size_t)nxt * BB * SS;
        bf16* hsl_n = hsl + (size_t)nxt * BB * SS;
        float* r_t = out_r + (size_t)t * BB * 2;

        step_gemm_kernel<<<328, 512, GSMEM>>>(
            hsh_c, hsl_c, Whsh, Whsl, sgpre + (size_t)t * 2048,
            hlh_c, hll_c, Whlh, Whll, lgpre + (size_t)t * 4096,
            Gs2, Gl4,
            sfeats, t, hl_c, cl_c, W_g, b_g, r_t);
        step_post_kernel<<<BB, 256>>>(
            Gs2, Gl4, r_t, hl_c, cl_c, cs_c,
            hs_n, cs_n, hsh_n, hsl_n,
            hl_n, cl_n, hlh_n, hll_n);
    }

    // ---- classifier on final h_l (buffer 0 after 64 steps)
    gemm3_kernel<<<dim3((NCLS + 127) / 128, BB / 128), 512, GSMEM>>>(
        hlh, hll, 1024, nullptr, nullptr, 0, 1024,
        Wch, Wcl, 1024, NCLS, 1024,
        b_c, nullptr, nullptr, 0, nullptr, nullptr,
        out_logits, NCLS, nullptr, nullptr, 0);
}

// round 13
// speedup vs baseline: 1.0868x; 1.0299x over previous
#include <cuda_runtime.h>
#include <cuda_bf16.h>
#include <math.h>
#include <stdint.h>

// ---------------------------------------------------------------------------
// Problem constants
// ---------------------------------------------------------------------------
#define BB 256
#define TT 64
#define LL 1024
#define SS 512
#define NCLS 239
#define MBT (BB * TT)          // 16384

typedef __nv_bfloat16 bf16;

// ---------------------------------------------------------------------------
// Scratch (device globals; no runtime allocation allowed)
// ---------------------------------------------------------------------------
__device__ bf16 g_x_hi  [MBT * 2048];
__device__ bf16 g_x_lo  [MBT * 2048];
__device__ bf16 g_xs_hi [MBT * 1280];
__device__ bf16 g_xs_lo [MBT * 1280];
__device__ bf16 g_f_hi  [MBT * 2048];
__device__ bf16 g_f_lo  [MBT * 2048];
__device__ bf16 g_sf_hi [MBT * 512];
__device__ bf16 g_sf_lo [MBT * 512];
__device__ bf16 g_Wp_hi [2048 * 2048];
__device__ bf16 g_Wp_lo [2048 * 2048];
__device__ bf16 g_Ws_hi [512 * 1280];
__device__ bf16 g_Ws_lo [512 * 1280];
__device__ bf16 g_Wl_hi [4096 * 2560];   // Wih_l full (K-concat GEMM)
__device__ bf16 g_Wl_lo [4096 * 2560];
__device__ bf16 g_Whl_hi[4096 * 1024];   // Whh_l
__device__ bf16 g_Whl_lo[4096 * 1024];
__device__ bf16 g_Wis_hi[2048 * 512];    // Wih_s
__device__ bf16 g_Wis_lo[2048 * 512];
__device__ bf16 g_Whs_hi[2048 * 512];    // Whh_s
__device__ bf16 g_Whs_lo[2048 * 512];
__device__ bf16 g_Wc_hi [NCLS * 1024];
__device__ bf16 g_Wc_lo [NCLS * 1024];
__device__ float g_sfeats[MBT * 512];
__device__ float g_sgpre [MBT * 2048];
__device__ float g_lgpre [MBT * 4096];
__device__ float g_Gs2[2][BB * 2048];    // Gs split-K partials
__device__ float g_Gl3[3][BB * 4096];    // Gl split-K partials (384,384,256)
__device__ float g_hl[2][BB * LL];
__device__ float g_cl[2][BB * LL];
__device__ float g_hs[2][BB * SS];
__device__ float g_cs[2][BB * SS];
__device__ bf16 g_hl_hi[2][BB * LL];
__device__ bf16 g_hl_lo[2][BB * LL];
__device__ bf16 g_hs_hi[2][BB * SS];
__device__ bf16 g_hs_lo[2][BB * SS];

// ---------------------------------------------------------------------------
// PTX helpers (legacy tensor path only — harness targets compute_100)
// ---------------------------------------------------------------------------
__device__ __forceinline__ uint32_t smem_u32(const void* p) {
    return (uint32_t)__cvta_generic_to_shared(p);
}
__device__ __forceinline__ void cp16(uint32_t dst, const void* src, int srcsize) {
    asm volatile("cp.async.cg.shared.global [%0], [%1], 16, %2;\n"
                 :: "r"(dst), "l"(src), "r"(srcsize));
}
__device__ __forceinline__ void cp_commit() {
    asm volatile("cp.async.commit_group;\n");
}
template<int N>
__device__ __forceinline__ void cp_wait() {
    asm volatile("cp.async.wait_group %0;\n" :: "n"(N));
}
__device__ __forceinline__ void ldsm4(uint32_t* r, uint32_t addr) {
    asm volatile("ldmatrix.sync.aligned.m8n8.x4.shared.b16 {%0,%1,%2,%3}, [%4];\n"
                 : "=r"(r[0]), "=r"(r[1]), "=r"(r[2]), "=r"(r[3]) : "r"(addr));
}
__device__ __forceinline__ void mma_bf16(float* d, const uint32_t* a, uint32_t b0, uint32_t b1) {
    asm volatile("mma.sync.aligned.m16n8k16.row.col.f32.bf16.bf16.f32 "
                 "{%0,%1,%2,%3},{%4,%5,%6,%7},{%8,%9},{%0,%1,%2,%3};\n"
                 : "+f"(d[0]), "+f"(d[1]), "+f"(d[2]), "+f"(d[3])
                 : "r"(a[0]), "r"(a[1]), "r"(a[2]), "r"(a[3]), "r"(b0), "r"(b1));
}

// ---------------------------------------------------------------------------
// Split-bf16 triple-product GEMM core, register-reuse schedule, K64 chunks.
//   C[M,N] = epi( A@W^T ), A = A_hi+A_lo, W = W_hi+W_lo, computed as
//   Ahi*Whi + Ahi*Wlo + Alo*Whi accumulated in fp32.
//   One pipeline stage = one K64 chunk = 8 K32 tiles {Ah,Al,Bh,Bl} x {k0,k1};
//   NSTG=2 ring (163840 B). ONE barrier + ONE cp.wait per K64 chunk.
//   Fragment loads ordered (ah,bh) -> product1 MMAs -> (al,bl) -> products 2,3.
//   BM=BN=128, 512 threads (16 warps, 32x32 tiles), 1 CTA/SM.
//   A may be a K-concat: cols [0,K1) from A, [K1,K) from A2 (K1 % 64 == 0).
//   Requires K % 64 == 0.
// ---------------------------------------------------------------------------
#define LDSH 40                         // halves per smem row (padded)
#define TILEB (128 * LDSH * 2)          // one K32 tile = 10240 bytes
#define GSMEM (16 * TILEB)              // 2 stages * 8 tiles = 163840 bytes

__device__ __forceinline__ void gemm_core(
    char* smem, int bx, int by,
    const bf16* __restrict__ Ahi, const bf16* __restrict__ Alo, int lda,
    const bf16* __restrict__ A2hi, const bf16* __restrict__ A2lo, int lda2, int K1,
    const bf16* __restrict__ Bhi, const bf16* __restrict__ Blo, int ldb,
    int N, int K,
    const float* __restrict__ b1, const float* __restrict__ b2,
    const float* __restrict__ addsrc, int ldadd,
    const float* __restrict__ gamma, const float* __restrict__ beta,
    float* __restrict__ Cf, int ldc,
    bf16* __restrict__ Chi, bf16* __restrict__ Clo, int ldsp)
{
    constexpr int BM = 128;
    const int tid  = threadIdx.x;
    const int lane = tid & 31;
    const int wid  = tid >> 5;          // 0..15
    const int wm   = wid >> 2;          // 4 warp rows (32 each)
    const int wn   = wid & 3;           // 4 warp cols (32 each)
    const int bm   = by * BM;
    const int bn   = bx * BM;

    const int NC = K / 64;              // K64 chunks

    float acc[2][4][4];
#pragma unroll
    for (int i = 0; i < 2; i++)
#pragma unroll
        for (int j = 0; j < 4; j++)
#pragma unroll
            for (int r = 0; r < 4; r++) acc[i][j][r] = 0.f;

    // one cp16 per thread per K32 tile (512 threads cover a 128x32 tile)
    const int srow = tid >> 2;
    const int skc  = (tid & 3) * 8;
    auto stage = [&](int c) {
        int k0 = c * 64;
        const bf16 *Ah, *Al; int ald, ak;
        if (k0 < K1) { Ah = Ahi;  Al = Alo;  ald = lda;  ak = k0; }
        else         { Ah = A2hi; Al = A2lo; ald = lda2; ak = k0 - K1; }
        uint32_t base = smem_u32(smem) + (c & 1) * (8 * TILEB);
        uint32_t soff = (srow * LDSH + skc) * 2;
        int n = bn + srow;
        bool ok = (n < N);
#pragma unroll
        for (int h = 0; h < 2; h++) {
            size_t aoff = (size_t)(bm + srow) * ald + ak + h * 32 + skc;
            cp16(base + (0 + h) * TILEB + soff, Ah + aoff, 16);
            cp16(base + (2 + h) * TILEB + soff, Al + aoff, 16);
            size_t boff = (size_t)(ok ? n : 0) * ldb + k0 + h * 32 + skc;
            cp16(base + (4 + h) * TILEB + soff, Bhi + boff, ok ? 16 : 0);
            cp16(base + (6 + h) * TILEB + soff, Blo + boff, ok ? 16 : 0);
        }
    };

    stage(0); cp_commit();

    // fragment addresses (fixed per thread, K-offset varies)
    const int arow = wm * 32 + (lane & 15);
    const int akk0 = (lane >> 4) * 8;
    const int brow = wn * 32 + (lane & 7) + ((lane >> 4) << 3);
    const int bkk0 = ((lane >> 3) & 1) << 3;

    for (int c = 0; c < NC; c++) {
        cp_wait<0>();
        __syncthreads();   // chunk c landed; all warps done reading chunk c-1
        if (c + 1 < NC) { stage(c + 1); cp_commit(); }

        uint32_t base = smem_u32(smem) + (c & 1) * (8 * TILEB);
#pragma unroll
        for (int h = 0; h < 2; h++) {
            uint32_t bAh = base + (0 + h) * TILEB;
            uint32_t bAl = base + (2 + h) * TILEB;
            uint32_t bBh = base + (4 + h) * TILEB;
            uint32_t bBl = base + (6 + h) * TILEB;
#pragma unroll
            for (int ks = 0; ks < 32; ks += 16) {
                uint32_t ah[2][4], al[2][4], bh[4][2], bl[4][2];
                const int akk = ks + akk0;
                const int bkk = ks + bkk0;
                // --- hi fragments first: unlock product 1 ASAP
#pragma unroll
                for (int mi = 0; mi < 2; mi++)
                    ldsm4(ah[mi], bAh + ((arow + mi * 16) * LDSH + akk) * 2);
#pragma unroll
                for (int ng = 0; ng < 2; ng++) {
                    uint32_t t[4];
                    ldsm4(t, bBh + ((brow + ng * 16) * LDSH + bkk) * 2);
                    bh[2 * ng][0] = t[0]; bh[2 * ng][1] = t[1];
                    bh[2 * ng + 1][0] = t[2]; bh[2 * ng + 1][1] = t[3];
                }
#pragma unroll
                for (int mi = 0; mi < 2; mi++)
#pragma unroll
                    for (int nj = 0; nj < 4; nj++)
                        mma_bf16(acc[mi][nj], ah[mi], bh[nj][0], bh[nj][1]);
                // --- lo fragments overlap under product-1 MMAs
#pragma unroll
                for (int mi = 0; mi < 2; mi++)
                    ldsm4(al[mi], bAl + ((arow + mi * 16) * LDSH + akk) * 2);
#pragma unroll
                for (int ng = 0; ng < 2; ng++) {
                    uint32_t t[4];
                    ldsm4(t, bBl + ((brow + ng * 16) * LDSH + bkk) * 2);
                    bl[2 * ng][0] = t[0]; bl[2 * ng][1] = t[1];
                    bl[2 * ng + 1][0] = t[2]; bl[2 * ng + 1][1] = t[3];
                }
#pragma unroll
                for (int mi = 0; mi < 2; mi++)
#pragma unroll
                    for (int nj = 0; nj < 4; nj++)
                        mma_bf16(acc[mi][nj], ah[mi], bl[nj][0], bl[nj][1]);
#pragma unroll
                for (int mi = 0; mi < 2; mi++)
#pragma unroll
                    for (int nj = 0; nj < 4; nj++)
                        mma_bf16(acc[mi][nj], al[mi], bh[nj][0], bh[nj][1]);
            }
        }
    }

    // ---- epilogue (register-resident)
    const float inv_std = rsqrtf(1.0f + 1e-5f);
    const int g  = lane >> 2;
    const int tg = lane & 3;
#pragma unroll
    for (int mi = 0; mi < 2; mi++)
#pragma unroll
        for (int nj = 0; nj < 4; nj++)
#pragma unroll
            for (int r = 0; r < 4; r++) {
                int m = bm + wm * 32 + mi * 16 + g + ((r >> 1) << 3);
                int n = bn + wn * 32 + nj * 8 + tg * 2 + (r & 1);
                if (n >= N) continue;
                float v = acc[mi][nj][r];
                if (b1)     v += b1[n];
                if (b2)     v += b2[n];
                if (addsrc) v += addsrc[(size_t)m * ldadd + n];
                if (gamma)  v = fmaxf(0.f, v * (gamma[n] * inv_std) + beta[n]);
                if (Cf)     Cf[(size_t)m * ldc + n] = v;
                if (Chi) {
                    bf16 h = __float2bfloat16(v);
                    Chi[(size_t)m * ldsp + n] = h;
                    Clo[(size_t)m * ldsp + n] = __float2bfloat16(v - __bfloat162float(h));
                }
            }
}

// standalone GEMM launcher (512 threads, 1 CTA/SM) — used for the classifier
__global__ void __launch_bounds__(512, 1)
gemm3_kernel(const bf16* Ahi, const bf16* Alo, int lda,
             const bf16* A2hi, const bf16* A2lo, int lda2, int K1,
             const bf16* Bhi, const bf16* Blo, int ldb,
             int N, int K,
             const float* b1, const float* b2,
             const float* addsrc, int ldadd,
             const float* gamma, const float* beta,
             float* Cf, int ldc,
             bf16* Chi, bf16* Clo, int ldsp)
{
    extern __shared__ char smem[];
    gemm_core(smem, blockIdx.x, blockIdx.y,
              Ahi, Alo, lda, A2hi, A2lo, lda2, K1, Bhi, Blo, ldb, N, K,
              b1, b2, addsrc, ldadd, gamma, beta, Cf, ldc, Chi, Clo, ldsp);
}

// merged phase-1 launch A: feats (2048 CTAs, K=2048, long — first) then
// sfeats (512 CTAs, K=1280). Short jobs backfill the long jobs' tail wave.
__global__ void __launch_bounds__(512, 1)
phase1a_kernel(const bf16* xh, const bf16* xl, const bf16* Wph, const bf16* Wpl,
               const float* b_p, const float* g_p, const float* be_p,
               bf16* fh, bf16* fl,
               const bf16* xsh, const bf16* xsl, const bf16* Wsh, const bf16* Wsl,
               const float* b_s, const float* g_s, const float* be_s,
               float* sfeats, bf16* sfh, bf16* sfl)
{
    extern __shared__ char smem[];
    int bid = blockIdx.x;
    if (bid < 2048) {
        gemm_core(smem, bid & 15, bid >> 4,
                  xh, xl, 2048, nullptr, nullptr, 0, 2048,
                  Wph, Wpl, 2048, 2048, 2048,
                  b_p, nullptr, nullptr, 0, g_p, be_p,
                  nullptr, 0, fh, fl, 2048);
    } else {
        int t = bid - 2048;
        gemm_core(smem, t & 3, t >> 2,
                  xsh, xsl, 1280, nullptr, nullptr, 0, 1280,
                  Wsh, Wsl, 1280, 512, 1280,
                  b_s, nullptr, nullptr, 0, g_s, be_s,
                  sfeats, 512, sfh, sfl, 512);
    }
}

// merged phase-1 launch B: lgpre (4096 CTAs, K=2560, long — first) then
// sgpre (2048 CTAs, K=512).
__global__ void __launch_bounds__(512, 1)
phase1b_kernel(const bf16* fh, const bf16* fl, const bf16* sfh, const bf16* sfl,
               const bf16* Wlh, const bf16* Wll,
               const float* bih_l, const float* bhh_l, float* lgpre,
               const bf16* Wish, const bf16* Wisl,
               const float* bih_s, const float* bhh_s, float* sgpre)
{
    extern __shared__ char smem[];
    int bid = blockIdx.x;
    if (bid < 4096) {
        gemm_core(smem, bid & 31, bid >> 5,
                  fh, fl, 2048, sfh, sfl, 512, 2048,
                  Wlh, Wll, 2560, 4096, 2560,
                  bih_l, bhh_l, nullptr, 0, nullptr, nullptr,
                  lgpre, 4096, nullptr, nullptr, 0);
    } else {
        int t = bid - 4096;
        gemm_core(smem, t & 15, t >> 4,
                  sfh, sfl, 512, nullptr, nullptr, 0, 512,
                  Wish, Wisl, 512, 2048, 512,
                  bih_s, bhh_s, nullptr, 0, nullptr, nullptr,
                  sgpre, 2048, nullptr, nullptr, 0);
    }
}

// fused per-step GEMM + gate, LPT unequal split-K (264 CTAs, crit ~10 chunks):
//   bid 0..127:   Gl parts 0,1 (K=384 each, 6 chunks) — longest first.
//   bid 128..191: Gl part 2 (K=256 @ offset 768, 4 chunks).
//   bid 192..255: Gs parts 0,1 (K=256 each, 4 chunks).
//   bid 256..263: hard gate on OLD state (32 rows/CTA, 16 threads/row).
//   addsrc folded into part 0 only.
__global__ void __launch_bounds__(512, 1)
step_gemm_kernel(const bf16* hsh, const bf16* hsl, const bf16* Whsh, const bf16* Whsl,
                 const float* sgpre_t,
                 const bf16* hlh, const bf16* hll, const bf16* Whlh, const bf16* Whll,
                 const float* lgpre_t,
                 float* Gs2, float* Gl3,
                 const float* sfeats, int t,
                 const float* hl_f32, const float* cl_f32,
                 const float* W_g, const float* b_g, float* r_out)
{
    extern __shared__ char smem[];
    int bid = blockIdx.x;
    if (bid < 128) {
        int p  = bid >> 6;                 // 0 or 1, K offset p*384, len 384
        int tt = bid & 63;
        int bx = tt >> 1, by = tt & 1;
        gemm_core(smem, bx, by,
                  hlh + p * 384, hll + p * 384, 1024, nullptr, nullptr, 0, 384,
                  Whlh + p * 384, Whll + p * 384, 1024, 4096, 384,
                  nullptr, nullptr, (p == 0) ? lgpre_t : nullptr, TT * 4096,
                  nullptr, nullptr,
                  Gl3 + (size_t)p * BB * 4096, 4096, nullptr, nullptr, 0);
    } else if (bid < 192) {
        int tt = bid - 128;                // part 2: K offset 768, len 256
        int bx = tt >> 1, by = tt & 1;
        gemm_core(smem, bx, by,
                  hlh + 768, hll + 768, 1024, nullptr, nullptr, 0, 256,
                  Whlh + 768, Whll + 768, 1024, 4096, 256,
                  nullptr, nullptr, nullptr, 0, nullptr, nullptr,
                  Gl3 + (size_t)2 * BB * 4096, 4096, nullptr, nullptr, 0);
    } else if (bid < 256) {
        int q  = bid - 192;
        int p  = q >> 5;
        int tt = q & 31;
        int bx = tt >> 1, by = tt & 1;
        gemm_core(smem, bx, by,
                  hsh + p * 256, hsl + p * 256, 512, nullptr, nullptr, 0, 256,
                  Whsh + p * 256, Whsl + p * 256, 512, 2048, 256,
                  nullptr, nullptr, (p == 0) ? sgpre_t : nullptr, TT * 2048,
                  nullptr, nullptr,
                  Gs2 + (size_t)p * BB * 2048, 2048, nullptr, nullptr, 0);
    } else {
        // gate: r = one_hot(argmax([s_t, h_l, c_l] @ W_g^T + b_g))
        int b   = (bid - 256) * 32 + (threadIdx.x >> 4);
        int sub = threadIdx.x & 15;
        const float* s = sfeats + ((size_t)b * TT + t) * SS;
        const float* h = hl_f32 + (size_t)b * LL;
        const float* c = cl_f32 + (size_t)b * LL;
        const float* w0 = W_g;
        const float* w1 = W_g + 2560;
        float p0 = 0.f, p1 = 0.f;
        for (int j = sub; j < SS; j += 16) { float v = s[j]; p0 += v * w0[j]; p1 += v * w1[j]; }
        for (int j = sub; j < LL; j += 16) { float v = h[j]; p0 += v * w0[SS + j]; p1 += v * w1[SS + j]; }
        for (int j = sub; j < LL; j += 16) { float v = c[j]; p0 += v * w0[SS + LL + j]; p1 += v * w1[SS + LL + j]; }
#pragma unroll
        for (int o = 8; o > 0; o >>= 1) {
            p0 += __shfl_down_sync(0xFFFFFFFFu, p0, o, 16);
            p1 += __shfl_down_sync(0xFFFFFFFFu, p1, o, 16);
        }
        if (sub == 0) {
            float r0 = (p0 + b_g[0] >= p1 + b_g[1]) ? 1.f : 0.f;
            r_out[b * 2 + 0] = r0;
            r_out[b * 2 + 1] = 1.f - r0;
        }
    }
}

// ---------------------------------------------------------------------------
// Elementwise kernels
// ---------------------------------------------------------------------------
__device__ __forceinline__ float sigf(float x) { return 1.f / (1.f + expf(-x)); }
__device__ __forceinline__ void split1(float v, bf16* hi, bf16* lo, size_t i) {
    bf16 h = __float2bfloat16(v);
    hi[i] = h;
    lo[i] = __float2bfloat16(v - __bfloat162float(h));
}

// one fused split kernel over all 9 tensors (float4-vectorized, grid-stride)
struct SJob { const float4* src; __nv_bfloat162* hi; __nv_bfloat162* lo; };
struct SJobs { SJob j[9]; unsigned cum[10]; };

__global__ void __launch_bounds__(256)
split_all_kernel(SJobs jb, unsigned total4)
{
    const unsigned stride = gridDim.x * blockDim.x;
    for (unsigned i = blockIdx.x * blockDim.x + threadIdx.x; i < total4; i += stride) {
        int k = 0;
#pragma unroll
        for (int q = 0; q < 8; q++) if (i >= jb.cum[q + 1]) k = q + 1;
        unsigned off = i - jb.cum[k];
        float4 v = jb.j[k].src[off];
        bf16 h0 = __float2bfloat16(v.x), h1 = __float2bfloat16(v.y);
        bf16 h2 = __float2bfloat16(v.z), h3 = __float2bfloat16(v.w);
        bf16 l0 = __float2bfloat16(v.x - __bfloat162float(h0));
        bf16 l1 = __float2bfloat16(v.y - __bfloat162float(h1));
        bf16 l2 = __float2bfloat16(v.z - __bfloat162float(h2));
        bf16 l3 = __float2bfloat16(v.w - __bfloat162float(h3));
        jb.j[k].hi[2 * off]     = __nv_bfloat162(h0, h1);
        jb.j[k].hi[2 * off + 1] = __nv_bfloat162(h2, h3);
        jb.j[k].lo[2 * off]     = __nv_bfloat162(l0, l1);
        jb.j[k].lo[2 * off + 1] = __nv_bfloat162(l2, l3);
    }
}

__global__ void zero_states_kernel(float* hl, float* cl, float* hs, float* cs,
                                   bf16* hlh, bf16* hll, bf16* hsh, bf16* hsl)
{
    int i = blockIdx.x * blockDim.x + threadIdx.x;
    if (i < BB * LL) { hl[i] = 0.f; cl[i] = 0.f; hlh[i] = __float2bfloat16(0.f); hll[i] = __float2bfloat16(0.f); }
    if (i < BB * SS) { hs[i] = 0.f; cs[i] = 0.f; hsh[i] = __float2bfloat16(0.f); hsl[i] = __float2bfloat16(0.f); }
}

// fused per-step post-GEMM kernel: small LSTM act + large act/merge.
// Gate already computed by step_gemm (read from r_in). One block per batch row.
__global__ void __launch_bounds__(256)
step_post_kernel(const float* __restrict__ Gs2, const float* __restrict__ Gl3,
                 const float* __restrict__ r_in,
                 const float* __restrict__ h_old, const float* __restrict__ c_old,
                 const float* __restrict__ cs_old,
                 float* __restrict__ hs_new, float* __restrict__ cs_new,
                 bf16* __restrict__ hsh, bf16* __restrict__ hsl,
                 float* __restrict__ h_new, float* __restrict__ c_new,
                 bf16* __restrict__ hh, bf16* __restrict__ hl)
{
    const int b   = blockIdx.x;
    const int tid = threadIdx.x;
    __shared__ float sh_h[SS], sh_c[SS];

    // ---- small LSTM activation (Gs = part0 + part1)
    const float* gs0 = Gs2 + (size_t)b * (4 * SS);
    const float* gs1 = Gs2 + (size_t)BB * 2048 + (size_t)b * (4 * SS);
    for (int n = tid; n < SS; n += 256) {
        float i_ = sigf(gs0[n] + gs1[n]);
        float f_ = sigf(gs0[SS + n] + gs1[SS + n]);
        float gg = tanhf(gs0[2 * SS + n] + gs1[2 * SS + n]);
        float o_ = sigf(gs0[3 * SS + n] + gs1[3 * SS + n]);
        float c2 = f_ * cs_old[(size_t)b * SS + n] + i_ * gg;
        float h2 = o_ * tanhf(c2);
        sh_h[n] = h2; sh_c[n] = c2;
        cs_new[(size_t)b * SS + n] = c2;
        hs_new[(size_t)b * SS + n] = h2;
        split1(h2, hsh, hsl, (size_t)b * SS + n);
    }
    __syncthreads();                       // publish sh_h/sh_c

    const float r0 = r_in[b * 2], r1 = 1.f - r0;

    // ---- large LSTM activation + straight-through merge (Gl = 3 partials)
    const float* gA = Gl3 + (size_t)b * (4 * LL);
    const float* gB = Gl3 + (size_t)BB * 4096 + (size_t)b * (4 * LL);
    const float* gC = Gl3 + (size_t)2 * BB * 4096 + (size_t)b * (4 * LL);
    for (int n = tid; n < LL; n += 256) {
        size_t idx = (size_t)b * LL + n;
        float i_ = sigf(gA[n] + gB[n] + gC[n]);
        float f_ = sigf(gA[LL + n] + gB[LL + n] + gC[LL + n]);
        float gg = tanhf(gA[2 * LL + n] + gB[2 * LL + n] + gC[2 * LL + n]);
        float o_ = sigf(gA[3 * LL + n] + gB[3 * LL + n] + gC[3 * LL + n]);
        float c_ln = f_ * c_old[idx] + i_ * gg;
        float h_ln = o_ * tanhf(c_ln);
        float ph = (n < SS) ? sh_h[n] : h_old[idx];
        float pc = (n < SS) ? sh_c[n] : c_old[idx];
        float h2 = r0 * h_ln + r1 * ph;
        c_new[idx] = r0 * c_ln + r1 * pc;
        h_new[idx] = h2;
        split1(h2, hh, hl, idx);
    }
}

// ---------------------------------------------------------------------------
// Launch
// ---------------------------------------------------------------------------
static inline float* fsym(const void* s) { void* p = nullptr; cudaGetSymbolAddress(&p, s); return (float*)p; }
static inline bf16*  bsym(const void* s) { void* p = nullptr; cudaGetSymbolAddress(&p, s); return (bf16*)p; }

extern "C" void kernel_launch(void* const* d_in, const int* in_sizes, int n_in,
                              void* d_out, int out_size)
{
    const float* x     = (const float*)d_in[0];
    const float* xs    = (const float*)d_in[1];
    const float* W_p   = (const float*)d_in[2];
    const float* b_p   = (const float*)d_in[3];
    const float* g_p   = (const float*)d_in[4];
    const float* be_p  = (const float*)d_in[5];
    const float* W_s   = (const float*)d_in[6];
    const float* b_s   = (const float*)d_in[7];
    const float* g_s   = (const float*)d_in[8];
    const float* be_s  = (const float*)d_in[9];
    const float* Wih_l = (const float*)d_in[10];
    const float* Whh_l = (const float*)d_in[11];
    const float* bih_l = (const float*)d_in[12];
    const float* bhh_l = (const float*)d_in[13];
    const float* Wih_s = (const float*)d_in[14];
    const float* Whh_s = (const float*)d_in[15];
    const float* bih_s = (const float*)d_in[16];
    const float* bhh_s = (const float*)d_in[17];
    const float* W_g   = (const float*)d_in[18];
    const float* b_g   = (const float*)d_in[19];
    const float* W_c   = (const float*)d_in[20];
    const float* b_c   = (const float*)d_in[21];

    float* out = (float*)d_out;
    float* out_logits = out;
    float* out_r      = out + BB * NCLS;

    bf16 *xh = bsym(g_x_hi), *xl = bsym(g_x_lo);
    bf16 *xsh = bsym(g_xs_hi), *xsl = bsym(g_xs_lo);
    bf16 *fh = bsym(g_f_hi), *fl = bsym(g_f_lo);
    bf16 *sfh = bsym(g_sf_hi), *sfl = bsym(g_sf_lo);
    bf16 *Wph = bsym(g_Wp_hi), *Wpl = bsym(g_Wp_lo);
    bf16 *Wsh = bsym(g_Ws_hi), *Wsl = bsym(g_Ws_lo);
    bf16 *Wlh = bsym(g_Wl_hi), *Wll = bsym(g_Wl_lo);
    bf16 *Whlh = bsym(g_Whl_hi), *Whll = bsym(g_Whl_lo);
    bf16 *Wish = bsym(g_Wis_hi), *Wisl = bsym(g_Wis_lo);
    bf16 *Whsh = bsym(g_Whs_hi), *Whsl = bsym(g_Whs_lo);
    bf16 *Wch = bsym(g_Wc_hi), *Wcl = bsym(g_Wc_lo);

    float* sfeats = fsym(g_sfeats);
    float* sgpre  = fsym(g_sgpre);
    float* lgpre  = fsym(g_lgpre);
    float* Gs2 = fsym(g_Gs2);
    float* Gl3 = fsym(g_Gl3);
    float* hl = fsym(g_hl);
    float* cl = fsym(g_cl);
    float* hs = fsym(g_hs);
    float* cs = fsym(g_cs);
    bf16* hlh = bsym(g_hl_hi); bf16* hll = bsym(g_hl_lo);
    bf16* hsh = bsym(g_hs_hi); bf16* hsl = bsym(g_hs_lo);

    cudaFuncSetAttribute(gemm3_kernel, cudaFuncAttributeMaxDynamicSharedMemorySize, GSMEM);
    cudaFuncSetAttribute(phase1a_kernel, cudaFuncAttributeMaxDynamicSharedMemorySize, GSMEM);
    cudaFuncSetAttribute(phase1b_kernel, cudaFuncAttributeMaxDynamicSharedMemorySize, GSMEM);
    cudaFuncSetAttribute(step_gemm_kernel, cudaFuncAttributeMaxDynamicSharedMemorySize, GSMEM);

    const int TPB = 256;

    // ---- fused split of all inputs & weights into bf16 pairs
    {
        SJobs jb;
        const float* srcs[9] = { x, xs, W_p, W_s, Wih_l, Whh_l, Wih_s, Whh_s, W_c };
        bf16* his[9] = { xh, xsh, Wph, Wsh, Wlh, Whlh, Wish, Whsh, Wch };
        bf16* los[9] = { xl, xsl, Wpl, Wsl, Wll, Whll, Wisl, Whsl, Wcl };
        long  ns [9] = { (long)MBT * 2048, (long)MBT * 1280, 2048L * 2048, 512L * 1280,
                         4096L * 2560, 4096L * 1024, 2048L * 512, 2048L * 512,
                         (long)NCLS * 1024 };
        unsigned cum = 0;
        for (int k = 0; k < 9; k++) {
            jb.j[k].src = (const float4*)srcs[k];
            jb.j[k].hi  = (__nv_bfloat162*)his[k];
            jb.j[k].lo  = (__nv_bfloat162*)los[k];
            jb.cum[k] = cum;
            cum += (unsigned)(ns[k] / 4);
        }
        jb.cum[9] = cum;
        int grid = (int)((cum / 2 + TPB - 1) / TPB);     // 2 float4 per thread
        split_all_kernel<<<grid, TPB>>>(jb, cum);
    }
    zero_states_kernel<<<(BB * LL + 255) / 256, TPB>>>(hl, cl, hs, cs, hlh, hll, hsh, hsl);

    // ---- Phase 1: time-parallel GEMMs (two merged launches)
    phase1a_kernel<<<2048 + 512, 512, GSMEM>>>(
        xh, xl, Wph, Wpl, b_p, g_p, be_p, fh, fl,
        xsh, xsl, Wsh, Wsl, b_s, g_s, be_s, sfeats, sfh, sfl);
    phase1b_kernel<<<4096 + 2048, 512, GSMEM>>>(
        fh, fl, sfh, sfl, Wlh, Wll, bih_l, bhh_l, lgpre,
        Wish, Wisl, bih_s, bhh_s, sgpre);

    // ---- Phase 2: recurrence (2 launches per step; gate fused into GEMM wave)
    for (int t = 0; t < TT; t++) {
        int cur = t & 1, nxt = 1 - cur;
        float* hl_c = hl + (size_t)cur * BB * LL;
        float* cl_c = cl + (size_t)cur * BB * LL;
        float* hl_n = hl + (size_t)nxt * BB * LL;
        float* cl_n = cl + (size_t)nxt * BB * LL;
        float* cs_c = cs + (size_t)cur * BB * SS;
        float* hs_n = hs + (size_t)nxt * BB * SS;
        float* cs_n = cs + (size_t)nxt * BB * SS;
        bf16* hlh_c = hlh + (size_t)cur * BB * LL;
        bf16* hll_c = hll + (size_t)cur * BB * LL;
        bf16* hlh_n = hlh + (size_t)nxt * BB * LL;
        bf16* hll_n = hll + (size_t)nxt * BB * LL;
        bf16* hsh_c = hsh + (size_t)cur * BB * SS;
        bf16* hsl_c = hsl + (size_t)cur * BB * SS;
        bf16* hsh_n = hsh + (size_t)nxt * BB * SS;
        bf16* hsl_n = hsl + (size_t)nxt * BB * SS;
        float* r_t = out_r + (size_t)t * BB * 2;

        step_gemm_kernel<<<264, 512, GSMEM>>>(
            hsh_c, hsl_c, Whsh, Whsl, sgpre + (size_t)t * 2048,
            hlh_c, hll_c, Whlh, Whll, lgpre + (size_t)t * 4096,
            Gs2, Gl3,
            sfeats, t, hl_c, cl_c, W_g, b_g, r_t);
        step_post_kernel<<<BB, 256>>>(
            Gs2, Gl3, r_t, hl_c, cl_c, cs_c,
            hs_n, cs_n, hsh_n, hsl_n,
            hl_n, cl_n, hlh_n, hll_n);
    }

    // ---- classifier on final h_l (buffer 0 after 64 steps)
    gemm3_kernel<<<dim3((NCLS + 127) / 128, BB / 128), 512, GSMEM>>>(
        hlh, hll, 1024, nullptr, nullptr, 0, 1024,
        Wch, Wcl, 1024, NCLS, 1024,
        b_c, nullptr, nullptr, 0, nullptr, nullptr,
        out_logits, NCLS, nullptr, nullptr, 0);
}

// round 14
// speedup vs baseline: 1.1298x; 1.0395x over previous
#include <cuda_runtime.h>
#include <cuda_bf16.h>
#include <math.h>
#include <stdint.h>

// ---------------------------------------------------------------------------
// Problem constants
// ---------------------------------------------------------------------------
#define BB 256
#define TT 64
#define LL 1024
#define SS 512
#define NCLS 239
#define MBT (BB * TT)          // 16384

typedef __nv_bfloat16 bf16;

// ---------------------------------------------------------------------------
// Scratch (device globals; no runtime allocation allowed)
// ---------------------------------------------------------------------------
__device__ bf16 g_x_hi  [MBT * 2048];
__device__ bf16 g_x_lo  [MBT * 2048];
__device__ bf16 g_xs_hi [MBT * 1280];
__device__ bf16 g_xs_lo [MBT * 1280];
__device__ bf16 g_f_hi  [MBT * 2048];
__device__ bf16 g_f_lo  [MBT * 2048];
__device__ bf16 g_sf_hi [MBT * 512];
__device__ bf16 g_sf_lo [MBT * 512];
__device__ bf16 g_Wp_hi [2048 * 2048];
__device__ bf16 g_Wp_lo [2048 * 2048];
__device__ bf16 g_Ws_hi [512 * 1280];
__device__ bf16 g_Ws_lo [512 * 1280];
__device__ bf16 g_Wl_hi [4096 * 2560];   // Wih_l full (K-concat GEMM)
__device__ bf16 g_Wl_lo [4096 * 2560];
__device__ bf16 g_Whl_hi[4096 * 1024];   // Whh_l
__device__ bf16 g_Whl_lo[4096 * 1024];
__device__ bf16 g_Wis_hi[2048 * 512];    // Wih_s
__device__ bf16 g_Wis_lo[2048 * 512];
__device__ bf16 g_Whs_hi[2048 * 512];    // Whh_s
__device__ bf16 g_Whs_lo[2048 * 512];
__device__ bf16 g_Wc_hi [NCLS * 1024];
__device__ bf16 g_Wc_lo [NCLS * 1024];
__device__ float g_sfeats[MBT * 512];
__device__ float g_sgpre [MBT * 2048];
__device__ float g_lgpre [MBT * 4096];
__device__ float g_Gs2[2][BB * 2048];    // Gs split-K partials
__device__ float g_Gl3[3][BB * 4096];    // Gl split-K partials (384,384,256)
__device__ float g_hl[2][BB * LL];
__device__ float g_cl[2][BB * LL];
__device__ float g_hs[2][BB * SS];
__device__ float g_cs[2][BB * SS];
__device__ bf16 g_hl_hi[2][BB * LL];
__device__ bf16 g_hl_lo[2][BB * LL];
__device__ bf16 g_hs_hi[2][BB * SS];
__device__ bf16 g_hs_lo[2][BB * SS];

// ---------------------------------------------------------------------------
// PTX helpers (legacy tensor path only — harness targets compute_100)
// ---------------------------------------------------------------------------
__device__ __forceinline__ uint32_t smem_u32(const void* p) {
    return (uint32_t)__cvta_generic_to_shared(p);
}
__device__ __forceinline__ void cp16(uint32_t dst, const void* src, int srcsize) {
    asm volatile("cp.async.cg.shared.global [%0], [%1], 16, %2;\n"
                 :: "r"(dst), "l"(src), "r"(srcsize));
}
__device__ __forceinline__ void cp_commit() {
    asm volatile("cp.async.commit_group;\n");
}
template<int N>
__device__ __forceinline__ void cp_wait() {
    asm volatile("cp.async.wait_group %0;\n" :: "n"(N));
}
__device__ __forceinline__ void ldsm4(uint32_t* r, uint32_t addr) {
    asm volatile("ldmatrix.sync.aligned.m8n8.x4.shared.b16 {%0,%1,%2,%3}, [%4];\n"
                 : "=r"(r[0]), "=r"(r[1]), "=r"(r[2]), "=r"(r[3]) : "r"(addr));
}
__device__ __forceinline__ void mma_bf16(float* d, const uint32_t* a, uint32_t b0, uint32_t b1) {
    asm volatile("mma.sync.aligned.m16n8k16.row.col.f32.bf16.bf16.f32 "
                 "{%0,%1,%2,%3},{%4,%5,%6,%7},{%8,%9},{%0,%1,%2,%3};\n"
                 : "+f"(d[0]), "+f"(d[1]), "+f"(d[2]), "+f"(d[3])
                 : "r"(a[0]), "r"(a[1]), "r"(a[2]), "r"(a[3]), "r"(b0), "r"(b1));
}

// ---------------------------------------------------------------------------
// Split-bf16 triple-product GEMM core, register-reuse schedule, K64 chunks.
//   C[M,N] = epi( A@W^T ), A = A_hi+A_lo, W = W_hi+W_lo, computed as
//   Ahi*Whi + Ahi*Wlo + Alo*Whi accumulated in fp32.
//   One pipeline stage = one K64 chunk = 8 K32 tiles {Ah,Al,Bh,Bl} x {k0,k1};
//   NSTG=2 ring (163840 B). ONE barrier + ONE cp.wait per K64 chunk.
//   Fragment loads ordered (ah,bh) -> product1 MMAs -> (al,bl) -> products 2,3.
//   BM=BN=128, 512 threads (16 warps, 32x32 tiles), 1 CTA/SM.
//   A may be a K-concat: cols [0,K1) from A, [K1,K) from A2 (K1 % 64 == 0).
//   Requires K % 64 == 0.
// ---------------------------------------------------------------------------
#define LDSH 40                         // halves per smem row (padded)
#define TILEB (128 * LDSH * 2)          // one K32 tile = 10240 bytes
#define GSMEM (16 * TILEB)              // 2 stages * 8 tiles = 163840 bytes

__device__ __forceinline__ void gemm_core(
    char* smem, int bx, int by,
    const bf16* __restrict__ Ahi, const bf16* __restrict__ Alo, int lda,
    const bf16* __restrict__ A2hi, const bf16* __restrict__ A2lo, int lda2, int K1,
    const bf16* __restrict__ Bhi, const bf16* __restrict__ Blo, int ldb,
    int N, int K,
    const float* __restrict__ b1, const float* __restrict__ b2,
    const float* __restrict__ addsrc, int ldadd,
    const float* __restrict__ gamma, const float* __restrict__ beta,
    float* __restrict__ Cf, int ldc,
    bf16* __restrict__ Chi, bf16* __restrict__ Clo, int ldsp)
{
    constexpr int BM = 128;
    const int tid  = threadIdx.x;
    const int lane = tid & 31;
    const int wid  = tid >> 5;          // 0..15
    const int wm   = wid >> 2;          // 4 warp rows (32 each)
    const int wn   = wid & 3;           // 4 warp cols (32 each)
    const int bm   = by * BM;
    const int bn   = bx * BM;

    const int NC = K / 64;              // K64 chunks

    float acc[2][4][4];
#pragma unroll
    for (int i = 0; i < 2; i++)
#pragma unroll
        for (int j = 0; j < 4; j++)
#pragma unroll
            for (int r = 0; r < 4; r++) acc[i][j][r] = 0.f;

    // one cp16 per thread per K32 tile (512 threads cover a 128x32 tile)
    const int srow = tid >> 2;
    const int skc  = (tid & 3) * 8;
    auto stage = [&](int c) {
        int k0 = c * 64;
        const bf16 *Ah, *Al; int ald, ak;
        if (k0 < K1) { Ah = Ahi;  Al = Alo;  ald = lda;  ak = k0; }
        else         { Ah = A2hi; Al = A2lo; ald = lda2; ak = k0 - K1; }
        uint32_t base = smem_u32(smem) + (c & 1) * (8 * TILEB);
        uint32_t soff = (srow * LDSH + skc) * 2;
        int n = bn + srow;
        bool ok = (n < N);
#pragma unroll
        for (int h = 0; h < 2; h++) {
            size_t aoff = (size_t)(bm + srow) * ald + ak + h * 32 + skc;
            cp16(base + (0 + h) * TILEB + soff, Ah + aoff, 16);
            cp16(base + (2 + h) * TILEB + soff, Al + aoff, 16);
            size_t boff = (size_t)(ok ? n : 0) * ldb + k0 + h * 32 + skc;
            cp16(base + (4 + h) * TILEB + soff, Bhi + boff, ok ? 16 : 0);
            cp16(base + (6 + h) * TILEB + soff, Blo + boff, ok ? 16 : 0);
        }
    };

    stage(0); cp_commit();

    // fragment addresses (fixed per thread, K-offset varies)
    const int arow = wm * 32 + (lane & 15);
    const int akk0 = (lane >> 4) * 8;
    const int brow = wn * 32 + (lane & 7) + ((lane >> 4) << 3);
    const int bkk0 = ((lane >> 3) & 1) << 3;

    for (int c = 0; c < NC; c++) {
        cp_wait<0>();
        __syncthreads();   // chunk c landed; all warps done reading chunk c-1
        if (c + 1 < NC) { stage(c + 1); cp_commit(); }

        uint32_t base = smem_u32(smem) + (c & 1) * (8 * TILEB);
#pragma unroll
        for (int h = 0; h < 2; h++) {
            uint32_t bAh = base + (0 + h) * TILEB;
            uint32_t bAl = base + (2 + h) * TILEB;
            uint32_t bBh = base + (4 + h) * TILEB;
            uint32_t bBl = base + (6 + h) * TILEB;
#pragma unroll
            for (int ks = 0; ks < 32; ks += 16) {
                uint32_t ah[2][4], al[2][4], bh[4][2], bl[4][2];
                const int akk = ks + akk0;
                const int bkk = ks + bkk0;
                // --- hi fragments first: unlock product 1 ASAP
#pragma unroll
                for (int mi = 0; mi < 2; mi++)
                    ldsm4(ah[mi], bAh + ((arow + mi * 16) * LDSH + akk) * 2);
#pragma unroll
                for (int ng = 0; ng < 2; ng++) {
                    uint32_t t[4];
                    ldsm4(t, bBh + ((brow + ng * 16) * LDSH + bkk) * 2);
                    bh[2 * ng][0] = t[0]; bh[2 * ng][1] = t[1];
                    bh[2 * ng + 1][0] = t[2]; bh[2 * ng + 1][1] = t[3];
                }
#pragma unroll
                for (int mi = 0; mi < 2; mi++)
#pragma unroll
                    for (int nj = 0; nj < 4; nj++)
                        mma_bf16(acc[mi][nj], ah[mi], bh[nj][0], bh[nj][1]);
                // --- lo fragments overlap under product-1 MMAs
#pragma unroll
                for (int mi = 0; mi < 2; mi++)
                    ldsm4(al[mi], bAl + ((arow + mi * 16) * LDSH + akk) * 2);
#pragma unroll
                for (int ng = 0; ng < 2; ng++) {
                    uint32_t t[4];
                    ldsm4(t, bBl + ((brow + ng * 16) * LDSH + bkk) * 2);
                    bl[2 * ng][0] = t[0]; bl[2 * ng][1] = t[1];
                    bl[2 * ng + 1][0] = t[2]; bl[2 * ng + 1][1] = t[3];
                }
#pragma unroll
                for (int mi = 0; mi < 2; mi++)
#pragma unroll
                    for (int nj = 0; nj < 4; nj++)
                        mma_bf16(acc[mi][nj], ah[mi], bl[nj][0], bl[nj][1]);
#pragma unroll
                for (int mi = 0; mi < 2; mi++)
#pragma unroll
                    for (int nj = 0; nj < 4; nj++)
                        mma_bf16(acc[mi][nj], al[mi], bh[nj][0], bh[nj][1]);
            }
        }
    }

    // ---- epilogue (register-resident)
    const float inv_std = rsqrtf(1.0f + 1e-5f);
    const int g  = lane >> 2;
    const int tg = lane & 3;
#pragma unroll
    for (int mi = 0; mi < 2; mi++)
#pragma unroll
        for (int nj = 0; nj < 4; nj++)
#pragma unroll
            for (int r = 0; r < 4; r++) {
                int m = bm + wm * 32 + mi * 16 + g + ((r >> 1) << 3);
                int n = bn + wn * 32 + nj * 8 + tg * 2 + (r & 1);
                if (n >= N) continue;
                float v = acc[mi][nj][r];
                if (b1)     v += b1[n];
                if (b2)     v += b2[n];
                if (addsrc) v += addsrc[(size_t)m * ldadd + n];
                if (gamma)  v = fmaxf(0.f, v * (gamma[n] * inv_std) + beta[n]);
                if (Cf)     Cf[(size_t)m * ldc + n] = v;
                if (Chi) {
                    bf16 h = __float2bfloat16(v);
                    Chi[(size_t)m * ldsp + n] = h;
                    Clo[(size_t)m * ldsp + n] = __float2bfloat16(v - __bfloat162float(h));
                }
            }
}

// standalone GEMM launcher (512 threads, 1 CTA/SM) — used for the classifier
__global__ void __launch_bounds__(512, 1)
gemm3_kernel(const bf16* Ahi, const bf16* Alo, int lda,
             const bf16* A2hi, const bf16* A2lo, int lda2, int K1,
             const bf16* Bhi, const bf16* Blo, int ldb,
             int N, int K,
             const float* b1, const float* b2,
             const float* addsrc, int ldadd,
             const float* gamma, const float* beta,
             float* Cf, int ldc,
             bf16* Chi, bf16* Clo, int ldsp)
{
    extern __shared__ char smem[];
    gemm_core(smem, blockIdx.x, blockIdx.y,
              Ahi, Alo, lda, A2hi, A2lo, lda2, K1, Bhi, Blo, ldb, N, K,
              b1, b2, addsrc, ldadd, gamma, beta, Cf, ldc, Chi, Clo, ldsp);
}

// merged phase-1 launch A: feats (2048 CTAs, K=2048, long — first) then
// sfeats (512 CTAs, K=1280). Short jobs backfill the long jobs' tail wave.
__global__ void __launch_bounds__(512, 1)
phase1a_kernel(const bf16* xh, const bf16* xl, const bf16* Wph, const bf16* Wpl,
               const float* b_p, const float* g_p, const float* be_p,
               bf16* fh, bf16* fl,
               const bf16* xsh, const bf16* xsl, const bf16* Wsh, const bf16* Wsl,
               const float* b_s, const float* g_s, const float* be_s,
               float* sfeats, bf16* sfh, bf16* sfl)
{
    extern __shared__ char smem[];
    int bid = blockIdx.x;
    if (bid < 2048) {
        gemm_core(smem, bid & 15, bid >> 4,
                  xh, xl, 2048, nullptr, nullptr, 0, 2048,
                  Wph, Wpl, 2048, 2048, 2048,
                  b_p, nullptr, nullptr, 0, g_p, be_p,
                  nullptr, 0, fh, fl, 2048);
    } else {
        int t = bid - 2048;
        gemm_core(smem, t & 3, t >> 2,
                  xsh, xsl, 1280, nullptr, nullptr, 0, 1280,
                  Wsh, Wsl, 1280, 512, 1280,
                  b_s, nullptr, nullptr, 0, g_s, be_s,
                  sfeats, 512, sfh, sfl, 512);
    }
}

// merged phase-1 launch B: lgpre (4096 CTAs, K=2560, long — first) then
// sgpre (2048 CTAs, K=512).
__global__ void __launch_bounds__(512, 1)
phase1b_kernel(const bf16* fh, const bf16* fl, const bf16* sfh, const bf16* sfl,
               const bf16* Wlh, const bf16* Wll,
               const float* bih_l, const float* bhh_l, float* lgpre,
               const bf16* Wish, const bf16* Wisl,
               const float* bih_s, const float* bhh_s, float* sgpre)
{
    extern __shared__ char smem[];
    int bid = blockIdx.x;
    if (bid < 4096) {
        gemm_core(smem, bid & 31, bid >> 5,
                  fh, fl, 2048, sfh, sfl, 512, 2048,
                  Wlh, Wll, 2560, 4096, 2560,
                  bih_l, bhh_l, nullptr, 0, nullptr, nullptr,
                  lgpre, 4096, nullptr, nullptr, 0);
    } else {
        int t = bid - 4096;
        gemm_core(smem, t & 15, t >> 4,
                  sfh, sfl, 512, nullptr, nullptr, 0, 512,
                  Wish, Wisl, 512, 2048, 512,
                  bih_s, bhh_s, nullptr, 0, nullptr, nullptr,
                  sgpre, 2048, nullptr, nullptr, 0);
    }
}

// fused per-step GEMM + gate, LPT unequal split-K (264 CTAs, crit ~10 chunks):
//   bid 0..127:   Gl parts 0,1 (K=384 each, 6 chunks) — longest first.
//   bid 128..191: Gl part 2 (K=256 @ offset 768, 4 chunks).
//   bid 192..255: Gs parts 0,1 (K=256 each, 4 chunks).
//   bid 256..263: hard gate on OLD state (32 rows/CTA, 16 threads/row).
//   addsrc folded into part 0 only.
__global__ void __launch_bounds__(512, 1)
step_gemm_kernel(const bf16* hsh, const bf16* hsl, const bf16* Whsh, const bf16* Whsl,
                 const float* sgpre_t,
                 const bf16* hlh, const bf16* hll, const bf16* Whlh, const bf16* Whll,
                 const float* lgpre_t,
                 float* Gs2, float* Gl3,
                 const float* sfeats, int t,
                 const float* hl_f32, const float* cl_f32,
                 const float* W_g, const float* b_g, float* r_out)
{
    extern __shared__ char smem[];
    int bid = blockIdx.x;
    if (bid < 128) {
        int p  = bid >> 6;                 // 0 or 1, K offset p*384, len 384
        int tt = bid & 63;
        int bx = tt >> 1, by = tt & 1;
        gemm_core(smem, bx, by,
                  hlh + p * 384, hll + p * 384, 1024, nullptr, nullptr, 0, 384,
                  Whlh + p * 384, Whll + p * 384, 1024, 4096, 384,
                  nullptr, nullptr, (p == 0) ? lgpre_t : nullptr, TT * 4096,
                  nullptr, nullptr,
                  Gl3 + (size_t)p * BB * 4096, 4096, nullptr, nullptr, 0);
    } else if (bid < 192) {
        int tt = bid - 128;                // part 2: K offset 768, len 256
        int bx = tt >> 1, by = tt & 1;
        gemm_core(smem, bx, by,
                  hlh + 768, hll + 768, 1024, nullptr, nullptr, 0, 256,
                  Whlh + 768, Whll + 768, 1024, 4096, 256,
                  nullptr, nullptr, nullptr, 0, nullptr, nullptr,
                  Gl3 + (size_t)2 * BB * 4096, 4096, nullptr, nullptr, 0);
    } else if (bid < 256) {
        int q  = bid - 192;
        int p  = q >> 5;
        int tt = q & 31;
        int bx = tt >> 1, by = tt & 1;
        gemm_core(smem, bx, by,
                  hsh + p * 256, hsl + p * 256, 512, nullptr, nullptr, 0, 256,
                  Whsh + p * 256, Whsl + p * 256, 512, 2048, 256,
                  nullptr, nullptr, (p == 0) ? sgpre_t : nullptr, TT * 2048,
                  nullptr, nullptr,
                  Gs2 + (size_t)p * BB * 2048, 2048, nullptr, nullptr, 0);
    } else {
        // gate: r = one_hot(argmax([s_t, h_l, c_l] @ W_g^T + b_g))
        int b   = (bid - 256) * 32 + (threadIdx.x >> 4);
        int sub = threadIdx.x & 15;
        const float* s = sfeats + ((size_t)b * TT + t) * SS;
        const float* h = hl_f32 + (size_t)b * LL;
        const float* c = cl_f32 + (size_t)b * LL;
        const float* w0 = W_g;
        const float* w1 = W_g + 2560;
        float p0 = 0.f, p1 = 0.f;
        for (int j = sub; j < SS; j += 16) { float v = s[j]; p0 += v * w0[j]; p1 += v * w1[j]; }
        for (int j = sub; j < LL; j += 16) { float v = h[j]; p0 += v * w0[SS + j]; p1 += v * w1[SS + j]; }
        for (int j = sub; j < LL; j += 16) { float v = c[j]; p0 += v * w0[SS + LL + j]; p1 += v * w1[SS + LL + j]; }
#pragma unroll
        for (int o = 8; o > 0; o >>= 1) {
            p0 += __shfl_down_sync(0xFFFFFFFFu, p0, o, 16);
            p1 += __shfl_down_sync(0xFFFFFFFFu, p1, o, 16);
        }
        if (sub == 0) {
            float r0 = (p0 + b_g[0] >= p1 + b_g[1]) ? 1.f : 0.f;
            r_out[b * 2 + 0] = r0;
            r_out[b * 2 + 1] = 1.f - r0;
        }
    }
}

// ---------------------------------------------------------------------------
// Elementwise kernels
// ---------------------------------------------------------------------------
__device__ __forceinline__ float sigf(float x) { return 1.f / (1.f + expf(-x)); }
__device__ __forceinline__ void split1(float v, bf16* hi, bf16* lo, size_t i) {
    bf16 h = __float2bfloat16(v);
    hi[i] = h;
    lo[i] = __float2bfloat16(v - __bfloat162float(h));
}
// store a float4's bf16 hi/lo splits at element offset off (off % 4 == 0)
__device__ __forceinline__ void split_store4(const float4& v, bf16* hi, bf16* lo, size_t off) {
    bf16 h0 = __float2bfloat16(v.x), h1 = __float2bfloat16(v.y);
    bf16 h2 = __float2bfloat16(v.z), h3 = __float2bfloat16(v.w);
    __nv_bfloat162* H = (__nv_bfloat162*)(hi + off);
    H[0] = __nv_bfloat162(h0, h1); H[1] = __nv_bfloat162(h2, h3);
    bf16 l0 = __float2bfloat16(v.x - __bfloat162float(h0));
    bf16 l1 = __float2bfloat16(v.y - __bfloat162float(h1));
    bf16 l2 = __float2bfloat16(v.z - __bfloat162float(h2));
    bf16 l3 = __float2bfloat16(v.w - __bfloat162float(h3));
    __nv_bfloat162* L = (__nv_bfloat162*)(lo + off);
    L[0] = __nv_bfloat162(l0, l1); L[1] = __nv_bfloat162(l2, l3);
}

// one fused split kernel over all 9 tensors, MLP=4 (4 grid-strided float4/thread)
struct SJob { const float4* src; __nv_bfloat162* hi; __nv_bfloat162* lo; };
struct SJobs { SJob j[9]; unsigned cum[10]; };

__global__ void __launch_bounds__(256)
split_all_kernel(SJobs jb, unsigned total4)
{
    const unsigned S = gridDim.x * blockDim.x;
    const unsigned base = blockIdx.x * blockDim.x + threadIdx.x;
    float4 v[4];
    int kk[4];
    unsigned off[4];
    bool ok[4];
#pragma unroll
    for (int q = 0; q < 4; q++) {
        unsigned i = base + q * S;
        ok[q] = (i < total4);
        if (ok[q]) {
            int k = 0;
#pragma unroll
            for (int z = 0; z < 8; z++) if (i >= jb.cum[z + 1]) k = z + 1;
            kk[q]  = k;
            off[q] = i - jb.cum[k];
            v[q]   = jb.j[k].src[off[q]];   // 4 independent loads in flight
        }
    }
#pragma unroll
    for (int q = 0; q < 4; q++) {
        if (!ok[q]) continue;
        float4 x = v[q];
        int k = kk[q];
        unsigned o = off[q];
        bf16 h0 = __float2bfloat16(x.x), h1 = __float2bfloat16(x.y);
        bf16 h2 = __float2bfloat16(x.z), h3 = __float2bfloat16(x.w);
        bf16 l0 = __float2bfloat16(x.x - __bfloat162float(h0));
        bf16 l1 = __float2bfloat16(x.y - __bfloat162float(h1));
        bf16 l2 = __float2bfloat16(x.z - __bfloat162float(h2));
        bf16 l3 = __float2bfloat16(x.w - __bfloat162float(h3));
        jb.j[k].hi[2 * o]     = __nv_bfloat162(h0, h1);
        jb.j[k].hi[2 * o + 1] = __nv_bfloat162(h2, h3);
        jb.j[k].lo[2 * o]     = __nv_bfloat162(l0, l1);
        jb.j[k].lo[2 * o + 1] = __nv_bfloat162(l2, l3);
    }
}

__global__ void zero_states_kernel(float* hl, float* cl, float* hs, float* cs,
                                   bf16* hlh, bf16* hll, bf16* hsh, bf16* hsl)
{
    int i = blockIdx.x * blockDim.x + threadIdx.x;
    if (i < BB * LL) { hl[i] = 0.f; cl[i] = 0.f; hlh[i] = __float2bfloat16(0.f); hll[i] = __float2bfloat16(0.f); }
    if (i < BB * SS) { hs[i] = 0.f; cs[i] = 0.f; hsh[i] = __float2bfloat16(0.f); hsl[i] = __float2bfloat16(0.f); }
}

// fused per-step post-GEMM kernel: small LSTM act + large act/merge.
// Gate precomputed by step_gemm (r_in). One block/batch row, float4-vectorized.
__global__ void __launch_bounds__(256)
step_post_kernel(const float* __restrict__ Gs2, const float* __restrict__ Gl3,
                 const float* __restrict__ r_in,
                 const float* __restrict__ h_old, const float* __restrict__ c_old,
                 const float* __restrict__ cs_old,
                 float* __restrict__ hs_new, float* __restrict__ cs_new,
                 bf16* __restrict__ hsh, bf16* __restrict__ hsl,
                 float* __restrict__ h_new, float* __restrict__ c_new,
                 bf16* __restrict__ hh, bf16* __restrict__ hl)
{
    const int b   = blockIdx.x;
    const int tid = threadIdx.x;
    __shared__ float4 sh_h4[SS / 4], sh_c4[SS / 4];

    // ---- small LSTM activation (Gs = part0 + part1), one float4 per thread
    if (tid < SS / 4) {
        const float4* gs0 = (const float4*)(Gs2 + (size_t)b * (4 * SS));
        const float4* gs1 = (const float4*)(Gs2 + (size_t)BB * 2048 + (size_t)b * (4 * SS));
        const float4* co4 = (const float4*)(cs_old + (size_t)b * SS);
        int n4 = tid;
        float4 ia = gs0[n4],           ib = gs1[n4];
        float4 fa = gs0[128 + n4],     fb = gs1[128 + n4];
        float4 ga = gs0[256 + n4],     gb = gs1[256 + n4];
        float4 oa = gs0[384 + n4],     ob = gs1[384 + n4];
        float4 co = co4[n4];
        float4 h2, c2;
        {
            float i_ = sigf(ia.x + ib.x), f_ = sigf(fa.x + fb.x);
            float g_ = tanhf(ga.x + gb.x), o_ = sigf(oa.x + ob.x);
            c2.x = f_ * co.x + i_ * g_; h2.x = o_ * tanhf(c2.x);
            i_ = sigf(ia.y + ib.y); f_ = sigf(fa.y + fb.y);
            g_ = tanhf(ga.y + gb.y); o_ = sigf(oa.y + ob.y);
            c2.y = f_ * co.y + i_ * g_; h2.y = o_ * tanhf(c2.y);
            i_ = sigf(ia.z + ib.z); f_ = sigf(fa.z + fb.z);
            g_ = tanhf(ga.z + gb.z); o_ = sigf(oa.z + ob.z);
            c2.z = f_ * co.z + i_ * g_; h2.z = o_ * tanhf(c2.z);
            i_ = sigf(ia.w + ib.w); f_ = sigf(fa.w + fb.w);
            g_ = tanhf(ga.w + gb.w); o_ = sigf(oa.w + ob.w);
            c2.w = f_ * co.w + i_ * g_; h2.w = o_ * tanhf(c2.w);
        }
        sh_h4[n4] = h2; sh_c4[n4] = c2;
        ((float4*)(cs_new + (size_t)b * SS))[n4] = c2;
        ((float4*)(hs_new + (size_t)b * SS))[n4] = h2;
        split_store4(h2, hsh, hsl, (size_t)b * SS + 4 * n4);
    }
    __syncthreads();                       // publish sh_h4/sh_c4

    const float r0 = r_in[b * 2], r1 = 1.f - r0;

    // ---- large LSTM activation + merge (Gl = 3 partials), one float4 per thread
    {
        const float4* gA = (const float4*)(Gl3 + (size_t)b * (4 * LL));
        const float4* gB = (const float4*)(Gl3 + (size_t)BB * 4096 + (size_t)b * (4 * LL));
        const float4* gC = (const float4*)(Gl3 + (size_t)2 * BB * 4096 + (size_t)b * (4 * LL));
        const float4* ho4 = (const float4*)(h_old + (size_t)b * LL);
        const float4* co4 = (const float4*)(c_old + (size_t)b * LL);
        int n4 = tid;                      // 0..255 covers LL/4
        float4 iA = gA[n4],        iB = gB[n4],        iC = gC[n4];
        float4 fA = gA[256 + n4],  fB = gB[256 + n4],  fC = gC[256 + n4];
        float4 gA4 = gA[512 + n4], gB4 = gB[512 + n4], gC4 = gC[512 + n4];
        float4 oA = gA[768 + n4],  oB = gB[768 + n4],  oC = gC[768 + n4];
        float4 ho = ho4[n4], co = co4[n4];
        float4 ph, pc;
        if (n4 < SS / 4) { ph = sh_h4[n4]; pc = sh_c4[n4]; }
        else             { ph = ho;        pc = co; }
        float4 h2, c2;
        {
            float i_ = sigf(iA.x + iB.x + iC.x), f_ = sigf(fA.x + fB.x + fC.x);
            float g_ = tanhf(gA4.x + gB4.x + gC4.x), o_ = sigf(oA.x + oB.x + oC.x);
            float cl_ = f_ * co.x + i_ * g_, hl_ = o_ * tanhf(cl_);
            h2.x = r0 * hl_ + r1 * ph.x; c2.x = r0 * cl_ + r1 * pc.x;
            i_ = sigf(iA.y + iB.y + iC.y); f_ = sigf(fA.y + fB.y + fC.y);
            g_ = tanhf(gA4.y + gB4.y + gC4.y); o_ = sigf(oA.y + oB.y + oC.y);
            cl_ = f_ * co.y + i_ * g_; hl_ = o_ * tanhf(cl_);
            h2.y = r0 * hl_ + r1 * ph.y; c2.y = r0 * cl_ + r1 * pc.y;
            i_ = sigf(iA.z + iB.z + iC.z); f_ = sigf(fA.z + fB.z + fC.z);
            g_ = tanhf(gA4.z + gB4.z + gC4.z); o_ = sigf(oA.z + oB.z + oC.z);
            cl_ = f_ * co.z + i_ * g_; hl_ = o_ * tanhf(cl_);
            h2.z = r0 * hl_ + r1 * ph.z; c2.z = r0 * cl_ + r1 * pc.z;
            i_ = sigf(iA.w + iB.w + iC.w); f_ = sigf(fA.w + fB.w + fC.w);
            g_ = tanhf(gA4.w + gB4.w + gC4.w); o_ = sigf(oA.w + oB.w + oC.w);
            cl_ = f_ * co.w + i_ * g_; hl_ = o_ * tanhf(cl_);
            h2.w = r0 * hl_ + r1 * ph.w; c2.w = r0 * cl_ + r1 * pc.w;
        }
        ((float4*)(c_new + (size_t)b * LL))[n4] = c2;
        ((float4*)(h_new + (size_t)b * LL))[n4] = h2;
        split_store4(h2, hh, hl, (size_t)b * LL + 4 * n4);
    }
}

// ---------------------------------------------------------------------------
// Launch
// ---------------------------------------------------------------------------
static inline float* fsym(const void* s) { void* p = nullptr; cudaGetSymbolAddress(&p, s); return (float*)p; }
static inline bf16*  bsym(const void* s) { void* p = nullptr; cudaGetSymbolAddress(&p, s); return (bf16*)p; }

extern "C" void kernel_launch(void* const* d_in, const int* in_sizes, int n_in,
                              void* d_out, int out_size)
{
    const float* x     = (const float*)d_in[0];
    const float* xs    = (const float*)d_in[1];
    const float* W_p   = (const float*)d_in[2];
    const float* b_p   = (const float*)d_in[3];
    const float* g_p   = (const float*)d_in[4];
    const float* be_p  = (const float*)d_in[5];
    const float* W_s   = (const float*)d_in[6];
    const float* b_s   = (const float*)d_in[7];
    const float* g_s   = (const float*)d_in[8];
    const float* be_s  = (const float*)d_in[9];
    const float* Wih_l = (const float*)d_in[10];
    const float* Whh_l = (const float*)d_in[11];
    const float* bih_l = (const float*)d_in[12];
    const float* bhh_l = (const float*)d_in[13];
    const float* Wih_s = (const float*)d_in[14];
    const float* Whh_s = (const float*)d_in[15];
    const float* bih_s = (const float*)d_in[16];
    const float* bhh_s = (const float*)d_in[17];
    const float* W_g   = (const float*)d_in[18];
    const float* b_g   = (const float*)d_in[19];
    const float* W_c   = (const float*)d_in[20];
    const float* b_c   = (const float*)d_in[21];

    float* out = (float*)d_out;
    float* out_logits = out;
    float* out_r      = out + BB * NCLS;

    bf16 *xh = bsym(g_x_hi), *xl = bsym(g_x_lo);
    bf16 *xsh = bsym(g_xs_hi), *xsl = bsym(g_xs_lo);
    bf16 *fh = bsym(g_f_hi), *fl = bsym(g_f_lo);
    bf16 *sfh = bsym(g_sf_hi), *sfl = bsym(g_sf_lo);
    bf16 *Wph = bsym(g_Wp_hi), *Wpl = bsym(g_Wp_lo);
    bf16 *Wsh = bsym(g_Ws_hi), *Wsl = bsym(g_Ws_lo);
    bf16 *Wlh = bsym(g_Wl_hi), *Wll = bsym(g_Wl_lo);
    bf16 *Whlh = bsym(g_Whl_hi), *Whll = bsym(g_Whl_lo);
    bf16 *Wish = bsym(g_Wis_hi), *Wisl = bsym(g_Wis_lo);
    bf16 *Whsh = bsym(g_Whs_hi), *Whsl = bsym(g_Whs_lo);
    bf16 *Wch = bsym(g_Wc_hi), *Wcl = bsym(g_Wc_lo);

    float* sfeats = fsym(g_sfeats);
    float* sgpre  = fsym(g_sgpre);
    float* lgpre  = fsym(g_lgpre);
    float* Gs2 = fsym(g_Gs2);
    float* Gl3 = fsym(g_Gl3);
    float* hl = fsym(g_hl);
    float* cl = fsym(g_cl);
    float* hs = fsym(g_hs);
    float* cs = fsym(g_cs);
    bf16* hlh = bsym(g_hl_hi); bf16* hll = bsym(g_hl_lo);
    bf16* hsh = bsym(g_hs_hi); bf16* hsl = bsym(g_hs_lo);

    cudaFuncSetAttribute(gemm3_kernel, cudaFuncAttributeMaxDynamicSharedMemorySize, GSMEM);
    cudaFuncSetAttribute(phase1a_kernel, cudaFuncAttributeMaxDynamicSharedMemorySize, GSMEM);
    cudaFuncSetAttribute(phase1b_kernel, cudaFuncAttributeMaxDynamicSharedMemorySize, GSMEM);
    cudaFuncSetAttribute(step_gemm_kernel, cudaFuncAttributeMaxDynamicSharedMemorySize, GSMEM);

    const int TPB = 256;

    // ---- fused split of all inputs & weights into bf16 pairs (MLP=4)
    {
        SJobs jb;
        const float* srcs[9] = { x, xs, W_p, W_s, Wih_l, Whh_l, Wih_s, Whh_s, W_c };
        bf16* his[9] = { xh, xsh, Wph, Wsh, Wlh, Whlh, Wish, Whsh, Wch };
        bf16* los[9] = { xl, xsl, Wpl, Wsl, Wll, Whll, Wisl, Whsl, Wcl };
        long  ns [9] = { (long)MBT * 2048, (long)MBT * 1280, 2048L * 2048, 512L * 1280,
                         4096L * 2560, 4096L * 1024, 2048L * 512, 2048L * 512,
                         (long)NCLS * 1024 };
        unsigned cum = 0;
        for (int k = 0; k < 9; k++) {
            jb.j[k].src = (const float4*)srcs[k];
            jb.j[k].hi  = (__nv_bfloat162*)his[k];
            jb.j[k].lo  = (__nv_bfloat162*)los[k];
            jb.cum[k] = cum;
            cum += (unsigned)(ns[k] / 4);
        }
        jb.cum[9] = cum;
        int grid = (int)((cum + TPB * 4 - 1) / (TPB * 4));   // 4 float4 per thread
        split_all_kernel<<<grid, TPB>>>(jb, cum);
    }
    zero_states_kernel<<<(BB * LL + 255) / 256, TPB>>>(hl, cl, hs, cs, hlh, hll, hsh, hsl);

    // ---- Phase 1: time-parallel GEMMs (two merged launches)
    phase1a_kernel<<<2048 + 512, 512, GSMEM>>>(
        xh, xl, Wph, Wpl, b_p, g_p, be_p, fh, fl,
        xsh, xsl, Wsh, Wsl, b_s, g_s, be_s, sfeats, sfh, sfl);
    phase1b_kernel<<<4096 + 2048, 512, GSMEM>>>(
        fh, fl, sfh, sfl, Wlh, Wll, bih_l, bhh_l, lgpre,
        Wish, Wisl, bih_s, bhh_s, sgpre);

    // ---- Phase 2: recurrence (2 launches per step; gate fused into GEMM wave)
    for (int t = 0; t < TT; t++) {
        int cur = t & 1, nxt = 1 - cur;
        float* hl_c = hl + (size_t)cur * BB * LL;
        float* cl_c = cl + (size_t)cur * BB * LL;
        float* hl_n = hl + (size_t)nxt * BB * LL;
        float* cl_n = cl + (size_t)nxt * BB * LL;
        float* cs_c = cs + (size_t)cur * BB * SS;
        float* hs_n = hs + (size_t)nxt * BB * SS;
        float* cs_n = cs + (size_t)nxt * BB * SS;
        bf16* hlh_c = hlh + (size_t)cur * BB * LL;
        bf16* hll_c = hll + (size_t)cur * BB * LL;
        bf16* hlh_n = hlh + (size_t)nxt * BB * LL;
        bf16* hll_n = hll + (size_t)nxt * BB * LL;
        bf16* hsh_c = hsh + (size_t)cur * BB * SS;
        bf16* hsl_c = hsl + (size_t)cur * BB * SS;
        bf16* hsh_n = hsh + (size_t)nxt * BB * SS;
        bf16* hsl_n = hsl + (size_t)nxt * BB * SS;
        float* r_t = out_r + (size_t)t * BB * 2;

        step_gemm_kernel<<<264, 512, GSMEM>>>(
            hsh_c, hsl_c, Whsh, Whsl, sgpre + (size_t)t * 2048,
            hlh_c, hll_c, Whlh, Whll, lgpre + (size_t)t * 4096,
            Gs2, Gl3,
            sfeats, t, hl_c, cl_c, W_g, b_g, r_t);
        step_post_kernel<<<BB, 256>>>(
            Gs2, Gl3, r_t, hl_c, cl_c, cs_c,
            hs_n, cs_n, hsh_n, hsl_n,
            hl_n, cl_n, hlh_n, hll_n);
    }

    // ---- classifier on final h_l (buffer 0 after 64 steps)
    gemm3_kernel<<<dim3((NCLS + 127) / 128, BB / 128), 512, GSMEM>>>(
        hlh, hll, 1024, nullptr, nullptr, 0, 1024,
        Wch, Wcl, 1024, NCLS, 1024,
        b_c, nullptr, nullptr, 0, nullptr, nullptr,
        out_logits, NCLS, nullptr, nullptr, 0);
}

// round 15
// speedup vs baseline: 1.2067x; 1.0680x over previous
#include <cuda_runtime.h>
#include <cuda_bf16.h>
#include <math.h>
#include <stdint.h>

#define BB 256
#define TT 64
#define LL 1024
#define SS 512
#define NCLS 239
#define MBT (BB * TT)

typedef __nv_bfloat16 bf16;

__device__ bf16 g_x_hi  [MBT * 2048];
__device__ bf16 g_x_lo  [MBT * 2048];
__device__ bf16 g_xs_hi [MBT * 1280];
__device__ bf16 g_xs_lo [MBT * 1280];
__device__ bf16 g_f_hi  [MBT * 2048];
__device__ bf16 g_f_lo  [MBT * 2048];
__device__ bf16 g_sf_hi [MBT * 512];
__device__ bf16 g_sf_lo [MBT * 512];
__device__ bf16 g_Wp_hi [2048 * 2048];
__device__ bf16 g_Wp_lo [2048 * 2048];
__device__ bf16 g_Ws_hi [512 * 1280];
__device__ bf16 g_Ws_lo [512 * 1280];
__device__ bf16 g_Wl_hi [4096 * 2560];
__device__ bf16 g_Wl_lo [4096 * 2560];
__device__ bf16 g_Whl_hi[4096 * 1024];
__device__ bf16 g_Whl_lo[4096 * 1024];
__device__ bf16 g_Wis_hi[2048 * 512];
__device__ bf16 g_Wis_lo[2048 * 512];
__device__ bf16 g_Whs_hi[2048 * 512];
__device__ bf16 g_Whs_lo[2048 * 512];
__device__ bf16 g_Wc_hi [NCLS * 1024];
__device__ bf16 g_Wc_lo [NCLS * 1024];
__device__ float g_sfeats[MBT * 512];
__device__ float g_sgpre [MBT * 2048];
__device__ float g_lgpre [MBT * 4096];
__device__ float g_Gs2[2][BB * 2048];
__device__ float g_Gl3[3][BB * 4096];
__device__ float g_hl[2][BB * LL];
__device__ float g_cl[2][BB * LL];
__device__ float g_hs[2][BB * SS];
__device__ float g_cs[2][BB * SS];
__device__ bf16 g_hl_hi[2][BB * LL];
__device__ bf16 g_hl_lo[2][BB * LL];
__device__ bf16 g_hs_hi[2][BB * SS];
__device__ bf16 g_hs_lo[2][BB * SS];

__device__ __forceinline__ uint32_t smem_u32(const void* p) {
    return (uint32_t)__cvta_generic_to_shared(p);
}
__device__ __forceinline__ void cp16(uint32_t dst, const void* src, int srcsize) {
    asm volatile("cp.async.cg.shared.global [%0], [%1], 16, %2;\n"
                 :: "r"(dst), "l"(src), "r"(srcsize));
}
__device__ __forceinline__ void cp_commit() {
    asm volatile("cp.async.commit_group;\n");
}
template<int N>
__device__ __forceinline__ void cp_wait() {
    asm volatile("cp.async.wait_group %0;\n" :: "n"(N));
}
__device__ __forceinline__ void ldsm4(uint32_t* r, uint32_t addr) {
    asm volatile("ldmatrix.sync.aligned.m8n8.x4.shared.b16 {%0,%1,%2,%3}, [%4];\n"
                 : "=r"(r[0]), "=r"(r[1]), "=r"(r[2]), "=r"(r[3]) : "r"(addr));
}
__device__ __forceinline__ void mma_bf16(float* d, const uint32_t* a, uint32_t b0, uint32_t b1) {
    asm volatile("mma.sync.aligned.m16n8k16.row.col.f32.bf16.bf16.f32 "
                 "{%0,%1,%2,%3},{%4,%5,%6,%7},{%8,%9},{%0,%1,%2,%3};\n"
                 : "+f"(d[0]), "+f"(d[1]), "+f"(d[2]), "+f"(d[3])
                 : "r"(a[0]), "r"(a[1]), "r"(a[2]), "r"(a[3]), "r"(b0), "r"(b1));
}

#define LDSH 40
#define TILEB (128 * LDSH * 2)
#define GSMEM (16 * TILEB)

// ---- original 128x128 core (step & classifier) ----
__device__ __forceinline__ void gemm_core(
    char* smem, int bx, int by,
    const bf16* __restrict__ Ahi, const bf16* __restrict__ Alo, int lda,
    const bf16* __restrict__ A2hi, const bf16* __restrict__ A2lo, int lda2, int K1,
    const bf16* __restrict__ Bhi, const bf16* __restrict__ Blo, int ldb,
    int N, int K,
    const float* __restrict__ b1, const float* __restrict__ b2,
    const float* __restrict__ addsrc, int ldadd,
    const float* __restrict__ gamma, const float* __restrict__ beta,
    float* __restrict__ Cf, int ldc,
    bf16* __restrict__ Chi, bf16* __restrict__ Clo, int ldsp)
{
    constexpr int BM = 128;
    const int tid  = threadIdx.x;
    const int lane = tid & 31;
    const int wid  = tid >> 5;
    const int wm   = wid >> 2;
    const int wn   = wid & 3;
    const int bm   = by * BM;
    const int bn   = bx * BM;
    const int NC = K / 64;

    float acc[2][4][4];
#pragma unroll
    for (int i = 0; i < 2; i++)
#pragma unroll
        for (int j = 0; j < 4; j++)
#pragma unroll
            for (int r = 0; r < 4; r++) acc[i][j][r] = 0.f;

    const int srow = tid >> 2;
    const int skc  = (tid & 3) * 8;
    auto stage = [&](int c) {
        int k0 = c * 64;
        const bf16 *Ah, *Al; int ald, ak;
        if (k0 < K1) { Ah = Ahi;  Al = Alo;  ald = lda;  ak = k0; }
        else         { Ah = A2hi; Al = A2lo; ald = lda2; ak = k0 - K1; }
        uint32_t base = smem_u32(smem) + (c & 1) * (8 * TILEB);
        uint32_t soff = (srow * LDSH + skc) * 2;
        int n = bn + srow;
        bool ok = (n < N);
#pragma unroll
        for (int h = 0; h < 2; h++) {
            size_t aoff = (size_t)(bm + srow) * ald + ak + h * 32 + skc;
            cp16(base + (0 + h) * TILEB + soff, Ah + aoff, 16);
            cp16(base + (2 + h) * TILEB + soff, Al + aoff, 16);
            size_t boff = (size_t)(ok ? n : 0) * ldb + k0 + h * 32 + skc;
            cp16(base + (4 + h) * TILEB + soff, Bhi + boff, ok ? 16 : 0);
            cp16(base + (6 + h) * TILEB + soff, Blo + boff, ok ? 16 : 0);
        }
    };

    stage(0); cp_commit();

    const int arow = wm * 32 + (lane & 15);
    const int akk0 = (lane >> 4) * 8;
    const int brow = wn * 32 + (lane & 7) + ((lane >> 4) << 3);
    const int bkk0 = ((lane >> 3) & 1) << 3;

    for (int c = 0; c < NC; c++) {
        cp_wait<0>();
        __syncthreads();
        if (c + 1 < NC) { stage(c + 1); cp_commit(); }

        uint32_t base = smem_u32(smem) + (c & 1) * (8 * TILEB);
#pragma unroll
        for (int h = 0; h < 2; h++) {
            uint32_t bAh = base + (0 + h) * TILEB;
            uint32_t bAl = base + (2 + h) * TILEB;
            uint32_t bBh = base + (4 + h) * TILEB;
            uint32_t bBl = base + (6 + h) * TILEB;
#pragma unroll
            for (int ks = 0; ks < 32; ks += 16) {
                uint32_t ah[2][4], al[2][4], bh[4][2], bl[4][2];
                const int akk = ks + akk0;
                const int bkk = ks + bkk0;
#pragma unroll
                for (int mi = 0; mi < 2; mi++)
                    ldsm4(ah[mi], bAh + ((arow + mi * 16) * LDSH + akk) * 2);
#pragma unroll
                for (int ng = 0; ng < 2; ng++) {
                    uint32_t t[4];
                    ldsm4(t, bBh + ((brow + ng * 16) * LDSH + bkk) * 2);
                    bh[2 * ng][0] = t[0]; bh[2 * ng][1] = t[1];
                    bh[2 * ng + 1][0] = t[2]; bh[2 * ng + 1][1] = t[3];
                }
#pragma unroll
                for (int mi = 0; mi < 2; mi++)
#pragma unroll
                    for (int nj = 0; nj < 4; nj++)
                        mma_bf16(acc[mi][nj], ah[mi], bh[nj][0], bh[nj][1]);
#pragma unroll
                for (int mi = 0; mi < 2; mi++)
                    ldsm4(al[mi], bAl + ((arow + mi * 16) * LDSH + akk) * 2);
#pragma unroll
                for (int ng = 0; ng < 2; ng++) {
                    uint32_t t[4];
                    ldsm4(t, bBl + ((brow + ng * 16) * LDSH + bkk) * 2);
                    bl[2 * ng][0] = t[0]; bl[2 * ng][1] = t[1];
                    bl[2 * ng + 1][0] = t[2]; bl[2 * ng + 1][1] = t[3];
                }
#pragma unroll
                for (int mi = 0; mi < 2; mi++)
#pragma unroll
                    for (int nj = 0; nj < 4; nj++)
                        mma_bf16(acc[mi][nj], ah[mi], bl[nj][0], bl[nj][1]);
#pragma unroll
                for (int mi = 0; mi < 2; mi++)
#pragma unroll
                    for (int nj = 0; nj < 4; nj++)
                        mma_bf16(acc[mi][nj], al[mi], bh[nj][0], bh[nj][1]);
            }
        }
    }

    const float inv_std = rsqrtf(1.0f + 1e-5f);
    const int g  = lane >> 2;
    const int tg = lane & 3;
#pragma unroll
    for (int mi = 0; mi < 2; mi++)
#pragma unroll
        for (int nj = 0; nj < 4; nj++)
#pragma unroll
            for (int r = 0; r < 4; r++) {
                int m = bm + wm * 32 + mi * 16 + g + ((r >> 1) << 3);
                int n = bn + wn * 32 + nj * 8 + tg * 2 + (r & 1);
                if (n >= N) continue;
                float v = acc[mi][nj][r];
                if (b1)     v += b1[n];
                if (b2)     v += b2[n];
                if (addsrc) v += addsrc[(size_t)m * ldadd + n];
                if (gamma)  v = fmaxf(0.f, v * (gamma[n] * inv_std) + beta[n]);
                if (Cf)     Cf[(size_t)m * ldc + n] = v;
                if (Chi) {
                    bf16 h = __float2bfloat16(v);
                    Chi[(size_t)m * ldsp + n] = h;
                    Clo[(size_t)m * ldsp + n] = __float2bfloat16(v - __bfloat162float(h));
                }
            }
}

// ---- wide 128x256 core (phase-1): warp 32x64, K32 chunks, 3-stage ring ----
#define BTILE (256 * LDSH * 2)
#define CHUNK2 (2 * TILEB + 2 * BTILE)
#define GSMEM2 (3 * CHUNK2)

__device__ __forceinline__ void gemm_core2(
    char* smem, int bx, int by,
    const bf16* __restrict__ Ahi, const bf16* __restrict__ Alo, int lda,
    const bf16* __restrict__ A2hi, const bf16* __restrict__ A2lo, int lda2, int K1,
    const bf16* __restrict__ Bhi, const bf16* __restrict__ Blo, int ldb,
    int N, int K,
    const float* __restrict__ b1, const float* __restrict__ b2,
    const float* __restrict__ gamma, const float* __restrict__ beta,
    float* __restrict__ Cf, int ldc,
    bf16* __restrict__ Chi, bf16* __restrict__ Clo, int ldsp)
{
    const int tid  = threadIdx.x;
    const int lane = tid & 31;
    const int wid  = tid >> 5;
    const int wm   = wid >> 2;
    const int wn   = wid & 3;
    const int bm   = by * 128;
    const int bn   = bx * 256;
    const int NC = K / 32;

    float acc[2][8][4];
#pragma unroll
    for (int i = 0; i < 2; i++)
#pragma unroll
        for (int j = 0; j < 8; j++)
#pragma unroll
            for (int r = 0; r < 4; r++) acc[i][j][r] = 0.f;

    const int arowS = tid >> 2;
    const int akcS  = (tid & 3) * 8;
    auto stage = [&](int c) {
        int k0 = c * 32;
        const bf16 *Ah, *Al; int ald, ak;
        if (k0 < K1) { Ah = Ahi;  Al = Alo;  ald = lda;  ak = k0; }
        else         { Ah = A2hi; Al = A2lo; ald = lda2; ak = k0 - K1; }
        uint32_t base = smem_u32(smem) + (c % 3) * CHUNK2;
        {
            uint32_t soff = (arowS * LDSH + akcS) * 2;
            size_t aoff = (size_t)(bm + arowS) * ald + ak + akcS;
            cp16(base + 0 * TILEB + soff, Ah + aoff, 16);
            cp16(base + 1 * TILEB + soff, Al + aoff, 16);
        }
#pragma unroll
        for (int q = 0; q < 2; q++) {
            int v = tid + q * 512;
            int row = v >> 2, kc = (v & 3) * 8;
            int n = bn + row;
            bool ok = (n < N);
            uint32_t soff = (row * LDSH + kc) * 2;
            size_t boff = (size_t)(ok ? n : 0) * ldb + k0 + kc;
            cp16(base + 2 * TILEB + soff, Bhi + boff, ok ? 16 : 0);
            cp16(base + 2 * TILEB + BTILE + soff, Blo + boff, ok ? 16 : 0);
        }
    };

    stage(0); cp_commit();
    if (NC > 1) stage(1);
    cp_commit();

    const int arow = wm * 32 + (lane & 15);
    const int akk0 = (lane >> 4) * 8;
    const int brow = wn * 64 + (lane & 7) + ((lane >> 4) << 3);
    const int bkk0 = ((lane >> 3) & 1) << 3;

    for (int c = 0; c < NC; c++) {
        cp_wait<1>();
        __syncthreads();
        if (c + 2 < NC) stage(c + 2);
        cp_commit();

        uint32_t base = smem_u32(smem) + (c % 3) * CHUNK2;
        uint32_t bAh = base;
        uint32_t bAl = base + TILEB;
        uint32_t bBh = base + 2 * TILEB;
        uint32_t bBl = base + 2 * TILEB + BTILE;
#pragma unroll
        for (int ks = 0; ks < 32; ks += 16) {
            const int akk = ks + akk0;
            const int bkk = ks + bkk0;
            uint32_t ah[2][4], al[2][4], bh[8][2];
#pragma unroll
            for (int mi = 0; mi < 2; mi++)
                ldsm4(ah[mi], bAh + ((arow + mi * 16) * LDSH + akk) * 2);
#pragma unroll
            for (int ng = 0; ng < 4; ng++) {
                uint32_t t[4];
                ldsm4(t, bBh + ((brow + ng * 16) * LDSH + bkk) * 2);
                bh[2 * ng][0] = t[0]; bh[2 * ng][1] = t[1];
                bh[2 * ng + 1][0] = t[2]; bh[2 * ng + 1][1] = t[3];
            }
#pragma unroll
            for (int mi = 0; mi < 2; mi++)
#pragma unroll
                for (int nj = 0; nj < 8; nj++)
                    mma_bf16(acc[mi][nj], ah[mi], bh[nj][0], bh[nj][1]);
#pragma unroll
            for (int mi = 0; mi < 2; mi++)
                ldsm4(al[mi], bAl + ((arow + mi * 16) * LDSH + akk) * 2);
#pragma unroll
            for (int mi = 0; mi < 2; mi++)
#pragma unroll
                for (int nj = 0; nj < 8; nj++)
                    mma_bf16(acc[mi][nj], al[mi], bh[nj][0], bh[nj][1]);
            uint32_t bl[8][2];
#pragma unroll
            for (int ng = 0; ng < 4; ng++) {
                uint32_t t[4];
                ldsm4(t, bBl + ((brow + ng * 16) * LDSH + bkk) * 2);
                bl[2 * ng][0] = t[0]; bl[2 * ng][1] = t[1];
                bl[2 * ng + 1][0] = t[2]; bl[2 * ng + 1][1] = t[3];
            }
#pragma unroll
            for (int mi = 0; mi < 2; mi++)
#pragma unroll
                for (int nj = 0; nj < 8; nj++)
                    mma_bf16(acc[mi][nj], ah[mi], bl[nj][0], bl[nj][1]);
        }
    }

    const float inv_std = rsqrtf(1.0f + 1e-5f);
    const int g  = lane >> 2;
    const int tg = lane & 3;
#pragma unroll
    for (int mi = 0; mi < 2; mi++)
#pragma unroll
        for (int nj = 0; nj < 8; nj++)
#pragma unroll
            for (int r = 0; r < 4; r++) {
                int m = bm + wm * 32 + mi * 16 + g + ((r >> 1) << 3);
                int n = bn + wn * 64 + nj * 8 + tg * 2 + (r & 1);
                if (n >= N) continue;
                float v = acc[mi][nj][r];
                if (b1)    v += b1[n];
                if (b2)    v += b2[n];
                if (gamma) v = fmaxf(0.f, v * (gamma[n] * inv_std) + beta[n]);
                if (Cf)    Cf[(size_t)m * ldc + n] = v;
                if (Chi) {
                    bf16 h = __float2bfloat16(v);
                    Chi[(size_t)m * ldsp + n] = h;
                    Clo[(size_t)m * ldsp + n] = __float2bfloat16(v - __bfloat162float(h));
                }
            }
}

__global__ void __launch_bounds__(512, 1)
gemm3_kernel(const bf16* Ahi, const bf16* Alo, int lda,
             const bf16* A2hi, const bf16* A2lo, int lda2, int K1,
             const bf16* Bhi, const bf16* Blo, int ldb,
             int N, int K,
             const float* b1, const float* b2,
             const float* addsrc, int ldadd,
             const float* gamma, const float* beta,
             float* Cf, int ldc,
             bf16* Chi, bf16* Clo, int ldsp)
{
    extern __shared__ char smem[];
    gemm_core(smem, blockIdx.x, blockIdx.y,
              Ahi, Alo, lda, A2hi, A2lo, lda2, K1, Bhi, Blo, ldb, N, K,
              b1, b2, addsrc, ldadd, gamma, beta, Cf, ldc, Chi, Clo, ldsp);
}

__global__ void __launch_bounds__(512, 1)
phase1a_kernel(const bf16* xh, const bf16* xl, const bf16* Wph, const bf16* Wpl,
               const float* b_p, const float* g_p, const float* be_p,
               bf16* fh, bf16* fl,
               const bf16* xsh, const bf16* xsl, const bf16* Wsh, const bf16* Wsl,
               const float* b_s, const float* g_s, const float* be_s,
               float* sfeats, bf16* sfh, bf16* sfl)
{
    extern __shared__ char smem[];
    int bid = blockIdx.x;
    if (bid < 1024) {
        gemm_core2(smem, bid & 7, bid >> 3,
                   xh, xl, 2048, nullptr, nullptr, 0, 2048,
                   Wph, Wpl, 2048, 2048, 2048,
                   b_p, nullptr, g_p, be_p,
                   nullptr, 0, fh, fl, 2048);
    } else {
        int t = bid - 1024;
        gemm_core2(smem, t & 1, t >> 1,
                   xsh, xsl, 1280, nullptr, nullptr, 0, 1280,
                   Wsh, Wsl, 1280, 512, 1280,
                   b_s, nullptr, g_s, be_s,
                   sfeats, 512, sfh, sfl, 512);
    }
}

__global__ void __launch_bounds__(512, 1)
phase1b_kernel(const bf16* fh, const bf16* fl, const bf16* sfh, const bf16* sfl,
               const bf16* Wlh, const bf16* Wll,
               const float* bih_l, const float* bhh_l, float* lgpre,
               const bf16* Wish, const bf16* Wisl,
               const float* bih_s, const float* bhh_s, float* sgpre)
{
    extern __shared__ char smem[];
    int bid = blockIdx.x;
    if (bid < 2048) {
        gemm_core2(smem, bid & 15, bid >> 4,
                   fh, fl, 2048, sfh, sfl, 512, 2048,
                   Wlh, Wll, 2560, 4096, 2560,
                   bih_l, bhh_l, nullptr, nullptr,
                   lgpre, 4096, nullptr, nullptr, 0);
    } else {
        int t = bid - 2048;
        gemm_core2(smem, t & 7, t >> 3,
                   sfh, sfl, 512, nullptr, nullptr, 0, 512,
                   Wish, Wisl, 512, 2048, 512,
                   bih_s, bhh_s, nullptr, nullptr,
                   sgpre, 2048, nullptr, nullptr, 0);
    }
}

__global__ void __launch_bounds__(512, 1)
step_gemm_kernel(const bf16* hsh, const bf16* hsl, const bf16* Whsh, const bf16* Whsl,
                 const float* sgpre_t,
                 const bf16* hlh, const bf16* hll, const bf16* Whlh, const bf16* Whll,
                 const float* lgpre_t,
                 float* Gs2, float* Gl3,
                 const float* sfeats, int t,
                 const float* hl_f32, const float* cl_f32,
                 const float* W_g, const float* b_g, float* r_out)
{
    extern __shared__ char smem[];
    int bid = blockIdx.x;
    if (bid < 128) {
        int p  = bid >> 6;
        int tt = bid & 63;
        int bx = tt >> 1, by = tt & 1;
        gemm_core(smem, bx, by,
                  hlh + p * 384, hll + p * 384, 1024, nullptr, nullptr, 0, 384,
                  Whlh + p * 384, Whll + p * 384, 1024, 4096, 384,
                  nullptr, nullptr, (p == 0) ? lgpre_t : nullptr, TT * 4096,
                  nullptr, nullptr,
                  Gl3 + (size_t)p * BB * 4096, 4096, nullptr, nullptr, 0);
    } else if (bid < 192) {
        int tt = bid - 128;
        int bx = tt >> 1, by = tt & 1;
        gemm_core(smem, bx, by,
                  hlh + 768, hll + 768, 1024, nullptr, nullptr, 0, 256,
                  Whlh + 768, Whll + 768, 1024, 4096, 256,
                  nullptr, nullptr, nullptr, 0, nullptr, nullptr,
                  Gl3 + (size_t)2 * BB * 4096, 4096, nullptr, nullptr, 0);
    } else if (bid < 256) {
        int q  = bid - 192;
        int p  = q >> 5;
        int tt = q & 31;
        int bx = tt >> 1, by = tt & 1;
        gemm_core(smem, bx, by,
                  hsh + p * 256, hsl + p * 256, 512, nullptr, nullptr, 0, 256,
                  Whsh + p * 256, Whsl + p * 256, 512, 2048, 256,
                  nullptr, nullptr, (p == 0) ? sgpre_t : nullptr, TT * 2048,
                  nullptr, nullptr,
                  Gs2 + (size_t)p * BB * 2048, 2048, nullptr, nullptr, 0);
    } else {
        int b   = (bid - 256) * 32 + (threadIdx.x >> 4);
        int sub = threadIdx.x & 15;
        const float* s = sfeats + ((size_t)b * TT + t) * SS;
        const float* h = hl_f32 + (size_t)b * LL;
        const float* c = cl_f32 + (size_t)b * LL;
        const float* w0 = W_g;
        const float* w1 = W_g + 2560;
        float p0 = 0.f, p1 = 0.f;
        for (int j = sub; j < SS; j += 16) { float v = s[j]; p0 += v * w0[j]; p1 += v * w1[j]; }
        for (int j = sub; j < LL; j += 16) { float v = h[j]; p0 += v * w0[SS + j]; p1 += v * w1[SS + j]; }
        for (int j = sub; j < LL; j += 16) { float v = c[j]; p0 += v * w0[SS + LL + j]; p1 += v * w1[SS + LL + j]; }
#pragma unroll
        for (int o = 8; o > 0; o >>= 1) {
            p0 += __shfl_down_sync(0xFFFFFFFFu, p0, o, 16);
            p1 += __shfl_down_sync(0xFFFFFFFFu, p1, o, 16);
        }
        if (sub == 0) {
            float r0 = (p0 + b_g[0] >= p1 + b_g[1]) ? 1.f : 0.f;
            r_out[b * 2 + 0] = r0;
            r_out[b * 2 + 1] = 1.f - r0;
        }
    }
}

__device__ __forceinline__ float sigf(float x) { return 1.f / (1.f + expf(-x)); }
__device__ __forceinline__ void split_store4(const float4& v, bf16* hi, bf16* lo, size_t off) {
    bf16 h0 = __float2bfloat16(v.x), h1 = __float2bfloat16(v.y);
    bf16 h2 = __float2bfloat16(v.z), h3 = __float2bfloat16(v.w);
    __nv_bfloat162* H = (__nv_bfloat162*)(hi + off);
    H[0] = __nv_bfloat162(h0, h1); H[1] = __nv_bfloat162(h2, h3);
    bf16 l0 = __float2bfloat16(v.x - __bfloat162float(h0));
    bf16 l1 = __float2bfloat16(v.y - __bfloat162float(h1));
    bf16 l2 = __float2bfloat16(v.z - __bfloat162float(h2));
    bf16 l3 = __float2bfloat16(v.w - __bfloat162float(h3));
    __nv_bfloat162* L = (__nv_bfloat162*)(lo + off);
    L[0] = __nv_bfloat162(l0, l1); L[1] = __nv_bfloat162(l2, l3);
}

struct SJob { const float4* src; __nv_bfloat162* hi; __nv_bfloat162* lo; };
struct SJobs { SJob j[9]; unsigned cum[10]; };

__global__ void __launch_bounds__(256)
split_all_kernel(SJobs jb, unsigned total4)
{
    const unsigned S = gridDim.x * blockDim.x;
    const unsigned base = blockIdx.x * blockDim.x + threadIdx.x;
    float4 v[4];
    int kk[4];
    unsigned off[4];
    bool ok[4];
#pragma unroll
    for (int q = 0; q < 4; q++) {
        unsigned i = base + q * S;
        ok[q] = (i < total4);
        if (ok[q]) {
            int k = 0;
#pragma unroll
            for (int z = 0; z < 8; z++) if (i >= jb.cum[z + 1]) k = z + 1;
            kk[q]  = k;
            off[q] = i - jb.cum[k];
            v[q]   = jb.j[k].src[off[q]];
        }
    }
#pragma unroll
    for (int q = 0; q < 4; q++) {
        if (!ok[q]) continue;
        float4 x = v[q];
        int k = kk[q];
        unsigned o = off[q];
        bf16 h0 = __float2bfloat16(x.x), h1 = __float2bfloat16(x.y);
        bf16 h2 = __float2bfloat16(x.z), h3 = __float2bfloat16(x.w);
        bf16 l0 = __float2bfloat16(x.x - __bfloat162float(h0));
        bf16 l1 = __float2bfloat16(x.y - __bfloat162float(h1));
        bf16 l2 = __float2bfloat16(x.z - __bfloat162float(h2));
        bf16 l3 = __float2bfloat16(x.w - __bfloat162float(h3));
        jb.j[k].hi[2 * o]     = __nv_bfloat162(h0, h1);
        jb.j[k].hi[2 * o + 1] = __nv_bfloat162(h2, h3);
        jb.j[k].lo[2 * o]     = __nv_bfloat162(l0, l1);
        jb.j[k].lo[2 * o + 1] = __nv_bfloat162(l2, l3);
    }
}

__global__ void zero_states_kernel(float* hl, float* cl, float* hs, float* cs,
                                   bf16* hlh, bf16* hll, bf16* hsh, bf16* hsl)
{
    int i = blockIdx.x * blockDim.x + threadIdx.x;
    if (i < BB * LL) { hl[i] = 0.f; cl[i] = 0.f; hlh[i] = __float2bfloat16(0.f); hll[i] = __float2bfloat16(0.f); }
    if (i < BB * SS) { hs[i] = 0.f; cs[i] = 0.f; hsh[i] = __float2bfloat16(0.f); hsl[i] = __float2bfloat16(0.f); }
}

__global__ void __launch_bounds__(256)
step_post_kernel(const float* __restrict__ Gs2, const float* __restrict__ Gl3,
                 const float* __restrict__ r_in,
                 const float* __restrict__ h_old, const float* __restrict__ c_old,
                 const float* __restrict__ cs_old,
                 float* __restrict__ hs_new, float* __restrict__ cs_new,
                 bf16* __restrict__ hsh, bf16* __restrict__ hsl,
                 float* __restrict__ h_new, float* __restrict__ c_new,
                 bf16* __restrict__ hh, bf16* __restrict__ hl)
{
    const int b   = blockIdx.x;
    const int tid = threadIdx.x;
    __shared__ float4 sh_h4[SS / 4], sh_c4[SS / 4];

    if (tid < SS / 4) {
        const float4* gs0 = (const float4*)(Gs2 + (size_t)b * (4 * SS));
        const float4* gs1 = (const float4*)(Gs2 + (size_t)BB * 2048 + (size_t)b * (4 * SS));
        const float4* co4 = (const float4*)(cs_old + (size_t)b * SS);
        int n4 = tid;
        float4 ia = gs0[n4],           ib = gs1[n4];
        float4 fa = gs0[128 + n4],     fb = gs1[128 + n4];
        float4 ga = gs0[256 + n4],     gb = gs1[256 + n4];
        float4 oa = gs0[384 + n4],     ob = gs1[384 + n4];
        float4 co = co4[n4];
        float4 h2, c2;
        {
            float i_ = sigf(ia.x + ib.x), f_ = sigf(fa.x + fb.x);
            float g_ = tanhf(ga.x + gb.x), o_ = sigf(oa.x + ob.x);
            c2.x = f_ * co.x + i_ * g_; h2.x = o_ * tanhf(c2.x);
            i_ = sigf(ia.y + ib.y); f_ = sigf(fa.y + fb.y);
            g_ = tanhf(ga.y + gb.y); o_ = sigf(oa.y + ob.y);
            c2.y = f_ * co.y + i_ * g_; h2.y = o_ * tanhf(c2.y);
            i_ = sigf(ia.z + ib.z); f_ = sigf(fa.z + fb.z);
            g_ = tanhf(ga.z + gb.z); o_ = sigf(oa.z + ob.z);
            c2.z = f_ * co.z + i_ * g_; h2.z = o_ * tanhf(c2.z);
            i_ = sigf(ia.w + ib.w); f_ = sigf(fa.w + fb.w);
            g_ = tanhf(ga.w + gb.w); o_ = sigf(oa.w + ob.w);
            c2.w = f_ * co.w + i_ * g_; h2.w = o_ * tanhf(c2.w);
        }
        sh_h4[n4] = h2; sh_c4[n4] = c2;
        ((float4*)(cs_new + (size_t)b * SS))[n4] = c2;
        ((float4*)(hs_new + (size_t)b * SS))[n4] = h2;
        split_store4(h2, hsh, hsl, (size_t)b * SS + 4 * n4);
    }
    __syncthreads();

    const float r0 = r_in[b * 2], r1 = 1.f - r0;

    {
        const float4* gA = (const float4*)(Gl3 + (size_t)b * (4 * LL));
        const float4* gB = (const float4*)(Gl3 + (size_t)BB * 4096 + (size_t)b * (4 * LL));
        const float4* gC = (const float4*)(Gl3 + (size_t)2 * BB * 4096 + (size_t)b * (4 * LL));
        const float4* ho4 = (const float4*)(h_old + (size_t)b * LL);
        const float4* co4 = (const float4*)(c_old + (size_t)b * LL);
        int n4 = tid;
        float4 iA = gA[n4],        iB = gB[n4],        iC = gC[n4];
        float4 fA = gA[256 + n4],  fB = gB[256 + n4],  fC = gC[256 + n4];
        float4 gA4 = gA[512 + n4], gB4 = gB[512 + n4], gC4 = gC[512 + n4];
        float4 oA = gA[768 + n4],  oB = gB[768 + n4],  oC = gC[768 + n4];
        float4 ho = ho4[n4], co = co4[n4];
        float4 ph, pc;
        if (n4 < SS / 4) { ph = sh_h4[n4]; pc = sh_c4[n4]; }
        else             { ph = ho;        pc = co; }
        float4 h2, c2;
        {
            float i_ = sigf(iA.x + iB.x + iC.x), f_ = sigf(fA.x + fB.x + fC.x);
            float g_ = tanhf(gA4.x + gB4.x + gC4.x), o_ = sigf(oA.x + oB.x + oC.x);
            float cl_ = f_ * co.x + i_ * g_, hl_ = o_ * tanhf(cl_);
            h2.x = r0 * hl_ + r1 * ph.x; c2.x = r0 * cl_ + r1 * pc.x;
            i_ = sigf(iA.y + iB.y + iC.y); f_ = sigf(fA.y + fB.y + fC.y);
            g_ = tanhf(gA4.y + gB4.y + gC4.y); o_ = sigf(oA.y + oB.y + oC.y);
            cl_ = f_ * co.y + i_ * g_; hl_ = o_ * tanhf(cl_);
            h2.y = r0 * hl_ + r1 * ph.y; c2.y = r0 * cl_ + r1 * pc.y;
            i_ = sigf(iA.z + iB.z + iC.z); f_ = sigf(fA.z + fB.z + fC.z);
            g_ = tanhf(gA4.z + gB4.z + gC4.z); o_ = sigf(oA.z + oB.z + oC.z);
            cl_ = f_ * co.z + i_ * g_; hl_ = o_ * tanhf(cl_);
            h2.z = r0 * hl_ + r1 * ph.z; c2.z = r0 * cl_ + r1 * pc.z;
            i_ = sigf(iA.w + iB.w + iC.w); f_ = sigf(fA.w + fB.w + fC.w);
            g_ = tanhf(gA4.w + gB4.w + gC4.w); o_ = sigf(oA.w + oB.w + oC.w);
            cl_ = f_ * co.w + i_ * g_; hl_ = o_ * tanhf(cl_);
            h2.w = r0 * hl_ + r1 * ph.w; c2.w = r0 * cl_ + r1 * pc.w;
        }
        ((float4*)(c_new + (size_t)b * LL))[n4] = c2;
        ((float4*)(h_new + (size_t)b * LL))[n4] = h2;
        split_store4(h2, hh, hl, (size_t)b * LL + 4 * n4);
    }
}

static inline float* fsym(const void* s) { void* p = nullptr; cudaGetSymbolAddress(&p, s); return (float*)p; }
static inline bf16*  bsym(const void* s) { void* p = nullptr; cudaGetSymbolAddress(&p, s); return (bf16*)p; }

extern "C" void kernel_launch(void* const* d_in, const int* in_sizes, int n_in,
                              void* d_out, int out_size)
{
    const float* x     = (const float*)d_in[0];
    const float* xs    = (const float*)d_in[1];
    const float* W_p   = (const float*)d_in[2];
    const float* b_p   = (const float*)d_in[3];
    const float* g_p   = (const float*)d_in[4];
    const float* be_p  = (const float*)d_in[5];
    const float* W_s   = (const float*)d_in[6];
    const float* b_s   = (const float*)d_in[7];
    const float* g_s   = (const float*)d_in[8];
    const float* be_s  = (const float*)d_in[9];
    const float* Wih_l = (const float*)d_in[10];
    const float* Whh_l = (const float*)d_in[11];
    const float* bih_l = (const float*)d_in[12];
    const float* bhh_l = (const float*)d_in[13];
    const float* Wih_s = (const float*)d_in[14];
    const float* Whh_s = (const float*)d_in[15];
    const float* bih_s = (const float*)d_in[16];
    const float* bhh_s = (const float*)d_in[17];
    const float* W_g   = (const float*)d_in[18];
    const float* b_g   = (const float*)d_in[19];
    const float* W_c   = (const float*)d_in[20];
    const float* b_c   = (const float*)d_in[21];

    float* out = (float*)d_out;
    float* out_logits = out;
    float* out_r      = out + BB * NCLS;

    bf16 *xh = bsym(g_x_hi), *xl = bsym(g_x_lo);
    bf16 *xsh = bsym(g_xs_hi), *xsl = bsym(g_xs_lo);
    bf16 *fh = bsym(g_f_hi), *fl = bsym(g_f_lo);
    bf16 *sfh = bsym(g_sf_hi), *sfl = bsym(g_sf_lo);
    bf16 *Wph = bsym(g_Wp_hi), *Wpl = bsym(g_Wp_lo);
    bf16 *Wsh = bsym(g_Ws_hi), *Wsl = bsym(g_Ws_lo);
    bf16 *Wlh = bsym(g_Wl_hi), *Wll = bsym(g_Wl_lo);
    bf16 *Whlh = bsym(g_Whl_hi), *Whll = bsym(g_Whl_lo);
    bf16 *Wish = bsym(g_Wis_hi), *Wisl = bsym(g_Wis_lo);
    bf16 *Whsh = bsym(g_Whs_hi), *Whsl = bsym(g_Whs_lo);
    bf16 *Wch = bsym(g_Wc_hi), *Wcl = bsym(g_Wc_lo);

    float* sfeats = fsym(g_sfeats);
    float* sgpre  = fsym(g_sgpre);
    float* lgpre  = fsym(g_lgpre);
    float* Gs2 = fsym(g_Gs2);
    float* Gl3 = fsym(g_Gl3);
    float* hl = fsym(g_hl);
    float* cl = fsym(g_cl);
    float* hs = fsym(g_hs);
    float* cs = fsym(g_cs);
    bf16* hlh = bsym(g_hl_hi); bf16* hll = bsym(g_hl_lo);
    bf16* hsh = bsym(g_hs_hi); bf16* hsl = bsym(g_hs_lo);

    cudaFuncSetAttribute(gemm3_kernel, cudaFuncAttributeMaxDynamicSharedMemorySize, GSMEM);
    cudaFuncSetAttribute(phase1a_kernel, cudaFuncAttributeMaxDynamicSharedMemorySize, GSMEM2);
    cudaFuncSetAttribute(phase1b_kernel, cudaFuncAttributeMaxDynamicSharedMemorySize, GSMEM2);
    cudaFuncSetAttribute(step_gemm_kernel, cudaFuncAttributeMaxDynamicSharedMemorySize, GSMEM);

    const int TPB = 256;

    {
        SJobs jb;
        const float* srcs[9] = { x, xs, W_p, W_s, Wih_l, Whh_l, Wih_s, Whh_s, W_c };
        bf16* his[9] = { xh, xsh, Wph, Wsh, Wlh, Whlh, Wish, Whsh, Wch };
        bf16* los[9] = { xl, xsl, Wpl, Wsl, Wll, Whll, Wisl, Whsl, Wcl };
        long  ns [9] = { (long)MBT * 2048, (long)MBT * 1280, 2048L * 2048, 512L * 1280,
                         4096L * 2560, 4096L * 1024, 2048L * 512, 2048L * 512,
                         (long)NCLS * 1024 };
        unsigned cum = 0;
        for (int k = 0; k < 9; k++) {
            jb.j[k].src = (const float4*)srcs[k];
            jb.j[k].hi  = (__nv_bfloat162*)his[k];
            jb.j[k].lo  = (__nv_bfloat162*)los[k];
            jb.cum[k] = cum;
            cum += (unsigned)(ns[k] / 4);
        }
        jb.cum[9] = cum;
        int grid = (int)((cum + TPB * 4 - 1) / (TPB * 4));
        split_all_kernel<<<grid, TPB>>>(jb, cum);
    }
    zero_states_kernel<<<(BB * LL + 255) / 256, TPB>>>(hl, cl, hs, cs, hlh, hll, hsh, hsl);

    phase1a_kernel<<<1024 + 256, 512, GSMEM2>>>(
        xh, xl, Wph, Wpl, b_p, g_p, be_p, fh, fl,
        xsh, xsl, Wsh, Wsl, b_s, g_s, be_s, sfeats, sfh, sfl);
    phase1b_kernel<<<2048 + 1024, 512, GSMEM2>>>(
        fh, fl, sfh, sfl, Wlh, Wll, bih_l, bhh_l, lgpre,
        Wish, Wisl, bih_s, bhh_s, sgpre);

    for (int t = 0; t < TT; t++) {
        int cur = t & 1, nxt = 1 - cur;
        float* hl_c = hl + (size_t)cur * BB * LL;
        float* cl_c = cl + (size_t)cur * BB * LL;
        float* hl_n = hl + (size_t)nxt * BB * LL;
        float* cl_n = cl + (size_t)nxt * BB * LL;
        float* cs_c = cs + (size_t)cur * BB * SS;
        float* hs_n = hs + (size_t)nxt * BB * SS;
        float* cs_n = cs + (size_t)nxt * BB * SS;
        bf16* hlh_c = hlh + (size_t)cur * BB * LL;
        bf16* hll_c = hll + (size_t)cur * BB * LL;
        bf16* hlh_n = hlh + (size_t)nxt * BB * LL;
        bf16* hll_n = hll + (size_t)nxt * BB * LL;
        bf16* hsh_c = hsh + (size_t)cur * BB * SS;
        bf16* hsl_c = hsl + (size_t)cur * BB * SS;
        bf16* hsh_n = hsh + (size_t)nxt * BB * SS;
        bf16* hsl_n = hsl + (size_t)nxt * BB * SS;
        float* r_t = out_r + (size_t)t * BB * 2;

        step_gemm_kernel<<<264, 512, GSMEM>>>(
            hsh_c, hsl_c, Whsh, Whsl, sgpre + (size_t)t * 2048,
            hlh_c, hll_c, Whlh, Whll, lgpre + (size_t)t * 4096,
            Gs2, Gl3,
            sfeats, t, hl_c, cl_c, W_g, b_g, r_t);
        step_post_kernel<<<BB, 256>>>(
            Gs2, Gl3, r_t, hl_c, cl_c, cs_c,
            hs_n, cs_n, hsh_n, hsl_n,
            hl_n, cl_n, hlh_n, hll_n);
    }

    gemm3_kernel<<<dim3((NCLS + 127) / 128, BB / 128), 512, GSMEM>>>(
        hlh, hll, 1024, nullptr, nullptr, 0, 1024,
        Wch, Wcl, 1024, NCLS, 1024,
        b_c, nullptr, nullptr, 0, nullptr, nullptr,
        out_logits, NCLS, nullptr, nullptr, 0);
}